// round 1
// baseline (speedup 1.0000x reference)
#include <cuda_runtime.h>
#include <math.h>

// ---------------- problem constants ----------------
#define B_      8
#define Q_      900
#define BQ      7200          // B*Q
#define DM      256
#define STOT    13294
#define BS      106352        // B*STOT
#define NH      8
#define HD      32
#define DFFN    1024

// ---------------- scratch (allocation-free) ----------------
__device__ float g_qkv [BQ * 768];
__device__ float g_sa  [BQ * DM];
__device__ float g_buf [BQ * DM];
__device__ float g_tgt1[BQ * DM];
__device__ float g_val [(size_t)BS * DM];
__device__ float g_off [BQ * DM];
__device__ float g_awl [BQ * 128];
__device__ float g_ca  [BQ * DM];
__device__ float g_tgt2[BQ * DM];
__device__ float g_ffn1[BQ * DFFN];

// ---------------- generic tiled fp32 GEMM ----------------
// C[M,N] = A[M,K] @ W[N,K]^T + bias[N]  (+ residual R[M,N]) (+ relu)
// BM=BN=64, BK=16, 256 threads, 4x4 micro-tile per thread.
// Requires: N % 64 == 0, K % 16 == 0. M guarded.
template<bool RELU, bool RESID>
__global__ __launch_bounds__(256)
void gemm64(const float* __restrict__ A, const float* __restrict__ W,
            const float* __restrict__ bias, const float* __restrict__ R,
            float* __restrict__ C, int M, int N, int K)
{
    __shared__ float As[16][68];   // +4 pad: keeps 16B alignment, kills most bank conflicts
    __shared__ float Ws[16][68];

    const int tid = threadIdx.x;
    const int tx = tid & 15;           // 0..15 -> 4 cols each
    const int ty = tid >> 4;           // 0..15 -> 4 rows each
    const int m0 = blockIdx.y * 64;
    const int n0 = blockIdx.x * 64;

    const int lr = tid >> 2;           // 0..63 (tile row for loads)
    const int lc = (tid & 3) * 4;      // 0,4,8,12 (k within chunk)

    float acc[4][4] = {};

    for (int k0 = 0; k0 < K; k0 += 16) {
        float4 av = make_float4(0.f, 0.f, 0.f, 0.f);
        if (m0 + lr < M)
            av = *(const float4*)(A + (size_t)(m0 + lr) * K + k0 + lc);
        As[lc + 0][lr] = av.x; As[lc + 1][lr] = av.y;
        As[lc + 2][lr] = av.z; As[lc + 3][lr] = av.w;

        float4 wv = *(const float4*)(W + (size_t)(n0 + lr) * K + k0 + lc);
        Ws[lc + 0][lr] = wv.x; Ws[lc + 1][lr] = wv.y;
        Ws[lc + 2][lr] = wv.z; Ws[lc + 3][lr] = wv.w;

        __syncthreads();

        #pragma unroll
        for (int kk = 0; kk < 16; kk++) {
            float4 a4 = *(const float4*)&As[kk][ty * 4];
            float4 b4 = *(const float4*)&Ws[kk][tx * 4];
            acc[0][0] += a4.x * b4.x; acc[0][1] += a4.x * b4.y;
            acc[0][2] += a4.x * b4.z; acc[0][3] += a4.x * b4.w;
            acc[1][0] += a4.y * b4.x; acc[1][1] += a4.y * b4.y;
            acc[1][2] += a4.y * b4.z; acc[1][3] += a4.y * b4.w;
            acc[2][0] += a4.z * b4.x; acc[2][1] += a4.z * b4.y;
            acc[2][2] += a4.z * b4.z; acc[2][3] += a4.z * b4.w;
            acc[3][0] += a4.w * b4.x; acc[3][1] += a4.w * b4.y;
            acc[3][2] += a4.w * b4.z; acc[3][3] += a4.w * b4.w;
        }
        __syncthreads();
    }

    const int nn = n0 + tx * 4;
    float4 bv = *(const float4*)(bias + nn);
    #pragma unroll
    for (int i = 0; i < 4; i++) {
        int m = m0 + ty * 4 + i;
        if (m >= M) continue;
        float4 cv;
        cv.x = acc[i][0] + bv.x; cv.y = acc[i][1] + bv.y;
        cv.z = acc[i][2] + bv.z; cv.w = acc[i][3] + bv.w;
        if (RESID) {
            float4 rv = *(const float4*)(R + (size_t)m * N + nn);
            cv.x += rv.x; cv.y += rv.y; cv.z += rv.z; cv.w += rv.w;
        }
        if (RELU) {
            cv.x = fmaxf(cv.x, 0.f); cv.y = fmaxf(cv.y, 0.f);
            cv.z = fmaxf(cv.z, 0.f); cv.w = fmaxf(cv.w, 0.f);
        }
        *(float4*)(C + (size_t)m * N + nn) = cv;
    }
}

// ---------------- flash-style self attention ----------------
// grid: (ceil(Q/128), NH, B), block 128. thread = one query row.
__global__ __launch_bounds__(128)
void self_attn_kernel(const float* __restrict__ qkv, float* __restrict__ sa)
{
    const int b = blockIdx.z, h = blockIdx.y;
    const int tid = threadIdx.x;
    const int q = blockIdx.x * 128 + tid;
    const bool active = q < Q_;

    __shared__ float Ks[64][32];
    __shared__ float Vs[64][32];

    const float scale = 0.17677669529663687f;   // 1/sqrt(32)

    float qr[32];
    {
        const float* qp = qkv + (size_t)(b * Q_ + (active ? q : 0)) * 768 + h * HD;
        #pragma unroll
        for (int d = 0; d < 32; d++) qr[d] = qp[d] * scale;
    }

    float m = -1e30f, l = 0.f;
    float acc[32] = {};

    for (int k0 = 0; k0 < Q_; k0 += 64) {
        const int jmax = min(64, Q_ - k0);
        for (int idx = tid; idx < 64 * 32; idx += 128) {
            int j = idx >> 5, d = idx & 31;
            if (j < jmax) {
                const float* base = qkv + (size_t)(b * Q_ + k0 + j) * 768 + h * HD + d;
                Ks[j][d] = base[256];
                Vs[j][d] = base[512];
            }
        }
        __syncthreads();

        if (active) {
            for (int j = 0; j < jmax; j++) {
                float s0 = 0.f, s1 = 0.f, s2 = 0.f, s3 = 0.f;
                #pragma unroll
                for (int d4 = 0; d4 < 8; d4++) {
                    float4 k4 = *(const float4*)&Ks[j][d4 * 4];
                    s0 += qr[d4 * 4 + 0] * k4.x;
                    s1 += qr[d4 * 4 + 1] * k4.y;
                    s2 += qr[d4 * 4 + 2] * k4.z;
                    s3 += qr[d4 * 4 + 3] * k4.w;
                }
                float s = (s0 + s1) + (s2 + s3);
                if (s > m) {
                    float corr = __expf(m - s);
                    l *= corr;
                    #pragma unroll
                    for (int d = 0; d < 32; d++) acc[d] *= corr;
                    m = s;
                }
                float p = __expf(s - m);
                l += p;
                #pragma unroll
                for (int d4 = 0; d4 < 8; d4++) {
                    float4 v4 = *(const float4*)&Vs[j][d4 * 4];
                    acc[d4 * 4 + 0] += p * v4.x;
                    acc[d4 * 4 + 1] += p * v4.y;
                    acc[d4 * 4 + 2] += p * v4.z;
                    acc[d4 * 4 + 3] += p * v4.w;
                }
            }
        }
        __syncthreads();
    }

    if (active) {
        float inv = 1.f / l;
        float* op = sa + (size_t)(b * Q_ + q) * DM + h * HD;
        #pragma unroll
        for (int d = 0; d < 32; d++) op[d] = acc[d] * inv;
    }
}

// ---------------- LayerNorm (row of 256) ----------------
__global__ __launch_bounds__(256)
void ln_kernel(const float* __restrict__ in, const float* __restrict__ g,
               const float* __restrict__ bta, float* __restrict__ out)
{
    __shared__ float red[256];
    const int row = blockIdx.x, tid = threadIdx.x;
    float x = in[(size_t)row * DM + tid];

    red[tid] = x; __syncthreads();
    #pragma unroll
    for (int s = 128; s > 0; s >>= 1) {
        if (tid < s) red[tid] += red[tid + s];
        __syncthreads();
    }
    float mu = red[0] * (1.f / 256.f);
    __syncthreads();

    float dx = x - mu;
    red[tid] = dx * dx; __syncthreads();
    #pragma unroll
    for (int s = 128; s > 0; s >>= 1) {
        if (tid < s) red[tid] += red[tid + s];
        __syncthreads();
    }
    float var = red[0] * (1.f / 256.f);
    float rs = rsqrtf(var + 1e-5f);
    out[(size_t)row * DM + tid] = dx * rs * g[tid] + bta[tid];
}

// ---------------- deformable sampling + weight softmax ----------------
// one warp per (b, q, h); lane = channel d (0..31)
__global__ __launch_bounds__(256)
void deform_kernel(const float* __restrict__ off, const float* __restrict__ awl,
                   const float* __restrict__ value, const float* __restrict__ refp,
                   float* __restrict__ out)
{
    const int gw = (blockIdx.x * blockDim.x + threadIdx.x) >> 5;
    const int lane = threadIdx.x & 31;
    if (gw >= B_ * Q_ * NH) return;
    const int h = gw & 7;
    const int q = (gw >> 3) % Q_;
    const int b = gw / (NH * Q_);
    const size_t bq = (size_t)b * Q_ + q;

    // softmax over the 16 (level,point) logits, lanes 0..15 hold them
    float logit = (lane < 16) ? awl[bq * 128 + h * 16 + lane] : -1e30f;
    float mx = logit;
    #pragma unroll
    for (int o = 16; o > 0; o >>= 1) mx = fmaxf(mx, __shfl_xor_sync(0xffffffffu, mx, o));
    float e = (lane < 16) ? __expf(logit - mx) : 0.f;
    float se = e;
    #pragma unroll
    for (int o = 16; o > 0; o >>= 1) se += __shfl_xor_sync(0xffffffffu, se, o);
    const float aw = e / se;

    const int   HWl[4][2] = {{100,100},{50,50},{25,25},{13,13}};   // (H, W)
    const int   ST[4]     = {0, 10000, 12500, 13125};

    float accv = 0.f;
    #pragma unroll
    for (int lvl = 0; lvl < 4; lvl++) {
        const int Hi = HWl[lvl][0], Wi = HWl[lvl][1];
        const float Hl = (float)Hi, Wl = (float)Wi;
        const float refx = refp[(bq * 4 + lvl) * 2 + 0];
        const float refy = refp[(bq * 4 + lvl) * 2 + 1];
        const float* vbase = value + ((size_t)b * STOT + ST[lvl]) * DM + h * HD + lane;
        #pragma unroll
        for (int p = 0; p < 4; p++) {
            const int oidx = ((h * 4 + lvl) * 4 + p) * 2;
            const float ox = off[bq * DM + oidx + 0];
            const float oy = off[bq * DM + oidx + 1];
            const float locx = refx + ox / Wl;
            const float locy = refy + oy / Hl;
            const float x = locx * Wl - 0.5f;
            const float y = locy * Hl - 0.5f;
            const float x0 = floorf(x), y0 = floorf(y);
            float samp = 0.f;
            #pragma unroll
            for (int c = 0; c < 4; c++) {
                const float xi = x0 + (float)(c & 1);
                const float yi = y0 + (float)(c >> 1);
                const float w = (1.f - fabsf(x - xi)) * (1.f - fabsf(y - yi));
                if (xi >= 0.f && xi < Wl && yi >= 0.f && yi < Hl && w != 0.f) {
                    const int ii = (int)yi * Wi + (int)xi;
                    samp += w * vbase[(size_t)ii * DM];
                }
            }
            const float awp = __shfl_sync(0xffffffffu, aw, lvl * 4 + p);
            accv += awp * samp;
        }
    }
    out[bq * DM + h * HD + lane] = accv;
}

// ---------------- launch ----------------
extern "C" void kernel_launch(void* const* d_in, const int* in_sizes, int n_in,
                              void* d_out, int out_size)
{
    (void)in_sizes; (void)n_in; (void)out_size;
    const float* tgt   = (const float*)d_in[0];
    const float* mem   = (const float*)d_in[1];
    // d_in[2] memory_padding_mask: all-false, ignored
    const float* refp  = (const float*)d_in[3];
    // d_in[4], d_in[5]: static shapes, hardcoded
    const float* ipw = (const float*)d_in[6],  *ipb = (const float*)d_in[7];
    const float* opw = (const float*)d_in[8],  *opb = (const float*)d_in[9];
    const float* n1g = (const float*)d_in[10], *n1b = (const float*)d_in[11];
    const float* n2g = (const float*)d_in[12], *n2b = (const float*)d_in[13];
    const float* n3g = (const float*)d_in[14], *n3b = (const float*)d_in[15];
    const float* sow = (const float*)d_in[16], *sob = (const float*)d_in[17];
    const float* aww = (const float*)d_in[18], *awb = (const float*)d_in[19];
    const float* vpw = (const float*)d_in[20], *vpb = (const float*)d_in[21];
    const float* oqw = (const float*)d_in[22], *oqb = (const float*)d_in[23];
    const float* l1w = (const float*)d_in[24], *l1b = (const float*)d_in[25];
    const float* l2w = (const float*)d_in[26], *l2b = (const float*)d_in[27];
    float* out = (float*)d_out;

    float *qkv, *sa, *buf, *tgt1, *val, *offb, *awlb, *ca, *tgt2, *ffn1;
    cudaGetSymbolAddress((void**)&qkv,  g_qkv);
    cudaGetSymbolAddress((void**)&sa,   g_sa);
    cudaGetSymbolAddress((void**)&buf,  g_buf);
    cudaGetSymbolAddress((void**)&tgt1, g_tgt1);
    cudaGetSymbolAddress((void**)&val,  g_val);
    cudaGetSymbolAddress((void**)&offb, g_off);
    cudaGetSymbolAddress((void**)&awlb, g_awl);
    cudaGetSymbolAddress((void**)&ca,   g_ca);
    cudaGetSymbolAddress((void**)&tgt2, g_tgt2);
    cudaGetSymbolAddress((void**)&ffn1, g_ffn1);

    const int MB = (BQ + 63) / 64;       // 113
    const int MBV = (BS + 63) / 64;      // 1662

    // 1. QKV projection
    gemm64<false,false><<<dim3(768/64, MB), 256>>>(tgt, ipw, ipb, nullptr, qkv, BQ, 768, DM);
    // 2. self attention
    self_attn_kernel<<<dim3((Q_ + 127)/128, NH, B_), 128>>>(qkv, sa);
    // 3. out-proj + residual, 4. LN1
    gemm64<false,true><<<dim3(DM/64, MB), 256>>>(sa, opw, opb, tgt, buf, BQ, DM, DM);
    ln_kernel<<<BQ, 256>>>(buf, n1g, n1b, tgt1);
    // 5. value projection (mask is all-false -> no-op)
    gemm64<false,false><<<dim3(DM/64, MBV), 256>>>(mem, vpw, vpb, nullptr, val, BS, DM, DM);
    // 6. sampling offsets, 7. attention-weight logits
    gemm64<false,false><<<dim3(DM/64, MB), 256>>>(tgt1, sow, sob, nullptr, offb, BQ, DM, DM);
    gemm64<false,false><<<dim3(128/64, MB), 256>>>(tgt1, aww, awb, nullptr, awlb, BQ, 128, DM);
    // 8. deformable sampling (softmax fused)
    deform_kernel<<<(B_ * Q_ * NH * 32 + 255)/256, 256>>>(offb, awlb, val, refp, ca);
    // 9. output proj + residual, 10. LN2
    gemm64<false,true><<<dim3(DM/64, MB), 256>>>(ca, oqw, oqb, tgt1, buf, BQ, DM, DM);
    ln_kernel<<<BQ, 256>>>(buf, n2g, n2b, tgt2);
    // 11. FFN up + relu, 12. FFN down + residual, 13. LN3 -> out
    gemm64<true,false><<<dim3(DFFN/64, MB), 256>>>(tgt2, l1w, l1b, nullptr, ffn1, BQ, DFFN, DM);
    gemm64<false,true><<<dim3(DM/64, MB), 256>>>(ffn1, l2w, l2b, tgt2, buf, BQ, DM, DFFN);
    ln_kernel<<<BQ, 256>>>(buf, n3g, n3b, out);
}

// round 4
// speedup vs baseline: 1.5198x; 1.5198x over previous
#include <cuda_runtime.h>
#include <cuda_bf16.h>
#include <math.h>
#include <stdint.h>

// ---------------- problem constants ----------------
#define B_      8
#define Q_      900
#define BQ      7200          // B*Q
#define DM      256
#define STOT    13294
#define BS      106352        // B*STOT
#define NH      8
#define HD      32
#define DFFN    1024

// ---------------- fp32 scratch ----------------
__device__ float g_qkv [BQ * 768];
__device__ float g_buf [BQ * DM];
__device__ float g_tgt1[BQ * DM];
__device__ float g_tgt2[BQ * DM];
__device__ float g_val [(size_t)BS * DM];
__device__ float g_off [BQ * DM];
__device__ float g_awl [BQ * 128];

// ---------------- bf16 split scratch (hi, lo) ----------------
__device__ __nv_bfloat16 s_tgt [2][BQ * DM];
__device__ __nv_bfloat16 s_mem [2][(size_t)BS * DM];
__device__ __nv_bfloat16 s_sa  [2][BQ * DM];
__device__ __nv_bfloat16 s_tgt1[2][BQ * DM];
__device__ __nv_bfloat16 s_ca  [2][BQ * DM];
__device__ __nv_bfloat16 s_tgt2[2][BQ * DM];
__device__ __nv_bfloat16 s_ffn1[2][BQ * DFFN];
__device__ __nv_bfloat16 s_ipw [2][768 * 256];
__device__ __nv_bfloat16 s_opw [2][256 * 256];
__device__ __nv_bfloat16 s_vpw [2][256 * 256];
__device__ __nv_bfloat16 s_sow [2][256 * 256];
__device__ __nv_bfloat16 s_aww [2][128 * 256];
__device__ __nv_bfloat16 s_oqw [2][256 * 256];
__device__ __nv_bfloat16 s_l1w [2][1024 * 256];
__device__ __nv_bfloat16 s_l2w [2][256 * 1024];

// ---------------- helpers ----------------
__device__ __forceinline__ uint32_t smem_u32(const void* p) {
    uint32_t a;
    asm("{ .reg .u64 t; cvta.to.shared.u64 t, %1; cvt.u32.u64 %0, t; }" : "=r"(a) : "l"(p));
    return a;
}
__device__ __forceinline__ void ldsm4(uint32_t* r, uint32_t addr) {
    asm volatile("ldmatrix.sync.aligned.m8n8.x4.shared.b16 {%0,%1,%2,%3}, [%4];"
        : "=r"(r[0]), "=r"(r[1]), "=r"(r[2]), "=r"(r[3]) : "r"(addr));
}
__device__ __forceinline__ void mma16816(float* c, const uint32_t* a, const uint32_t* b) {
    asm volatile("mma.sync.aligned.m16n8k16.row.col.f32.bf16.bf16.f32 "
        "{%0,%1,%2,%3}, {%4,%5,%6,%7}, {%8,%9}, {%0,%1,%2,%3};"
        : "+f"(c[0]), "+f"(c[1]), "+f"(c[2]), "+f"(c[3])
        : "r"(a[0]), "r"(a[1]), "r"(a[2]), "r"(a[3]), "r"(b[0]), "r"(b[1]));
}
__device__ __forceinline__ void cpasync16(uint32_t dst, const void* src, int sz) {
    asm volatile("cp.async.cg.shared.global [%0], [%1], 16, %2;" :: "r"(dst), "l"(src), "r"(sz));
}
__device__ __forceinline__ void split2(float a, float b, __nv_bfloat162& h, __nv_bfloat162& l) {
    h = __floats2bfloat162_rn(a, b);
    float2 hf = __bfloat1622float2(h);
    l = __floats2bfloat162_rn(a - hf.x, b - hf.y);
}

// ---------------- fp32 -> bf16 hi/lo split ----------------
__global__ __launch_bounds__(256)
void split_kernel(const float* __restrict__ in, __nv_bfloat16* __restrict__ hi,
                  __nv_bfloat16* __restrict__ lo, int n4)
{
    int i = blockIdx.x * 256 + threadIdx.x;
    if (i >= n4) return;
    float4 v = ((const float4*)in)[i];
    __nv_bfloat162 h0, l0, h1, l1;
    split2(v.x, v.y, h0, l0);
    split2(v.z, v.w, h1, l1);
    ((__nv_bfloat162*)hi)[i * 2 + 0] = h0;
    ((__nv_bfloat162*)hi)[i * 2 + 1] = h1;
    ((__nv_bfloat162*)lo)[i * 2 + 0] = l0;
    ((__nv_bfloat162*)lo)[i * 2 + 1] = l1;
}

// ---------------- bf16x3 mma.sync GEMM ----------------
// C[M,N] = A[M,K] @ W[N,K]^T + bias (+R) (+relu). Inputs pre-split bf16 hi/lo.
// CTA tile 128x128, BK=32, 256 threads (8 warps, 4m x 2n -> warp tile 32x64).
// smem: 2 stages x 4 tiles(Ah,Al,Wh,Wl) x 128 rows x 80B (32 bf16 + pad).
#define STG   40960
#define TILEB 10240

template<bool RELU, bool RESID, bool SPLITOUT>
__global__ __launch_bounds__(256)
void gemm_mma(const __nv_bfloat16* __restrict__ Ah, const __nv_bfloat16* __restrict__ Al,
              const __nv_bfloat16* __restrict__ Wh, const __nv_bfloat16* __restrict__ Wl,
              const float* __restrict__ bias, const float* __restrict__ R,
              float* __restrict__ C, __nv_bfloat16* __restrict__ Ch,
              __nv_bfloat16* __restrict__ Cl, int M, int N, int K)
{
    extern __shared__ char smem[];
    const uint32_t sb = smem_u32(smem);
    const int tid = threadIdx.x, lane = tid & 31, wid = tid >> 5;
    const int am = (wid & 3) * 32;          // warp m offset in tile
    const int bn = (wid >> 2) * 64;         // warp n offset in tile
    const int m0 = blockIdx.y * 128, n0 = blockIdx.x * 128;

    float c[2][8][4] = {};

#define ISSUE(st, ch) do {                                                        \
    const int kb_ = (ch) * 32;                                                    \
    const uint32_t so_ = sb + (st) * STG;                                         \
    _Pragma("unroll")                                                             \
    for (int cix = tid; cix < 2048; cix += 256) {                                 \
        int t_ = cix >> 9, idx_ = cix & 511, r_ = idx_ >> 2, q_ = idx_ & 3;       \
        uint32_t d_ = so_ + t_ * TILEB + r_ * 80 + q_ * 16;                       \
        if (t_ < 2) {                                                             \
            const __nv_bfloat16* s_ = (t_ == 0 ? Ah : Al) +                       \
                (size_t)(m0 + r_) * K + kb_ + q_ * 8;                             \
            cpasync16(d_, s_, (m0 + r_) < M ? 16 : 0);                            \
        } else {                                                                  \
            const __nv_bfloat16* s_ = (t_ == 2 ? Wh : Wl) +                       \
                (size_t)(n0 + r_) * K + kb_ + q_ * 8;                             \
            cpasync16(d_, s_, 16);                                                \
        }                                                                         \
    }                                                                             \
    asm volatile("cp.async.commit_group;" ::: "memory");                          \
} while (0)

    ISSUE(0, 0);
    const int nCh = K >> 5;

    const int lar = lane & 15;
    const int lac = (lane >> 4) * 16;                     // bytes
    const int lbr = (lane & 7) + ((lane >> 4) & 1) * 8;
    const int lbc = ((lane >> 3) & 1) * 16;               // bytes

    for (int ch = 0; ch < nCh; ch++) {
        if (ch + 1 < nCh) {
            ISSUE((ch + 1) & 1, ch + 1);
            asm volatile("cp.async.wait_group 1;" ::: "memory");
        } else {
            asm volatile("cp.async.wait_group 0;" ::: "memory");
        }
        __syncthreads();

        const uint32_t so = sb + (ch & 1) * STG;
        #pragma unroll
        for (int ks = 0; ks < 2; ks++) {
            uint32_t ah[2][4], al[2][4], bb[4][4];
            const uint32_t acol = ks * 32 + lac;
            const uint32_t bcol = ks * 32 + lbc;
            ldsm4(ah[0], so + 0     + (am + lar) * 80 + acol);
            ldsm4(ah[1], so + 0     + (am + 16 + lar) * 80 + acol);
            ldsm4(al[0], so + TILEB + (am + lar) * 80 + acol);
            ldsm4(al[1], so + TILEB + (am + 16 + lar) * 80 + acol);
            #pragma unroll
            for (int p = 0; p < 4; p++)
                ldsm4(bb[p], so + 2 * TILEB + (bn + p * 16 + lbr) * 80 + bcol);
            #pragma unroll
            for (int fm = 0; fm < 2; fm++)
                #pragma unroll
                for (int p = 0; p < 4; p++) {
                    mma16816(c[fm][2 * p],     ah[fm], bb[p]);
                    mma16816(c[fm][2 * p + 1], ah[fm], bb[p] + 2);
                    mma16816(c[fm][2 * p],     al[fm], bb[p]);
                    mma16816(c[fm][2 * p + 1], al[fm], bb[p] + 2);
                }
            #pragma unroll
            for (int p = 0; p < 4; p++)
                ldsm4(bb[p], so + 3 * TILEB + (bn + p * 16 + lbr) * 80 + bcol);
            #pragma unroll
            for (int fm = 0; fm < 2; fm++)
                #pragma unroll
                for (int p = 0; p < 4; p++) {
                    mma16816(c[fm][2 * p],     ah[fm], bb[p]);
                    mma16816(c[fm][2 * p + 1], ah[fm], bb[p] + 2);
                }
        }
        __syncthreads();
    }
#undef ISSUE

    // epilogue
    const int r0 = m0 + am + (lane >> 2);
    const int colb = n0 + bn + (lane & 3) * 2;
    #pragma unroll
    for (int fm = 0; fm < 2; fm++) {
        #pragma unroll
        for (int p = 0; p < 8; p++) {
            const int col = colb + p * 8;
            const float2 bv = *(const float2*)(bias + col);
            #pragma unroll
            for (int hh = 0; hh < 2; hh++) {
                const int row = r0 + fm * 16 + hh * 8;
                if (row < M) {
                    float o0 = c[fm][p][hh * 2 + 0] + bv.x;
                    float o1 = c[fm][p][hh * 2 + 1] + bv.y;
                    if (RESID) {
                        float2 rv = *(const float2*)(R + (size_t)row * N + col);
                        o0 += rv.x; o1 += rv.y;
                    }
                    if (RELU) { o0 = fmaxf(o0, 0.f); o1 = fmaxf(o1, 0.f); }
                    if (SPLITOUT) {
                        __nv_bfloat162 h, l;
                        split2(o0, o1, h, l);
                        *(__nv_bfloat162*)(Ch + (size_t)row * N + col) = h;
                        *(__nv_bfloat162*)(Cl + (size_t)row * N + col) = l;
                    } else {
                        *(float2*)(C + (size_t)row * N + col) = make_float2(o0, o1);
                    }
                }
            }
        }
    }
}

// ---------------- flash-style self attention (fp32), split-bf16 output ----------------
__global__ __launch_bounds__(128)
void self_attn_kernel(const float* __restrict__ qkv,
                      __nv_bfloat16* __restrict__ sah, __nv_bfloat16* __restrict__ sal)
{
    const int b = blockIdx.z, h = blockIdx.y;
    const int tid = threadIdx.x;
    const int q = blockIdx.x * 128 + tid;
    const bool active = q < Q_;

    __shared__ float Ks[64][32];
    __shared__ float Vs[64][32];

    const float scale = 0.17677669529663687f;

    float qr[32];
    {
        const float* qp = qkv + (size_t)(b * Q_ + (active ? q : 0)) * 768 + h * HD;
        #pragma unroll
        for (int d = 0; d < 32; d++) qr[d] = qp[d] * scale;
    }

    float m = -1e30f, l = 0.f;
    float acc[32] = {};

    for (int k0 = 0; k0 < Q_; k0 += 64) {
        const int jmax = min(64, Q_ - k0);
        for (int idx = tid; idx < 64 * 32; idx += 128) {
            int j = idx >> 5, d = idx & 31;
            if (j < jmax) {
                const float* base = qkv + (size_t)(b * Q_ + k0 + j) * 768 + h * HD + d;
                Ks[j][d] = base[256];
                Vs[j][d] = base[512];
            }
        }
        __syncthreads();

        if (active) {
            for (int j = 0; j < jmax; j++) {
                float s0 = 0.f, s1 = 0.f, s2 = 0.f, s3 = 0.f;
                #pragma unroll
                for (int d4 = 0; d4 < 8; d4++) {
                    float4 k4 = *(const float4*)&Ks[j][d4 * 4];
                    s0 += qr[d4 * 4 + 0] * k4.x;
                    s1 += qr[d4 * 4 + 1] * k4.y;
                    s2 += qr[d4 * 4 + 2] * k4.z;
                    s3 += qr[d4 * 4 + 3] * k4.w;
                }
                float s = (s0 + s1) + (s2 + s3);
                if (s > m) {
                    float corr = __expf(m - s);
                    l *= corr;
                    #pragma unroll
                    for (int d = 0; d < 32; d++) acc[d] *= corr;
                    m = s;
                }
                float p = __expf(s - m);
                l += p;
                #pragma unroll
                for (int d4 = 0; d4 < 8; d4++) {
                    float4 v4 = *(const float4*)&Vs[j][d4 * 4];
                    acc[d4 * 4 + 0] += p * v4.x;
                    acc[d4 * 4 + 1] += p * v4.y;
                    acc[d4 * 4 + 2] += p * v4.z;
                    acc[d4 * 4 + 3] += p * v4.w;
                }
            }
        }
        __syncthreads();
    }

    if (active) {
        const float inv = 1.f / l;
        const size_t base = (size_t)(b * Q_ + q) * DM + h * HD;
        #pragma unroll
        for (int d2 = 0; d2 < 16; d2++) {
            __nv_bfloat162 h2, l2;
            split2(acc[2 * d2] * inv, acc[2 * d2 + 1] * inv, h2, l2);
            *(__nv_bfloat162*)(sah + base + 2 * d2) = h2;
            *(__nv_bfloat162*)(sal + base + 2 * d2) = l2;
        }
    }
}

// ---------------- LayerNorm (row of 256) with optional split output ----------------
template<bool SPLIT>
__global__ __launch_bounds__(256)
void ln_kernel(const float* __restrict__ in, const float* __restrict__ g,
               const float* __restrict__ bta, float* __restrict__ out,
               __nv_bfloat16* __restrict__ oh, __nv_bfloat16* __restrict__ ol)
{
    __shared__ float red[256];
    const int row = blockIdx.x, tid = threadIdx.x;
    float x = in[(size_t)row * DM + tid];

    red[tid] = x; __syncthreads();
    #pragma unroll
    for (int s = 128; s > 0; s >>= 1) {
        if (tid < s) red[tid] += red[tid + s];
        __syncthreads();
    }
    float mu = red[0] * (1.f / 256.f);
    __syncthreads();

    float dx = x - mu;
    red[tid] = dx * dx; __syncthreads();
    #pragma unroll
    for (int s = 128; s > 0; s >>= 1) {
        if (tid < s) red[tid] += red[tid + s];
        __syncthreads();
    }
    float var = red[0] * (1.f / 256.f);
    float rs = rsqrtf(var + 1e-5f);
    float y = dx * rs * g[tid] + bta[tid];
    const size_t idx = (size_t)row * DM + tid;
    out[idx] = y;
    if (SPLIT) {
        __nv_bfloat16 hv = __float2bfloat16(y);
        oh[idx] = hv;
        ol[idx] = __float2bfloat16(y - __bfloat162float(hv));
    }
}

// ---------------- deformable sampling + weight softmax, split-bf16 out ----------------
__global__ __launch_bounds__(256)
void deform_kernel(const float* __restrict__ off, const float* __restrict__ awl,
                   const float* __restrict__ value, const float* __restrict__ refp,
                   __nv_bfloat16* __restrict__ outh, __nv_bfloat16* __restrict__ outl)
{
    const int gw = (blockIdx.x * blockDim.x + threadIdx.x) >> 5;
    const int lane = threadIdx.x & 31;
    if (gw >= B_ * Q_ * NH) return;
    const int h = gw & 7;
    const int q = (gw >> 3) % Q_;
    const int b = gw / (NH * Q_);
    const size_t bq = (size_t)b * Q_ + q;

    float logit = (lane < 16) ? awl[bq * 128 + h * 16 + lane] : -1e30f;
    float mx = logit;
    #pragma unroll
    for (int o = 16; o > 0; o >>= 1) mx = fmaxf(mx, __shfl_xor_sync(0xffffffffu, mx, o));
    float e = (lane < 16) ? __expf(logit - mx) : 0.f;
    float se = e;
    #pragma unroll
    for (int o = 16; o > 0; o >>= 1) se += __shfl_xor_sync(0xffffffffu, se, o);
    const float aw = e / se;

    const int HWl[4][2] = {{100,100},{50,50},{25,25},{13,13}};
    const int ST[4]     = {0, 10000, 12500, 13125};

    float accv = 0.f;
    #pragma unroll
    for (int lvl = 0; lvl < 4; lvl++) {
        const int Hi = HWl[lvl][0], Wi = HWl[lvl][1];
        const float Hl = (float)Hi, Wl = (float)Wi;
        const float refx = refp[(bq * 4 + lvl) * 2 + 0];
        const float refy = refp[(bq * 4 + lvl) * 2 + 1];
        const float* vbase = value + ((size_t)b * STOT + ST[lvl]) * DM + h * HD + lane;
        #pragma unroll
        for (int p = 0; p < 4; p++) {
            const int oidx = ((h * 4 + lvl) * 4 + p) * 2;
            const float ox = off[bq * DM + oidx + 0];
            const float oy = off[bq * DM + oidx + 1];
            const float x = (refx + ox / Wl) * Wl - 0.5f;
            const float y = (refy + oy / Hl) * Hl - 0.5f;
            const float x0 = floorf(x), y0 = floorf(y);
            float samp = 0.f;
            #pragma unroll
            for (int cq = 0; cq < 4; cq++) {
                const float xi = x0 + (float)(cq & 1);
                const float yi = y0 + (float)(cq >> 1);
                const float w = (1.f - fabsf(x - xi)) * (1.f - fabsf(y - yi));
                if (xi >= 0.f && xi < Wl && yi >= 0.f && yi < Hl && w != 0.f) {
                    const int ii = (int)yi * Wi + (int)xi;
                    samp += w * vbase[(size_t)ii * DM];
                }
            }
            const float awp = __shfl_sync(0xffffffffu, aw, lvl * 4 + p);
            accv += awp * samp;
        }
    }
    const size_t oi = bq * DM + h * HD + lane;
    __nv_bfloat16 hv = __float2bfloat16(accv);
    outh[oi] = hv;
    outl[oi] = __float2bfloat16(accv - __bfloat162float(hv));
}

// ---------------- launch ----------------
extern "C" void kernel_launch(void* const* d_in, const int* in_sizes, int n_in,
                              void* d_out, int out_size)
{
    (void)in_sizes; (void)n_in; (void)out_size;
    const float* tgt   = (const float*)d_in[0];
    const float* mem   = (const float*)d_in[1];
    const float* refp  = (const float*)d_in[3];
    const float* ipw = (const float*)d_in[6],  *ipb = (const float*)d_in[7];
    const float* opw = (const float*)d_in[8],  *opb = (const float*)d_in[9];
    const float* n1g = (const float*)d_in[10], *n1b = (const float*)d_in[11];
    const float* n2g = (const float*)d_in[12], *n2b = (const float*)d_in[13];
    const float* n3g = (const float*)d_in[14], *n3b = (const float*)d_in[15];
    const float* sow = (const float*)d_in[16], *sob = (const float*)d_in[17];
    const float* aww = (const float*)d_in[18], *awb = (const float*)d_in[19];
    const float* vpw = (const float*)d_in[20], *vpb = (const float*)d_in[21];
    const float* oqw = (const float*)d_in[22], *oqb = (const float*)d_in[23];
    const float* l1w = (const float*)d_in[24], *l1b = (const float*)d_in[25];
    const float* l2w = (const float*)d_in[26], *l2b = (const float*)d_in[27];
    float* out = (float*)d_out;

    float *qkv, *buf, *tgt1, *tgt2, *val, *offb, *awlb;
    cudaGetSymbolAddress((void**)&qkv,  g_qkv);
    cudaGetSymbolAddress((void**)&buf,  g_buf);
    cudaGetSymbolAddress((void**)&tgt1, g_tgt1);
    cudaGetSymbolAddress((void**)&tgt2, g_tgt2);
    cudaGetSymbolAddress((void**)&val,  g_val);
    cudaGetSymbolAddress((void**)&offb, g_off);
    cudaGetSymbolAddress((void**)&awlb, g_awl);

    __nv_bfloat16 *p_tgt, *p_mem, *p_sa, *p_tgt1, *p_ca, *p_tgt2, *p_ffn1;
    __nv_bfloat16 *p_ipw, *p_opw, *p_vpw, *p_sow, *p_aww, *p_oqw, *p_l1w, *p_l2w;
    cudaGetSymbolAddress((void**)&p_tgt,  s_tgt);
    cudaGetSymbolAddress((void**)&p_mem,  s_mem);
    cudaGetSymbolAddress((void**)&p_sa,   s_sa);
    cudaGetSymbolAddress((void**)&p_tgt1, s_tgt1);
    cudaGetSymbolAddress((void**)&p_ca,   s_ca);
    cudaGetSymbolAddress((void**)&p_tgt2, s_tgt2);
    cudaGetSymbolAddress((void**)&p_ffn1, s_ffn1);
    cudaGetSymbolAddress((void**)&p_ipw,  s_ipw);
    cudaGetSymbolAddress((void**)&p_opw,  s_opw);
    cudaGetSymbolAddress((void**)&p_vpw,  s_vpw);
    cudaGetSymbolAddress((void**)&p_sow,  s_sow);
    cudaGetSymbolAddress((void**)&p_aww,  s_aww);
    cudaGetSymbolAddress((void**)&p_oqw,  s_oqw);
    cudaGetSymbolAddress((void**)&p_l1w,  s_l1w);
    cudaGetSymbolAddress((void**)&p_l2w,  s_l2w);

    const int SMEM = 2 * STG;   // 81920
    cudaFuncSetAttribute(gemm_mma<false, false, false>, cudaFuncAttributeMaxDynamicSharedMemorySize, SMEM);
    cudaFuncSetAttribute(gemm_mma<false, true,  false>, cudaFuncAttributeMaxDynamicSharedMemorySize, SMEM);
    cudaFuncSetAttribute(gemm_mma<true,  false, true >, cudaFuncAttributeMaxDynamicSharedMemorySize, SMEM);

    const int MT  = (BQ + 127) / 128;    // 57
    const int MTV = (BS + 127) / 128;    // 831

#define SPLIT(src, dst, n) \
    split_kernel<<<((n) / 4 + 255) / 256, 256>>>((src), (dst), (dst) + (n), (n) / 4)

    // ---- conversions ----
    SPLIT(tgt, p_tgt, BQ * DM);
    SPLIT(mem, p_mem, (int)((size_t)BS * DM));
    SPLIT(ipw, p_ipw, 768 * 256);
    SPLIT(opw, p_opw, 256 * 256);
    SPLIT(vpw, p_vpw, 256 * 256);
    SPLIT(sow, p_sow, 256 * 256);
    SPLIT(aww, p_aww, 128 * 256);
    SPLIT(oqw, p_oqw, 256 * 256);
    SPLIT(l1w, p_l1w, 1024 * 256);
    SPLIT(l2w, p_l2w, 256 * 1024);

#define HL(p, n) (p), (p) + (n)

    // 1. QKV projection
    gemm_mma<false, false, false><<<dim3(6, MT), 256, SMEM>>>(
        HL(p_tgt, BQ * DM), HL(p_ipw, 768 * 256), ipb, nullptr, qkv, nullptr, nullptr, BQ, 768, DM);
    // 2. self attention -> split sa
    self_attn_kernel<<<dim3((Q_ + 127) / 128, NH, B_), 128>>>(qkv, HL(p_sa, BQ * DM));
    // 3. out-proj + residual, 4. LN1 (+split tgt1)
    gemm_mma<false, true, false><<<dim3(2, MT), 256, SMEM>>>(
        HL(p_sa, BQ * DM), HL(p_opw, 256 * 256), opb, tgt, buf, nullptr, nullptr, BQ, DM, DM);
    ln_kernel<true><<<BQ, 256>>>(buf, n1g, n1b, tgt1, HL(p_tgt1, BQ * DM));
    // 5. value projection
    gemm_mma<false, false, false><<<dim3(2, MTV), 256, SMEM>>>(
        HL(p_mem, (size_t)BS * DM), HL(p_vpw, 256 * 256), vpb, nullptr, val, nullptr, nullptr, BS, DM, DM);
    // 6. sampling offsets, 7. attention-weight logits
    gemm_mma<false, false, false><<<dim3(2, MT), 256, SMEM>>>(
        HL(p_tgt1, BQ * DM), HL(p_sow, 256 * 256), sob, nullptr, offb, nullptr, nullptr, BQ, DM, DM);
    gemm_mma<false, false, false><<<dim3(1, MT), 256, SMEM>>>(
        HL(p_tgt1, BQ * DM), HL(p_aww, 128 * 256), awb, nullptr, awlb, nullptr, nullptr, BQ, 128, DM);
    // 8. deformable sampling -> split ca
    deform_kernel<<<(B_ * Q_ * NH * 32 + 255) / 256, 256>>>(offb, awlb, val, refp, HL(p_ca, BQ * DM));
    // 9. output proj + residual, 10. LN2 (+split tgt2)
    gemm_mma<false, true, false><<<dim3(2, MT), 256, SMEM>>>(
        HL(p_ca, BQ * DM), HL(p_oqw, 256 * 256), oqb, tgt1, buf, nullptr, nullptr, BQ, DM, DM);
    ln_kernel<true><<<BQ, 256>>>(buf, n2g, n2b, tgt2, HL(p_tgt2, BQ * DM));
    // 11. FFN up + relu -> split ffn1, 12. FFN down + residual, 13. LN3 -> out
    gemm_mma<true, false, true><<<dim3(8, MT), 256, SMEM>>>(
        HL(p_tgt2, BQ * DM), HL(p_l1w, 1024 * 256), l1b, nullptr, nullptr, HL(p_ffn1, BQ * DFFN), BQ, DFFN, DM);
    gemm_mma<false, true, false><<<dim3(2, MT), 256, SMEM>>>(
        HL(p_ffn1, BQ * DFFN), HL(p_l2w, 256 * 1024), l2b, tgt2, buf, nullptr, nullptr, BQ, DM, DFFN);
    ln_kernel<false><<<BQ, 256>>>(buf, n3g, n3b, out, nullptr, nullptr);
#undef HL
#undef SPLIT
}

// round 6
// speedup vs baseline: 2.5540x; 1.6805x over previous
#include <cuda_runtime.h>
#include <cuda_bf16.h>
#include <math.h>
#include <stdint.h>

// ---------------- problem constants ----------------
#define B_      8
#define Q_      900
#define BQ      7200          // B*Q
#define DM      256
#define STOT    13294
#define BS      106352        // B*STOT
#define NH      8
#define HD      32
#define DFFN    1024

// ---------------- fp32 scratch ----------------
__device__ float g_buf [BQ * DM];
__device__ float g_tgt1[BQ * DM];
__device__ float g_tgt2[BQ * DM];
__device__ float g_off [BQ * DM];
__device__ float g_awl [BQ * 128];

// ---------------- bf16 scratch ----------------
__device__ __nv_bfloat16 b_qkv [BQ * 768];
__device__ __nv_bfloat16 b_sa  [BQ * DM];
__device__ __nv_bfloat16 b_tgt [BQ * DM];
__device__ __nv_bfloat16 b_tgt1[BQ * DM];
__device__ __nv_bfloat16 b_mem [(size_t)BS * DM];
__device__ __nv_bfloat16 b_val [(size_t)BS * DM];
__device__ __nv_bfloat16 b_ca  [2][BQ * DM];
__device__ __nv_bfloat16 b_tgt2[2][BQ * DM];
__device__ __nv_bfloat16 b_ffn1[2][BQ * DFFN];
__device__ __nv_bfloat16 b_ipw [768 * 256];
__device__ __nv_bfloat16 b_opw [256 * 256];
__device__ __nv_bfloat16 b_vpw [256 * 256];
__device__ __nv_bfloat16 b_sow [256 * 256];
__device__ __nv_bfloat16 b_aww [128 * 256];
__device__ __nv_bfloat16 b_oqw [2][256 * 256];
__device__ __nv_bfloat16 b_l1w [2][1024 * 256];
__device__ __nv_bfloat16 b_l2w [2][256 * 1024];

// ---------------- helpers ----------------
__device__ __forceinline__ uint32_t smem_u32(const void* p) {
    uint32_t a;
    asm("{ .reg .u64 t; cvta.to.shared.u64 t, %1; cvt.u32.u64 %0, t; }" : "=r"(a) : "l"(p));
    return a;
}
__device__ __forceinline__ void ldsm4(uint32_t* r, uint32_t addr) {
    asm volatile("ldmatrix.sync.aligned.m8n8.x4.shared.b16 {%0,%1,%2,%3}, [%4];"
        : "=r"(r[0]), "=r"(r[1]), "=r"(r[2]), "=r"(r[3]) : "r"(addr));
}
__device__ __forceinline__ void ldsm4t(uint32_t* r, uint32_t addr) {
    asm volatile("ldmatrix.sync.aligned.m8n8.x4.trans.shared.b16 {%0,%1,%2,%3}, [%4];"
        : "=r"(r[0]), "=r"(r[1]), "=r"(r[2]), "=r"(r[3]) : "r"(addr));
}
__device__ __forceinline__ void mma16816(float* c, const uint32_t* a, const uint32_t* b) {
    asm volatile("mma.sync.aligned.m16n8k16.row.col.f32.bf16.bf16.f32 "
        "{%0,%1,%2,%3}, {%4,%5,%6,%7}, {%8,%9}, {%0,%1,%2,%3};"
        : "+f"(c[0]), "+f"(c[1]), "+f"(c[2]), "+f"(c[3])
        : "r"(a[0]), "r"(a[1]), "r"(a[2]), "r"(a[3]), "r"(b[0]), "r"(b[1]));
}
__device__ __forceinline__ void cpasync16(uint32_t dst, const void* src, int sz) {
    asm volatile("cp.async.cg.shared.global [%0], [%1], 16, %2;" :: "r"(dst), "l"(src), "r"(sz));
}
__device__ __forceinline__ void split2(float a, float b, __nv_bfloat162& h, __nv_bfloat162& l) {
    h = __floats2bfloat162_rn(a, b);
    float2 hf = __bfloat1622float2(h);
    l = __floats2bfloat162_rn(a - hf.x, b - hf.y);
}
__device__ __forceinline__ uint32_t pack_bf16(float a, float b) {
    __nv_bfloat162 h = __floats2bfloat162_rn(a, b);
    return *reinterpret_cast<uint32_t*>(&h);
}

// ---------------- fp32 -> bf16 converters ----------------
__global__ __launch_bounds__(256)
void split_kernel(const float* __restrict__ in, __nv_bfloat16* __restrict__ hi,
                  __nv_bfloat16* __restrict__ lo, int n4)
{
    int i = blockIdx.x * 256 + threadIdx.x;
    if (i >= n4) return;
    float4 v = ((const float4*)in)[i];
    __nv_bfloat162 h0, l0, h1, l1;
    split2(v.x, v.y, h0, l0);
    split2(v.z, v.w, h1, l1);
    ((__nv_bfloat162*)hi)[i * 2 + 0] = h0;
    ((__nv_bfloat162*)hi)[i * 2 + 1] = h1;
    ((__nv_bfloat162*)lo)[i * 2 + 0] = l0;
    ((__nv_bfloat162*)lo)[i * 2 + 1] = l1;
}
__global__ __launch_bounds__(256)
void conv_hi_kernel(const float* __restrict__ in, __nv_bfloat16* __restrict__ hi, int n4)
{
    int i = blockIdx.x * 256 + threadIdx.x;
    if (i >= n4) return;
    float4 v = ((const float4*)in)[i];
    ((__nv_bfloat162*)hi)[i * 2 + 0] = __floats2bfloat162_rn(v.x, v.y);
    ((__nv_bfloat162*)hi)[i * 2 + 1] = __floats2bfloat162_rn(v.z, v.w);
}

// ---------------- bf16 mma.sync GEMM (x1 or x3 split passes) ----------------
// C[M,N] = A[M,K] @ W[N,K]^T + bias (+R) (+relu).
// CTA tile 128x128, BK=32, 256 threads (8 warps, 4m x 2n -> warp tile 32x64).
// OUT: 0 = fp32 C, 1 = bf16 Ch, 2 = bf16 Ch+Cl.
#define TILEB 10240

template<int NPASS, bool RELU, bool RESID, int OUT>
__global__ __launch_bounds__(256)
void gemm_mma(const __nv_bfloat16* __restrict__ Ah, const __nv_bfloat16* __restrict__ Al,
              const __nv_bfloat16* __restrict__ Wh, const __nv_bfloat16* __restrict__ Wl,
              const float* __restrict__ bias, const float* __restrict__ R,
              float* __restrict__ C, __nv_bfloat16* __restrict__ Ch,
              __nv_bfloat16* __restrict__ Cl, int M, int N, int K)
{
    constexpr int NTIL = (NPASS == 3) ? 4 : 2;
    constexpr int STGB = NTIL * TILEB;
    constexpr int WOFF = (NPASS == 3 ? 2 : 1) * TILEB;

    extern __shared__ char smem[];
    const uint32_t sb = smem_u32(smem);
    const int tid = threadIdx.x, lane = tid & 31, wid = tid >> 5;
    const int am = (wid & 3) * 32;
    const int bn = (wid >> 2) * 64;
    const int m0 = blockIdx.y * 128, n0 = blockIdx.x * 128;

    float c[2][8][4] = {};

#define ISSUE(st, ch) do {                                                        \
    const int kb_ = (ch) * 32;                                                    \
    const uint32_t so_ = sb + (st) * STGB;                                        \
    _Pragma("unroll")                                                             \
    for (int cix = tid; cix < NTIL * 512; cix += 256) {                           \
        int t_ = cix >> 9, idx_ = cix & 511, r_ = idx_ >> 2, q_ = idx_ & 3;       \
        uint32_t d_ = so_ + t_ * TILEB + r_ * 80 + q_ * 16;                       \
        const __nv_bfloat16* base_;                                               \
        bool isA_;                                                                \
        if (NPASS == 1) { isA_ = (t_ == 0); base_ = isA_ ? Ah : Wh; }             \
        else { isA_ = (t_ < 2);                                                   \
               base_ = (t_ == 0 ? Ah : t_ == 1 ? Al : t_ == 2 ? Wh : Wl); }       \
        if (isA_) cpasync16(d_, base_ + (size_t)(m0 + r_) * K + kb_ + q_ * 8,     \
                            (m0 + r_) < M ? 16 : 0);                              \
        else      cpasync16(d_, base_ + (size_t)(n0 + r_) * K + kb_ + q_ * 8, 16);\
    }                                                                             \
    asm volatile("cp.async.commit_group;" ::: "memory");                          \
} while (0)

    ISSUE(0, 0);
    const int nCh = K >> 5;

    const int lar = lane & 15;
    const int lac = (lane >> 4) * 16;
    const int lbr = (lane & 7) + ((lane >> 4) & 1) * 8;
    const int lbc = ((lane >> 3) & 1) * 16;

    for (int ch = 0; ch < nCh; ch++) {
        if (ch + 1 < nCh) {
            ISSUE((ch + 1) & 1, ch + 1);
            asm volatile("cp.async.wait_group 1;" ::: "memory");
        } else {
            asm volatile("cp.async.wait_group 0;" ::: "memory");
        }
        __syncthreads();

        const uint32_t so = sb + (ch & 1) * STGB;
        #pragma unroll
        for (int ks = 0; ks < 2; ks++) {
            uint32_t ah[2][4], al[2][4], bb[4][4];
            const uint32_t acol = ks * 32 + lac;
            const uint32_t bcol = ks * 32 + lbc;
            ldsm4(ah[0], so + (am + lar) * 80 + acol);
            ldsm4(ah[1], so + (am + 16 + lar) * 80 + acol);
            if (NPASS == 3) {
                ldsm4(al[0], so + TILEB + (am + lar) * 80 + acol);
                ldsm4(al[1], so + TILEB + (am + 16 + lar) * 80 + acol);
            }
            #pragma unroll
            for (int p = 0; p < 4; p++)
                ldsm4(bb[p], so + WOFF + (bn + p * 16 + lbr) * 80 + bcol);
            #pragma unroll
            for (int fm = 0; fm < 2; fm++)
                #pragma unroll
                for (int p = 0; p < 4; p++) {
                    mma16816(c[fm][2 * p],     ah[fm], bb[p]);
                    mma16816(c[fm][2 * p + 1], ah[fm], bb[p] + 2);
                    if (NPASS == 3) {
                        mma16816(c[fm][2 * p],     al[fm], bb[p]);
                        mma16816(c[fm][2 * p + 1], al[fm], bb[p] + 2);
                    }
                }
            if (NPASS == 3) {
                #pragma unroll
                for (int p = 0; p < 4; p++)
                    ldsm4(bb[p], so + WOFF + TILEB + (bn + p * 16 + lbr) * 80 + bcol);
                #pragma unroll
                for (int fm = 0; fm < 2; fm++)
                    #pragma unroll
                    for (int p = 0; p < 4; p++) {
                        mma16816(c[fm][2 * p],     ah[fm], bb[p]);
                        mma16816(c[fm][2 * p + 1], ah[fm], bb[p] + 2);
                    }
            }
        }
        __syncthreads();
    }
#undef ISSUE

    // epilogue
    const int r0 = m0 + am + (lane >> 2);
    const int colb = n0 + bn + (lane & 3) * 2;
    #pragma unroll
    for (int fm = 0; fm < 2; fm++) {
        #pragma unroll
        for (int p = 0; p < 8; p++) {
            const int col = colb + p * 8;
            const float2 bv = *(const float2*)(bias + col);
            #pragma unroll
            for (int hh = 0; hh < 2; hh++) {
                const int row = r0 + fm * 16 + hh * 8;
                if (row < M) {
                    float o0 = c[fm][p][hh * 2 + 0] + bv.x;
                    float o1 = c[fm][p][hh * 2 + 1] + bv.y;
                    if (RESID) {
                        float2 rv = *(const float2*)(R + (size_t)row * N + col);
                        o0 += rv.x; o1 += rv.y;
                    }
                    if (RELU) { o0 = fmaxf(o0, 0.f); o1 = fmaxf(o1, 0.f); }
                    if (OUT == 0) {
                        *(float2*)(C + (size_t)row * N + col) = make_float2(o0, o1);
                    } else if (OUT == 1) {
                        *(__nv_bfloat162*)(Ch + (size_t)row * N + col) = __floats2bfloat162_rn(o0, o1);
                    } else {
                        __nv_bfloat162 h, l;
                        split2(o0, o1, h, l);
                        *(__nv_bfloat162*)(Ch + (size_t)row * N + col) = h;
                        *(__nv_bfloat162*)(Cl + (size_t)row * N + col) = l;
                    }
                }
            }
        }
    }
}

// ---------------- flash self-attention, bf16 mma.sync ----------------
// grid (8, NH, B), 256 threads (8 warps). Warp w owns query rows 16w..16w+15.
__global__ __launch_bounds__(256)
void attn_mma(const __nv_bfloat16* __restrict__ qkv, __nv_bfloat16* __restrict__ sa)
{
    __shared__ __nv_bfloat16 Qs[128 * 40];   // 80B row stride (32 bf16 + pad)
    __shared__ __nv_bfloat16 Ks[64 * 40];
    __shared__ __nv_bfloat16 Vs[64 * 40];
    const int b = blockIdx.z, h = blockIdx.y, q0 = blockIdx.x * 128;
    const int tid = threadIdx.x, lane = tid & 31, wid = tid >> 5;
    const uint32_t sQ = smem_u32(Qs), sK = smem_u32(Ks), sV = smem_u32(Vs);

    // load Q tile (128 rows x 32ch)
    #pragma unroll
    for (int i = tid; i < 512; i += 256) {
        int r = i >> 2, cc = i & 3;
        const __nv_bfloat16* src = qkv + (size_t)(b * Q_ + q0 + r) * 768 + h * HD + cc * 8;
        cpasync16(sQ + r * 80 + cc * 16, src, (q0 + r) < Q_ ? 16 : 0);
    }
    asm volatile("cp.async.commit_group;" ::: "memory");
    asm volatile("cp.async.wait_group 0;" ::: "memory");
    __syncthreads();

    const int r8 = (lane & 7) + ((lane >> 3) & 1) * 8;
    const int c16 = (lane >> 4) * 16;

    uint32_t qf[2][4];
    {
        uint32_t qa = sQ + (wid * 16 + r8) * 80 + c16;
        ldsm4(qf[0], qa);
        ldsm4(qf[1], qa + 32);
    }

    float mr[2] = {-1e30f, -1e30f}, lr[2] = {0.f, 0.f};
    float o[4][4] = {};
    const float scale = 0.17677669529663687f;

    for (int t = 0; t < 15; t++) {
        const int kv0 = t * 64;
        __syncthreads();
        #pragma unroll
        for (int i = tid; i < 512; i += 256) {
            int te = i >> 8, idx = i & 255, r = idx >> 2, cc = idx & 3;
            const __nv_bfloat16* src = qkv + (size_t)(b * Q_ + kv0 + r) * 768
                                       + 256 + te * 256 + h * HD + cc * 8;
            cpasync16((te ? sV : sK) + r * 80 + cc * 16, src, (kv0 + r) < Q_ ? 16 : 0);
        }
        asm volatile("cp.async.commit_group;" ::: "memory");
        asm volatile("cp.async.wait_group 0;" ::: "memory");
        __syncthreads();

        // scores: 16x64 per warp
        float c[8][4] = {};
        #pragma unroll
        for (int ks = 0; ks < 2; ks++) {
            #pragma unroll
            for (int p = 0; p < 4; p++) {
                uint32_t kf[4];
                ldsm4(kf, sK + (p * 16 + r8) * 80 + c16 + ks * 32);
                uint32_t b0[2] = {kf[0], kf[2]}, b1[2] = {kf[1], kf[3]};
                mma16816(c[2 * p],     qf[ks], b0);
                mma16816(c[2 * p + 1], qf[ks], b1);
            }
        }
        #pragma unroll
        for (int p8 = 0; p8 < 8; p8++)
            #pragma unroll
            for (int j = 0; j < 4; j++) c[p8][j] *= scale;
        if (kv0 + 64 > Q_) {
            #pragma unroll
            for (int p8 = 0; p8 < 8; p8++)
                #pragma unroll
                for (int j = 0; j < 2; j++)
                    if (kv0 + p8 * 8 + 2 * (lane & 3) + j >= Q_) {
                        c[p8][j] = -1e30f;
                        c[p8][2 + j] = -1e30f;
                    }
        }
        // online softmax (2 rows per lane: r and r+8)
        #pragma unroll
        for (int rw = 0; rw < 2; rw++) {
            float mx = mr[rw];
            #pragma unroll
            for (int p8 = 0; p8 < 8; p8++)
                mx = fmaxf(mx, fmaxf(c[p8][2 * rw], c[p8][2 * rw + 1]));
            mx = fmaxf(mx, __shfl_xor_sync(0xffffffffu, mx, 1));
            mx = fmaxf(mx, __shfl_xor_sync(0xffffffffu, mx, 2));
            float corr = __expf(mr[rw] - mx);
            float s = 0.f;
            #pragma unroll
            for (int p8 = 0; p8 < 8; p8++) {
                c[p8][2 * rw]     = __expf(c[p8][2 * rw] - mx);
                c[p8][2 * rw + 1] = __expf(c[p8][2 * rw + 1] - mx);
                s += c[p8][2 * rw] + c[p8][2 * rw + 1];
            }
            s += __shfl_xor_sync(0xffffffffu, s, 1);
            s += __shfl_xor_sync(0xffffffffu, s, 2);
            lr[rw] = lr[rw] * corr + s;
            mr[rw] = mx;
            #pragma unroll
            for (int nt = 0; nt < 4; nt++) {
                o[nt][2 * rw] *= corr;
                o[nt][2 * rw + 1] *= corr;
            }
        }
        // PV: P[16x64] x V[64x32]
        #pragma unroll
        for (int ts = 0; ts < 4; ts++) {
            uint32_t af[4];
            af[0] = pack_bf16(c[2 * ts][0], c[2 * ts][1]);
            af[1] = pack_bf16(c[2 * ts][2], c[2 * ts][3]);
            af[2] = pack_bf16(c[2 * ts + 1][0], c[2 * ts + 1][1]);
            af[3] = pack_bf16(c[2 * ts + 1][2], c[2 * ts + 1][3]);
            #pragma unroll
            for (int np = 0; np < 2; np++) {
                uint32_t vf[4];
                ldsm4t(vf, sV + (ts * 16 + r8) * 80 + np * 32 + c16);
                uint32_t b0[2] = {vf[0], vf[1]}, b1[2] = {vf[2], vf[3]};
                mma16816(o[2 * np],     af, b0);
                mma16816(o[2 * np + 1], af, b1);
            }
        }
    }

    const float inv0 = 1.f / lr[0], inv1 = 1.f / lr[1];
    const int gr0 = q0 + wid * 16 + (lane >> 2);
    #pragma unroll
    for (int nt = 0; nt < 4; nt++) {
        const int col = h * HD + nt * 8 + 2 * (lane & 3);
        if (gr0 < Q_)
            *(__nv_bfloat162*)(sa + (size_t)(b * Q_ + gr0) * DM + col)
                = __floats2bfloat162_rn(o[nt][0] * inv0, o[nt][1] * inv0);
        if (gr0 + 8 < Q_)
            *(__nv_bfloat162*)(sa + (size_t)(b * Q_ + gr0 + 8) * DM + col)
                = __floats2bfloat162_rn(o[nt][2] * inv1, o[nt][3] * inv1);
    }
}

// ---------------- LayerNorm (row of 256), OSPLIT: 0 none, 1 hi, 2 hi+lo ----------------
template<int OSPLIT>
__global__ __launch_bounds__(256)
void ln_kernel(const float* __restrict__ in, const float* __restrict__ g,
               const float* __restrict__ bta, float* __restrict__ out,
               __nv_bfloat16* __restrict__ oh, __nv_bfloat16* __restrict__ ol)
{
    __shared__ float red[256];
    const int row = blockIdx.x, tid = threadIdx.x;
    float x = in[(size_t)row * DM + tid];

    red[tid] = x; __syncthreads();
    #pragma unroll
    for (int s = 128; s > 0; s >>= 1) {
        if (tid < s) red[tid] += red[tid + s];
        __syncthreads();
    }
    float mu = red[0] * (1.f / 256.f);
    __syncthreads();

    float dx = x - mu;
    red[tid] = dx * dx; __syncthreads();
    #pragma unroll
    for (int s = 128; s > 0; s >>= 1) {
        if (tid < s) red[tid] += red[tid + s];
        __syncthreads();
    }
    float var = red[0] * (1.f / 256.f);
    float rs = rsqrtf(var + 1e-5f);
    float y = dx * rs * g[tid] + bta[tid];
    const size_t idx = (size_t)row * DM + tid;
    out[idx] = y;
    if (OSPLIT >= 1) {
        __nv_bfloat16 hv = __float2bfloat16(y);
        oh[idx] = hv;
        if (OSPLIT == 2) ol[idx] = __float2bfloat16(y - __bfloat162float(hv));
    }
}

// ---------------- deformable sampling + weight softmax (bf16 value) ----------------
__global__ __launch_bounds__(256)
void deform_kernel(const float* __restrict__ off, const float* __restrict__ awl,
                   const __nv_bfloat16* __restrict__ value, const float* __restrict__ refp,
                   __nv_bfloat16* __restrict__ outh, __nv_bfloat16* __restrict__ outl)
{
    const int gw = (blockIdx.x * blockDim.x + threadIdx.x) >> 5;
    const int lane = threadIdx.x & 31;
    if (gw >= B_ * Q_ * NH) return;
    const int h = gw & 7;
    const int q = (gw >> 3) % Q_;
    const int b = gw / (NH * Q_);
    const size_t bq = (size_t)b * Q_ + q;

    float logit = (lane < 16) ? awl[bq * 128 + h * 16 + lane] : -1e30f;
    float mx = logit;
    #pragma unroll
    for (int o = 16; o > 0; o >>= 1) mx = fmaxf(mx, __shfl_xor_sync(0xffffffffu, mx, o));
    float e = (lane < 16) ? __expf(logit - mx) : 0.f;
    float se = e;
    #pragma unroll
    for (int o = 16; o > 0; o >>= 1) se += __shfl_xor_sync(0xffffffffu, se, o);
    const float aw = e / se;

    const int HWl[4][2] = {{100,100},{50,50},{25,25},{13,13}};
    const int ST[4]     = {0, 10000, 12500, 13125};

    float accv = 0.f;
    #pragma unroll
    for (int lvl = 0; lvl < 4; lvl++) {
        const int Hi = HWl[lvl][0], Wi = HWl[lvl][1];
        const float Hl = (float)Hi, Wl = (float)Wi;
        const float refx = refp[(bq * 4 + lvl) * 2 + 0];
        const float refy = refp[(bq * 4 + lvl) * 2 + 1];
        const __nv_bfloat16* vbase = value + ((size_t)b * STOT + ST[lvl]) * DM + h * HD + lane;
        #pragma unroll
        for (int p = 0; p < 4; p++) {
            const int oidx = ((h * 4 + lvl) * 4 + p) * 2;
            const float ox = off[bq * DM + oidx + 0];
            const float oy = off[bq * DM + oidx + 1];
            const float x = (refx + ox / Wl) * Wl - 0.5f;
            const float y = (refy + oy / Hl) * Hl - 0.5f;
            const float x0 = floorf(x), y0 = floorf(y);
            float samp = 0.f;
            #pragma unroll
            for (int cq = 0; cq < 4; cq++) {
                const float xi = x0 + (float)(cq & 1);
                const float yi = y0 + (float)(cq >> 1);
                const float w = (1.f - fabsf(x - xi)) * (1.f - fabsf(y - yi));
                if (xi >= 0.f && xi < Wl && yi >= 0.f && yi < Hl && w != 0.f) {
                    const int ii = (int)yi * Wi + (int)xi;
                    samp += w * __bfloat162float(vbase[(size_t)ii * DM]);
                }
            }
            const float awp = __shfl_sync(0xffffffffu, aw, lvl * 4 + p);
            accv += awp * samp;
        }
    }
    const size_t oi = bq * DM + h * HD + lane;
    __nv_bfloat16 hv = __float2bfloat16(accv);
    outh[oi] = hv;
    outl[oi] = __float2bfloat16(accv - __bfloat162float(hv));
}

// ---------------- launch ----------------
extern "C" void kernel_launch(void* const* d_in, const int* in_sizes, int n_in,
                              void* d_out, int out_size)
{
    (void)in_sizes; (void)n_in; (void)out_size;
    const float* tgt   = (const float*)d_in[0];
    const float* mem   = (const float*)d_in[1];
    const float* refp  = (const float*)d_in[3];
    const float* ipw = (const float*)d_in[6],  *ipb = (const float*)d_in[7];
    const float* opw = (const float*)d_in[8],  *opb = (const float*)d_in[9];
    const float* n1g = (const float*)d_in[10], *n1b = (const float*)d_in[11];
    const float* n2g = (const float*)d_in[12], *n2b = (const float*)d_in[13];
    const float* n3g = (const float*)d_in[14], *n3b = (const float*)d_in[15];
    const float* sow = (const float*)d_in[16], *sob = (const float*)d_in[17];
    const float* aww = (const float*)d_in[18], *awb = (const float*)d_in[19];
    const float* vpw = (const float*)d_in[20], *vpb = (const float*)d_in[21];
    const float* oqw = (const float*)d_in[22], *oqb = (const float*)d_in[23];
    const float* l1w = (const float*)d_in[24], *l1b = (const float*)d_in[25];
    const float* l2w = (const float*)d_in[26], *l2b = (const float*)d_in[27];
    float* out = (float*)d_out;

    float *buf, *tgt1, *tgt2, *offb, *awlb;
    cudaGetSymbolAddress((void**)&buf,  g_buf);
    cudaGetSymbolAddress((void**)&tgt1, g_tgt1);
    cudaGetSymbolAddress((void**)&tgt2, g_tgt2);
    cudaGetSymbolAddress((void**)&offb, g_off);
    cudaGetSymbolAddress((void**)&awlb, g_awl);

    __nv_bfloat16 *p_qkv, *p_sa, *p_tgt, *p_tgt1, *p_mem, *p_val, *p_ca, *p_tgt2, *p_ffn1;
    __nv_bfloat16 *p_ipw, *p_opw, *p_vpw, *p_sow, *p_aww, *p_oqw, *p_l1w, *p_l2w;
    cudaGetSymbolAddress((void**)&p_qkv,  b_qkv);
    cudaGetSymbolAddress((void**)&p_sa,   b_sa);
    cudaGetSymbolAddress((void**)&p_tgt,  b_tgt);
    cudaGetSymbolAddress((void**)&p_tgt1, b_tgt1);
    cudaGetSymbolAddress((void**)&p_mem,  b_mem);
    cudaGetSymbolAddress((void**)&p_val,  b_val);
    cudaGetSymbolAddress((void**)&p_ca,   b_ca);
    cudaGetSymbolAddress((void**)&p_tgt2, b_tgt2);
    cudaGetSymbolAddress((void**)&p_ffn1, b_ffn1);
    cudaGetSymbolAddress((void**)&p_ipw,  b_ipw);
    cudaGetSymbolAddress((void**)&p_opw,  b_opw);
    cudaGetSymbolAddress((void**)&p_vpw,  b_vpw);
    cudaGetSymbolAddress((void**)&p_sow,  b_sow);
    cudaGetSymbolAddress((void**)&p_aww,  b_aww);
    cudaGetSymbolAddress((void**)&p_oqw,  b_oqw);
    cudaGetSymbolAddress((void**)&p_l1w,  b_l1w);
    cudaGetSymbolAddress((void**)&p_l2w,  b_l2w);

    const int SMEM1 = 2 * 2 * TILEB;   // 40960
    const int SMEM3 = 2 * 4 * TILEB;   // 81920
    cudaFuncSetAttribute(gemm_mma<1, false, false, 1>, cudaFuncAttributeMaxDynamicSharedMemorySize, SMEM1);
    cudaFuncSetAttribute(gemm_mma<1, false, false, 0>, cudaFuncAttributeMaxDynamicSharedMemorySize, SMEM1);
    cudaFuncSetAttribute(gemm_mma<1, false, true,  0>, cudaFuncAttributeMaxDynamicSharedMemorySize, SMEM1);
    cudaFuncSetAttribute(gemm_mma<3, false, true,  0>, cudaFuncAttributeMaxDynamicSharedMemorySize, SMEM3);
    cudaFuncSetAttribute(gemm_mma<3, true,  false, 2>, cudaFuncAttributeMaxDynamicSharedMemorySize, SMEM3);

    const int MT  = (BQ + 127) / 128;    // 57
    const int MTV = (BS + 127) / 128;    // 831

#define CONV(src, dst, n) \
    conv_hi_kernel<<<((n) / 4 + 255) / 256, 256>>>((src), (dst), (n) / 4)
#define SPLIT(src, dst, n) \
    split_kernel<<<((n) / 4 + 255) / 256, 256>>>((src), (dst), (dst) + (n), (n) / 4)
#define HL(p, n) (p), (p) + (n)

    // ---- conversions ----
    CONV(tgt, p_tgt, BQ * DM);
    CONV(mem, p_mem, (int)((size_t)BS * DM));
    CONV(ipw, p_ipw, 768 * 256);
    CONV(opw, p_opw, 256 * 256);
    CONV(vpw, p_vpw, 256 * 256);
    CONV(sow, p_sow, 256 * 256);
    CONV(aww, p_aww, 128 * 256);
    SPLIT(oqw, p_oqw, 256 * 256);
    SPLIT(l1w, p_l1w, 1024 * 256);
    SPLIT(l2w, p_l2w, 256 * 1024);

    // 1. QKV projection (x1, bf16 out)
    gemm_mma<1, false, false, 1><<<dim3(6, MT), 256, SMEM1>>>(
        p_tgt, nullptr, p_ipw, nullptr, ipb, nullptr, nullptr, p_qkv, nullptr, BQ, 768, DM);
    // 2. flash self-attention (bf16 mma)
    attn_mma<<<dim3(8, NH, B_), 256>>>(p_qkv, p_sa);
    // 3. out-proj + residual (x1), 4. LN1 (hi split)
    gemm_mma<1, false, true, 0><<<dim3(2, MT), 256, SMEM1>>>(
        p_sa, nullptr, p_opw, nullptr, opb, tgt, buf, nullptr, nullptr, BQ, DM, DM);
    ln_kernel<1><<<BQ, 256>>>(buf, n1g, n1b, tgt1, p_tgt1, nullptr);
    // 5. value projection (x1, bf16 out)
    gemm_mma<1, false, false, 1><<<dim3(2, MTV), 256, SMEM1>>>(
        p_mem, nullptr, p_vpw, nullptr, vpb, nullptr, nullptr, p_val, nullptr, BS, DM, DM);
    // 6. sampling offsets (x1), 7. attention-weight logits (x1)
    gemm_mma<1, false, false, 0><<<dim3(2, MT), 256, SMEM1>>>(
        p_tgt1, nullptr, p_sow, nullptr, sob, nullptr, offb, nullptr, nullptr, BQ, DM, DM);
    gemm_mma<1, false, false, 0><<<dim3(1, MT), 256, SMEM1>>>(
        p_tgt1, nullptr, p_aww, nullptr, awb, nullptr, awlb, nullptr, nullptr, BQ, 128, DM);
    // 8. deformable sampling -> split ca
    deform_kernel<<<(B_ * Q_ * NH * 32 + 255) / 256, 256>>>(offb, awlb, p_val, refp, HL(p_ca, BQ * DM));
    // 9. output proj + residual (x3), 10. LN2 (hi+lo split)
    gemm_mma<3, false, true, 0><<<dim3(2, MT), 256, SMEM3>>>(
        HL(p_ca, BQ * DM), HL(p_oqw, 256 * 256), oqb, tgt1, buf, nullptr, nullptr, BQ, DM, DM);
    ln_kernel<2><<<BQ, 256>>>(buf, n2g, n2b, tgt2, HL(p_tgt2, BQ * DM));
    // 11. FFN up + relu (x3, split out), 12. FFN down + residual (x3), 13. LN3 -> out
    gemm_mma<3, true, false, 2><<<dim3(8, MT), 256, SMEM3>>>(
        HL(p_tgt2, BQ * DM), HL(p_l1w, 1024 * 256), l1b, nullptr, nullptr, HL(p_ffn1, BQ * DFFN), BQ, DFFN, DM);
    gemm_mma<3, false, true, 0><<<dim3(2, MT), 256, SMEM3>>>(
        HL(p_ffn1, BQ * DFFN), HL(p_l2w, 256 * 1024), l2b, tgt2, buf, nullptr, nullptr, BQ, DM, DFFN);
    ln_kernel<0><<<BQ, 256>>>(buf, n3g, n3b, out, nullptr, nullptr);
#undef HL
#undef SPLIT
#undef CONV
}

// round 7
// speedup vs baseline: 3.0470x; 1.1930x over previous
#include <cuda_runtime.h>
#include <cuda_bf16.h>
#include <math.h>
#include <stdint.h>

// ---------------- problem constants ----------------
#define B_      8
#define Q_      900
#define BQ      7200          // B*Q
#define DM      256
#define STOT    13294
#define BS      106352        // B*STOT
#define NH      8
#define HD      32
#define DFFN    1024

// ---------------- fp32 scratch ----------------
__device__ float g_buf  [BQ * DM];
__device__ float g_tgt1 [BQ * DM];
__device__ float g_tgt2 [BQ * DM];
__device__ float g_offaw[BQ * 384];
__device__ float g_soawb[384];

// ---------------- bf16 scratch ----------------
__device__ __nv_bfloat16 b_qkv [BQ * 768];
__device__ __nv_bfloat16 b_sa  [BQ * DM];
__device__ __nv_bfloat16 b_tgt1[BQ * DM];
__device__ __nv_bfloat16 b_val [(size_t)BS * DM];
__device__ __nv_bfloat16 b_ca  [2][BQ * DM];
__device__ __nv_bfloat16 b_tgt2[2][BQ * DM];
__device__ __nv_bfloat16 b_ffn1[2][BQ * DFFN];
__device__ __nv_bfloat16 b_ipw [768 * 256];
__device__ __nv_bfloat16 b_opw [256 * 256];
__device__ __nv_bfloat16 b_vpw [256 * 256];
__device__ __nv_bfloat16 b_soaw[384 * 256];      // sow (256 rows) ++ aww (128 rows)
__device__ __nv_bfloat16 b_oqw [2][256 * 256];
__device__ __nv_bfloat16 b_l1w [2][1024 * 256];
__device__ __nv_bfloat16 b_l2w [2][256 * 1024];

// ---------------- helpers ----------------
__device__ __forceinline__ uint32_t smem_u32(const void* p) {
    uint32_t a;
    asm("{ .reg .u64 t; cvta.to.shared.u64 t, %1; cvt.u32.u64 %0, t; }" : "=r"(a) : "l"(p));
    return a;
}
__device__ __forceinline__ void ldsm4(uint32_t* r, uint32_t addr) {
    asm volatile("ldmatrix.sync.aligned.m8n8.x4.shared.b16 {%0,%1,%2,%3}, [%4];"
        : "=r"(r[0]), "=r"(r[1]), "=r"(r[2]), "=r"(r[3]) : "r"(addr));
}
__device__ __forceinline__ void ldsm4t(uint32_t* r, uint32_t addr) {
    asm volatile("ldmatrix.sync.aligned.m8n8.x4.trans.shared.b16 {%0,%1,%2,%3}, [%4];"
        : "=r"(r[0]), "=r"(r[1]), "=r"(r[2]), "=r"(r[3]) : "r"(addr));
}
__device__ __forceinline__ void mma16816(float* c, const uint32_t* a, const uint32_t* b) {
    asm volatile("mma.sync.aligned.m16n8k16.row.col.f32.bf16.bf16.f32 "
        "{%0,%1,%2,%3}, {%4,%5,%6,%7}, {%8,%9}, {%0,%1,%2,%3};"
        : "+f"(c[0]), "+f"(c[1]), "+f"(c[2]), "+f"(c[3])
        : "r"(a[0]), "r"(a[1]), "r"(a[2]), "r"(a[3]), "r"(b[0]), "r"(b[1]));
}
__device__ __forceinline__ void cpasync16(uint32_t dst, const void* src, int sz) {
    asm volatile("cp.async.cg.shared.global [%0], [%1], 16, %2;" :: "r"(dst), "l"(src), "r"(sz));
}
__device__ __forceinline__ void split2(float a, float b, __nv_bfloat162& h, __nv_bfloat162& l) {
    h = __floats2bfloat162_rn(a, b);
    float2 hf = __bfloat1622float2(h);
    l = __floats2bfloat162_rn(a - hf.x, b - hf.y);
}
__device__ __forceinline__ uint32_t pack_bf16(float a, float b) {
    __nv_bfloat162 h = __floats2bfloat162_rn(a, b);
    return *reinterpret_cast<uint32_t*>(&h);
}

// ---------------- fp32 -> bf16 converters (weights only) ----------------
__global__ __launch_bounds__(256)
void split_kernel(const float* __restrict__ in, __nv_bfloat16* __restrict__ hi,
                  __nv_bfloat16* __restrict__ lo, int n4)
{
    int i = blockIdx.x * 256 + threadIdx.x;
    if (i >= n4) return;
    float4 v = ((const float4*)in)[i];
    __nv_bfloat162 h0, l0, h1, l1;
    split2(v.x, v.y, h0, l0);
    split2(v.z, v.w, h1, l1);
    ((__nv_bfloat162*)hi)[i * 2 + 0] = h0;
    ((__nv_bfloat162*)hi)[i * 2 + 1] = h1;
    ((__nv_bfloat162*)lo)[i * 2 + 0] = l0;
    ((__nv_bfloat162*)lo)[i * 2 + 1] = l1;
}
__global__ __launch_bounds__(256)
void conv_hi_kernel(const float* __restrict__ in, __nv_bfloat16* __restrict__ hi, int n4)
{
    int i = blockIdx.x * 256 + threadIdx.x;
    if (i >= n4) return;
    float4 v = ((const float4*)in)[i];
    ((__nv_bfloat162*)hi)[i * 2 + 0] = __floats2bfloat162_rn(v.x, v.y);
    ((__nv_bfloat162*)hi)[i * 2 + 1] = __floats2bfloat162_rn(v.z, v.w);
}

// ---------------- bf16 mma.sync GEMM ----------------
// C[M,N] = A[M,K] @ W[N,K]^T + bias (+R) (+relu).
// CTA tile 128x128, BK=32, 256 threads (8 warps, 4m x 2n -> warp tile 32x64).
// NPASS: 1 = plain bf16, 3 = hi/lo split x3.
// OUT: 0 = fp32 C, 1 = bf16 Ch, 2 = bf16 Ch+Cl.
// AFP32: A read as fp32 (Af) with register-pipelined inline conversion.
#define TILEB 10240

template<int NPASS, bool RELU, bool RESID, int OUT, bool AFP32>
__global__ __launch_bounds__(256)
void gemm_mma(const float* __restrict__ Af,
              const __nv_bfloat16* __restrict__ Ah, const __nv_bfloat16* __restrict__ Al,
              const __nv_bfloat16* __restrict__ Wh, const __nv_bfloat16* __restrict__ Wl,
              const float* __restrict__ bias, const float* __restrict__ R,
              float* __restrict__ C, __nv_bfloat16* __restrict__ Ch,
              __nv_bfloat16* __restrict__ Cl, int M, int N, int K)
{
    constexpr int NTIL = (NPASS == 3) ? 4 : 2;
    constexpr int STGB = NTIL * TILEB;
    constexpr int WOFF = (NPASS == 3 ? 2 : 1) * TILEB;

    extern __shared__ char smem[];
    const uint32_t sb = smem_u32(smem);
    const int tid = threadIdx.x, lane = tid & 31, wid = tid >> 5;
    const int am = (wid & 3) * 32;
    const int bn = (wid >> 2) * 64;
    const int m0 = blockIdx.y * 128, n0 = blockIdx.x * 128;

    float c[2][8][4] = {};

    // A fp32 register pipeline state (AFP32 only): 2 positions x 8 floats
    float4 aReg[2][2];
    const int pr0 = tid >> 2, pq = tid & 3;           // u=0 -> row pr0, u=1 -> row pr0+64

#define LDG_A(ch) do {                                                            \
    const int kb_ = (ch) * 32;                                                    \
    _Pragma("unroll")                                                             \
    for (int u_ = 0; u_ < 2; u_++) {                                              \
        int r_ = pr0 + u_ * 64;                                                   \
        int row_ = m0 + r_; if (row_ >= M) row_ = M - 1;                          \
        const float* p_ = Af + (size_t)row_ * K + kb_ + pq * 8;                   \
        aReg[u_][0] = *(const float4*)p_;                                         \
        aReg[u_][1] = *(const float4*)(p_ + 4);                                   \
    }                                                                             \
} while (0)

#define STS_A(st) do {                                                            \
    _Pragma("unroll")                                                             \
    for (int u_ = 0; u_ < 2; u_++) {                                              \
        int r_ = pr0 + u_ * 64;                                                   \
        uint4 w4_;                                                                \
        w4_.x = pack_bf16(aReg[u_][0].x, aReg[u_][0].y);                          \
        w4_.y = pack_bf16(aReg[u_][0].z, aReg[u_][0].w);                          \
        w4_.z = pack_bf16(aReg[u_][1].x, aReg[u_][1].y);                          \
        w4_.w = pack_bf16(aReg[u_][1].z, aReg[u_][1].w);                          \
        *(uint4*)(smem + (st) * STGB + r_ * 80 + pq * 16) = w4_;                  \
    }                                                                             \
} while (0)

#define ISSUE_W(st, ch) do {                                                      \
    const int kb_ = (ch) * 32;                                                    \
    const uint32_t so_ = sb + (st) * STGB;                                        \
    _Pragma("unroll")                                                             \
    for (int cix = tid; cix < (NPASS == 3 ? 1024 : 512); cix += 256) {            \
        int t_ = cix >> 9, idx_ = cix & 511, r_ = idx_ >> 2, q_ = idx_ & 3;       \
        const __nv_bfloat16* base_ = t_ ? Wl : Wh;                                \
        cpasync16(so_ + WOFF + t_ * TILEB + r_ * 80 + q_ * 16,                    \
                  base_ + (size_t)(n0 + r_) * K + kb_ + q_ * 8, 16);              \
    }                                                                             \
    asm volatile("cp.async.commit_group;" ::: "memory");                          \
} while (0)

#define ISSUE_AB(st, ch) do {                                                     \
    const int kb_ = (ch) * 32;                                                    \
    const uint32_t so_ = sb + (st) * STGB;                                        \
    _Pragma("unroll")                                                             \
    for (int cix = tid; cix < NTIL * 512; cix += 256) {                           \
        int t_ = cix >> 9, idx_ = cix & 511, r_ = idx_ >> 2, q_ = idx_ & 3;       \
        uint32_t d_ = so_ + t_ * TILEB + r_ * 80 + q_ * 16;                       \
        const __nv_bfloat16* base_;                                               \
        bool isA_;                                                                \
        if (NPASS == 1) { isA_ = (t_ == 0); base_ = isA_ ? Ah : Wh; }             \
        else { isA_ = (t_ < 2);                                                   \
               base_ = (t_ == 0 ? Ah : t_ == 1 ? Al : t_ == 2 ? Wh : Wl); }       \
        if (isA_) cpasync16(d_, base_ + (size_t)(m0 + r_) * K + kb_ + q_ * 8,     \
                            (m0 + r_) < M ? 16 : 0);                              \
        else      cpasync16(d_, base_ + (size_t)(n0 + r_) * K + kb_ + q_ * 8, 16);\
    }                                                                             \
    asm volatile("cp.async.commit_group;" ::: "memory");                          \
} while (0)

    const int nCh = K >> 5;
    if (AFP32) {
        LDG_A(0);
        ISSUE_W(0, 0);
    } else {
        ISSUE_AB(0, 0);
    }

    const int lar = lane & 15;
    const int lac = (lane >> 4) * 16;
    const int lbr = (lane & 7) + ((lane >> 4) & 1) * 8;
    const int lbc = ((lane >> 3) & 1) * 16;

    for (int ch = 0; ch < nCh; ch++) {
        if (AFP32) {
            STS_A(ch & 1);
            if (ch + 1 < nCh) {
                LDG_A(ch + 1);
                ISSUE_W((ch + 1) & 1, ch + 1);
                asm volatile("cp.async.wait_group 1;" ::: "memory");
            } else {
                asm volatile("cp.async.wait_group 0;" ::: "memory");
            }
        } else {
            if (ch + 1 < nCh) {
                ISSUE_AB((ch + 1) & 1, ch + 1);
                asm volatile("cp.async.wait_group 1;" ::: "memory");
            } else {
                asm volatile("cp.async.wait_group 0;" ::: "memory");
            }
        }
        __syncthreads();

        const uint32_t so = sb + (ch & 1) * STGB;
        #pragma unroll
        for (int ks = 0; ks < 2; ks++) {
            uint32_t ah[2][4], al[2][4], bb[4][4];
            const uint32_t acol = ks * 32 + lac;
            const uint32_t bcol = ks * 32 + lbc;
            ldsm4(ah[0], so + (am + lar) * 80 + acol);
            ldsm4(ah[1], so + (am + 16 + lar) * 80 + acol);
            if (NPASS == 3) {
                ldsm4(al[0], so + TILEB + (am + lar) * 80 + acol);
                ldsm4(al[1], so + TILEB + (am + 16 + lar) * 80 + acol);
            }
            #pragma unroll
            for (int p = 0; p < 4; p++)
                ldsm4(bb[p], so + WOFF + (bn + p * 16 + lbr) * 80 + bcol);
            #pragma unroll
            for (int fm = 0; fm < 2; fm++)
                #pragma unroll
                for (int p = 0; p < 4; p++) {
                    mma16816(c[fm][2 * p],     ah[fm], bb[p]);
                    mma16816(c[fm][2 * p + 1], ah[fm], bb[p] + 2);
                    if (NPASS == 3) {
                        mma16816(c[fm][2 * p],     al[fm], bb[p]);
                        mma16816(c[fm][2 * p + 1], al[fm], bb[p] + 2);
                    }
                }
            if (NPASS == 3) {
                #pragma unroll
                for (int p = 0; p < 4; p++)
                    ldsm4(bb[p], so + WOFF + TILEB + (bn + p * 16 + lbr) * 80 + bcol);
                #pragma unroll
                for (int fm = 0; fm < 2; fm++)
                    #pragma unroll
                    for (int p = 0; p < 4; p++) {
                        mma16816(c[fm][2 * p],     ah[fm], bb[p]);
                        mma16816(c[fm][2 * p + 1], ah[fm], bb[p] + 2);
                    }
            }
        }
        __syncthreads();
    }
#undef ISSUE_AB
#undef ISSUE_W
#undef STS_A
#undef LDG_A

    // epilogue
    const int r0 = m0 + am + (lane >> 2);
    const int colb = n0 + bn + (lane & 3) * 2;
    #pragma unroll
    for (int fm = 0; fm < 2; fm++) {
        #pragma unroll
        for (int p = 0; p < 8; p++) {
            const int col = colb + p * 8;
            const float2 bv = *(const float2*)(bias + col);
            #pragma unroll
            for (int hh = 0; hh < 2; hh++) {
                const int row = r0 + fm * 16 + hh * 8;
                if (row < M) {
                    float o0 = c[fm][p][hh * 2 + 0] + bv.x;
                    float o1 = c[fm][p][hh * 2 + 1] + bv.y;
                    if (RESID) {
                        float2 rv = *(const float2*)(R + (size_t)row * N + col);
                        o0 += rv.x; o1 += rv.y;
                    }
                    if (RELU) { o0 = fmaxf(o0, 0.f); o1 = fmaxf(o1, 0.f); }
                    if (OUT == 0) {
                        *(float2*)(C + (size_t)row * N + col) = make_float2(o0, o1);
                    } else if (OUT == 1) {
                        *(__nv_bfloat162*)(Ch + (size_t)row * N + col) = __floats2bfloat162_rn(o0, o1);
                    } else {
                        __nv_bfloat162 h, l;
                        split2(o0, o1, h, l);
                        *(__nv_bfloat162*)(Ch + (size_t)row * N + col) = h;
                        *(__nv_bfloat162*)(Cl + (size_t)row * N + col) = l;
                    }
                }
            }
        }
    }
}

// ---------------- flash self-attention, bf16 mma.sync ----------------
// grid (8, NH, B), 256 threads (8 warps). Warp w owns query rows 16w..16w+15.
__global__ __launch_bounds__(256)
void attn_mma(const __nv_bfloat16* __restrict__ qkv, __nv_bfloat16* __restrict__ sa)
{
    __shared__ __nv_bfloat16 Qs[128 * 40];   // 80B row stride
    __shared__ __nv_bfloat16 Ks[64 * 40];
    __shared__ __nv_bfloat16 Vs[64 * 40];
    const int b = blockIdx.z, h = blockIdx.y, q0 = blockIdx.x * 128;
    const int tid = threadIdx.x, lane = tid & 31, wid = tid >> 5;
    const uint32_t sQ = smem_u32(Qs), sK = smem_u32(Ks), sV = smem_u32(Vs);

    #pragma unroll
    for (int i = tid; i < 512; i += 256) {
        int r = i >> 2, cc = i & 3;
        const __nv_bfloat16* src = qkv + (size_t)(b * Q_ + q0 + r) * 768 + h * HD + cc * 8;
        cpasync16(sQ + r * 80 + cc * 16, src, (q0 + r) < Q_ ? 16 : 0);
    }
    asm volatile("cp.async.commit_group;" ::: "memory");
    asm volatile("cp.async.wait_group 0;" ::: "memory");
    __syncthreads();

    const int r8 = (lane & 7) + ((lane >> 3) & 1) * 8;
    const int c16 = (lane >> 4) * 16;

    uint32_t qf[2][4];
    {
        uint32_t qa = sQ + (wid * 16 + r8) * 80 + c16;
        ldsm4(qf[0], qa);
        ldsm4(qf[1], qa + 32);
    }

    float mr[2] = {-1e30f, -1e30f}, lr[2] = {0.f, 0.f};
    float o[4][4] = {};
    const float scale = 0.17677669529663687f;

    for (int t = 0; t < 15; t++) {
        const int kv0 = t * 64;
        __syncthreads();
        #pragma unroll
        for (int i = tid; i < 512; i += 256) {
            int te = i >> 8, idx = i & 255, r = idx >> 2, cc = idx & 3;
            const __nv_bfloat16* src = qkv + (size_t)(b * Q_ + kv0 + r) * 768
                                       + 256 + te * 256 + h * HD + cc * 8;
            cpasync16((te ? sV : sK) + r * 80 + cc * 16, src, (kv0 + r) < Q_ ? 16 : 0);
        }
        asm volatile("cp.async.commit_group;" ::: "memory");
        asm volatile("cp.async.wait_group 0;" ::: "memory");
        __syncthreads();

        float c[8][4] = {};
        #pragma unroll
        for (int ks = 0; ks < 2; ks++) {
            #pragma unroll
            for (int p = 0; p < 4; p++) {
                uint32_t kf[4];
                ldsm4(kf, sK + (p * 16 + r8) * 80 + c16 + ks * 32);
                uint32_t b0[2] = {kf[0], kf[2]}, b1[2] = {kf[1], kf[3]};
                mma16816(c[2 * p],     qf[ks], b0);
                mma16816(c[2 * p + 1], qf[ks], b1);
            }
        }
        #pragma unroll
        for (int p8 = 0; p8 < 8; p8++)
            #pragma unroll
            for (int j = 0; j < 4; j++) c[p8][j] *= scale;
        if (kv0 + 64 > Q_) {
            #pragma unroll
            for (int p8 = 0; p8 < 8; p8++)
                #pragma unroll
                for (int j = 0; j < 2; j++)
                    if (kv0 + p8 * 8 + 2 * (lane & 3) + j >= Q_) {
                        c[p8][j] = -1e30f;
                        c[p8][2 + j] = -1e30f;
                    }
        }
        #pragma unroll
        for (int rw = 0; rw < 2; rw++) {
            float mx = mr[rw];
            #pragma unroll
            for (int p8 = 0; p8 < 8; p8++)
                mx = fmaxf(mx, fmaxf(c[p8][2 * rw], c[p8][2 * rw + 1]));
            mx = fmaxf(mx, __shfl_xor_sync(0xffffffffu, mx, 1));
            mx = fmaxf(mx, __shfl_xor_sync(0xffffffffu, mx, 2));
            float corr = __expf(mr[rw] - mx);
            float s = 0.f;
            #pragma unroll
            for (int p8 = 0; p8 < 8; p8++) {
                c[p8][2 * rw]     = __expf(c[p8][2 * rw] - mx);
                c[p8][2 * rw + 1] = __expf(c[p8][2 * rw + 1] - mx);
                s += c[p8][2 * rw] + c[p8][2 * rw + 1];
            }
            s += __shfl_xor_sync(0xffffffffu, s, 1);
            s += __shfl_xor_sync(0xffffffffu, s, 2);
            lr[rw] = lr[rw] * corr + s;
            mr[rw] = mx;
            #pragma unroll
            for (int nt = 0; nt < 4; nt++) {
                o[nt][2 * rw] *= corr;
                o[nt][2 * rw + 1] *= corr;
            }
        }
        #pragma unroll
        for (int ts = 0; ts < 4; ts++) {
            uint32_t af[4];
            af[0] = pack_bf16(c[2 * ts][0], c[2 * ts][1]);
            af[1] = pack_bf16(c[2 * ts][2], c[2 * ts][3]);
            af[2] = pack_bf16(c[2 * ts + 1][0], c[2 * ts + 1][1]);
            af[3] = pack_bf16(c[2 * ts + 1][2], c[2 * ts + 1][3]);
            #pragma unroll
            for (int np = 0; np < 2; np++) {
                uint32_t vf[4];
                ldsm4t(vf, sV + (ts * 16 + r8) * 80 + np * 32 + c16);
                uint32_t b0[2] = {vf[0], vf[1]}, b1[2] = {vf[2], vf[3]};
                mma16816(o[2 * np],     af, b0);
                mma16816(o[2 * np + 1], af, b1);
            }
        }
    }

    const float inv0 = 1.f / lr[0], inv1 = 1.f / lr[1];
    const int gr0 = q0 + wid * 16 + (lane >> 2);
    #pragma unroll
    for (int nt = 0; nt < 4; nt++) {
        const int col = h * HD + nt * 8 + 2 * (lane & 3);
        if (gr0 < Q_)
            *(__nv_bfloat162*)(sa + (size_t)(b * Q_ + gr0) * DM + col)
                = __floats2bfloat162_rn(o[nt][0] * inv0, o[nt][1] * inv0);
        if (gr0 + 8 < Q_)
            *(__nv_bfloat162*)(sa + (size_t)(b * Q_ + gr0 + 8) * DM + col)
                = __floats2bfloat162_rn(o[nt][2] * inv1, o[nt][3] * inv1);
    }
}

// ---------------- LayerNorm: warp per row, 8 rows/CTA ----------------
// OSPLIT: 0 none, 1 hi, 2 hi+lo
template<int OSPLIT>
__global__ __launch_bounds__(256)
void ln_kernel(const float* __restrict__ in, const float* __restrict__ g,
               const float* __restrict__ bta, float* __restrict__ out,
               __nv_bfloat16* __restrict__ oh, __nv_bfloat16* __restrict__ ol)
{
    const int warp = threadIdx.x >> 5, lane = threadIdx.x & 31;
    const int row = blockIdx.x * 8 + warp;
    const float4* ip = (const float4*)(in + (size_t)row * DM);
    float4 v0 = ip[lane], v1 = ip[lane + 32];

    float s = ((v0.x + v0.y) + (v0.z + v0.w)) + ((v1.x + v1.y) + (v1.z + v1.w));
    #pragma unroll
    for (int o = 16; o > 0; o >>= 1) s += __shfl_xor_sync(0xffffffffu, s, o);
    const float mu = s * (1.f / 256.f);

    v0.x -= mu; v0.y -= mu; v0.z -= mu; v0.w -= mu;
    v1.x -= mu; v1.y -= mu; v1.z -= mu; v1.w -= mu;
    float vs = ((v0.x * v0.x + v0.y * v0.y) + (v0.z * v0.z + v0.w * v0.w))
             + ((v1.x * v1.x + v1.y * v1.y) + (v1.z * v1.z + v1.w * v1.w));
    #pragma unroll
    for (int o = 16; o > 0; o >>= 1) vs += __shfl_xor_sync(0xffffffffu, vs, o);
    const float rs = rsqrtf(vs * (1.f / 256.f) + 1e-5f);

    const float4 g0 = ((const float4*)g)[lane],  g1 = ((const float4*)g)[lane + 32];
    const float4 b0 = ((const float4*)bta)[lane], b1 = ((const float4*)bta)[lane + 32];
    float4 y0, y1;
    y0.x = v0.x * rs * g0.x + b0.x; y0.y = v0.y * rs * g0.y + b0.y;
    y0.z = v0.z * rs * g0.z + b0.z; y0.w = v0.w * rs * g0.w + b0.w;
    y1.x = v1.x * rs * g1.x + b1.x; y1.y = v1.y * rs * g1.y + b1.y;
    y1.z = v1.z * rs * g1.z + b1.z; y1.w = v1.w * rs * g1.w + b1.w;

    float4* op = (float4*)(out + (size_t)row * DM);
    op[lane] = y0; op[lane + 32] = y1;

    if (OSPLIT >= 1) {
        const size_t i0 = (size_t)row * DM + lane * 4;
        const size_t i1 = i0 + 128;
        if (OSPLIT == 1) {
            *(__nv_bfloat162*)(oh + i0)     = __floats2bfloat162_rn(y0.x, y0.y);
            *(__nv_bfloat162*)(oh + i0 + 2) = __floats2bfloat162_rn(y0.z, y0.w);
            *(__nv_bfloat162*)(oh + i1)     = __floats2bfloat162_rn(y1.x, y1.y);
            *(__nv_bfloat162*)(oh + i1 + 2) = __floats2bfloat162_rn(y1.z, y1.w);
        } else {
            __nv_bfloat162 h, l;
            split2(y0.x, y0.y, h, l);
            *(__nv_bfloat162*)(oh + i0) = h;     *(__nv_bfloat162*)(ol + i0) = l;
            split2(y0.z, y0.w, h, l);
            *(__nv_bfloat162*)(oh + i0 + 2) = h; *(__nv_bfloat162*)(ol + i0 + 2) = l;
            split2(y1.x, y1.y, h, l);
            *(__nv_bfloat162*)(oh + i1) = h;     *(__nv_bfloat162*)(ol + i1) = l;
            split2(y1.z, y1.w, h, l);
            *(__nv_bfloat162*)(oh + i1 + 2) = h; *(__nv_bfloat162*)(ol + i1 + 2) = l;
        }
    }
}

// ---------------- deformable sampling + weight softmax (fused offaw buffer) ----------------
__global__ __launch_bounds__(256)
void deform_kernel(const float* __restrict__ offaw,
                   const __nv_bfloat16* __restrict__ value, const float* __restrict__ refp,
                   __nv_bfloat16* __restrict__ outh, __nv_bfloat16* __restrict__ outl)
{
    const int gw = (blockIdx.x * blockDim.x + threadIdx.x) >> 5;
    const int lane = threadIdx.x & 31;
    if (gw >= B_ * Q_ * NH) return;
    const int h = gw & 7;
    const int q = (gw >> 3) % Q_;
    const int b = gw / (NH * Q_);
    const size_t bq = (size_t)b * Q_ + q;

    float logit = (lane < 16) ? offaw[bq * 384 + 256 + h * 16 + lane] : -1e30f;
    float mx = logit;
    #pragma unroll
    for (int o = 16; o > 0; o >>= 1) mx = fmaxf(mx, __shfl_xor_sync(0xffffffffu, mx, o));
    float e = (lane < 16) ? __expf(logit - mx) : 0.f;
    float se = e;
    #pragma unroll
    for (int o = 16; o > 0; o >>= 1) se += __shfl_xor_sync(0xffffffffu, se, o);
    const float aw = e / se;

    const int HWl[4][2] = {{100,100},{50,50},{25,25},{13,13}};
    const int ST[4]     = {0, 10000, 12500, 13125};

    float accv = 0.f;
    #pragma unroll
    for (int lvl = 0; lvl < 4; lvl++) {
        const int Hi = HWl[lvl][0], Wi = HWl[lvl][1];
        const float Hl = (float)Hi, Wl = (float)Wi;
        const float refx = refp[(bq * 4 + lvl) * 2 + 0];
        const float refy = refp[(bq * 4 + lvl) * 2 + 1];
        const __nv_bfloat16* vbase = value + ((size_t)b * STOT + ST[lvl]) * DM + h * HD + lane;
        #pragma unroll
        for (int p = 0; p < 4; p++) {
            const int oidx = ((h * 4 + lvl) * 4 + p) * 2;
            const float ox = offaw[bq * 384 + oidx + 0];
            const float oy = offaw[bq * 384 + oidx + 1];
            const float x = (refx + ox / Wl) * Wl - 0.5f;
            const float y = (refy + oy / Hl) * Hl - 0.5f;
            const float x0 = floorf(x), y0 = floorf(y);
            float samp = 0.f;
            #pragma unroll
            for (int cq = 0; cq < 4; cq++) {
                const float xi = x0 + (float)(cq & 1);
                const float yi = y0 + (float)(cq >> 1);
                const float w = (1.f - fabsf(x - xi)) * (1.f - fabsf(y - yi));
                if (xi >= 0.f && xi < Wl && yi >= 0.f && yi < Hl && w != 0.f) {
                    const int ii = (int)yi * Wi + (int)xi;
                    samp += w * __bfloat162float(vbase[(size_t)ii * DM]);
                }
            }
            const float awp = __shfl_sync(0xffffffffu, aw, lvl * 4 + p);
            accv += awp * samp;
        }
    }
    const size_t oi = bq * DM + h * HD + lane;
    __nv_bfloat16 hv = __float2bfloat16(accv);
    outh[oi] = hv;
    outl[oi] = __float2bfloat16(accv - __bfloat162float(hv));
}

// ---------------- launch ----------------
extern "C" void kernel_launch(void* const* d_in, const int* in_sizes, int n_in,
                              void* d_out, int out_size)
{
    (void)in_sizes; (void)n_in; (void)out_size;
    const float* tgt   = (const float*)d_in[0];
    const float* mem   = (const float*)d_in[1];
    const float* refp  = (const float*)d_in[3];
    const float* ipw = (const float*)d_in[6],  *ipb = (const float*)d_in[7];
    const float* opw = (const float*)d_in[8],  *opb = (const float*)d_in[9];
    const float* n1g = (const float*)d_in[10], *n1b = (const float*)d_in[11];
    const float* n2g = (const float*)d_in[12], *n2b = (const float*)d_in[13];
    const float* n3g = (const float*)d_in[14], *n3b = (const float*)d_in[15];
    const float* sow = (const float*)d_in[16], *sob = (const float*)d_in[17];
    const float* aww = (const float*)d_in[18], *awb = (const float*)d_in[19];
    const float* vpw = (const float*)d_in[20], *vpb = (const float*)d_in[21];
    const float* oqw = (const float*)d_in[22], *oqb = (const float*)d_in[23];
    const float* l1w = (const float*)d_in[24], *l1b = (const float*)d_in[25];
    const float* l2w = (const float*)d_in[26], *l2b = (const float*)d_in[27];
    float* out = (float*)d_out;

    float *buf, *tgt1, *tgt2, *offaw, *soawb;
    cudaGetSymbolAddress((void**)&buf,   g_buf);
    cudaGetSymbolAddress((void**)&tgt1,  g_tgt1);
    cudaGetSymbolAddress((void**)&tgt2,  g_tgt2);
    cudaGetSymbolAddress((void**)&offaw, g_offaw);
    cudaGetSymbolAddress((void**)&soawb, g_soawb);

    __nv_bfloat16 *p_qkv, *p_sa, *p_tgt1, *p_val, *p_ca, *p_tgt2, *p_ffn1;
    __nv_bfloat16 *p_ipw, *p_opw, *p_vpw, *p_soaw, *p_oqw, *p_l1w, *p_l2w;
    cudaGetSymbolAddress((void**)&p_qkv,  b_qkv);
    cudaGetSymbolAddress((void**)&p_sa,   b_sa);
    cudaGetSymbolAddress((void**)&p_tgt1, b_tgt1);
    cudaGetSymbolAddress((void**)&p_val,  b_val);
    cudaGetSymbolAddress((void**)&p_ca,   b_ca);
    cudaGetSymbolAddress((void**)&p_tgt2, b_tgt2);
    cudaGetSymbolAddress((void**)&p_ffn1, b_ffn1);
    cudaGetSymbolAddress((void**)&p_ipw,  b_ipw);
    cudaGetSymbolAddress((void**)&p_opw,  b_opw);
    cudaGetSymbolAddress((void**)&p_vpw,  b_vpw);
    cudaGetSymbolAddress((void**)&p_soaw, b_soaw);
    cudaGetSymbolAddress((void**)&p_oqw,  b_oqw);
    cudaGetSymbolAddress((void**)&p_l1w,  b_l1w);
    cudaGetSymbolAddress((void**)&p_l2w,  b_l2w);

    const int SMEM1 = 2 * 2 * TILEB;   // 40960
    const int SMEM3 = 2 * 4 * TILEB;   // 81920
    cudaFuncSetAttribute(gemm_mma<1, false, false, 1, true >, cudaFuncAttributeMaxDynamicSharedMemorySize, SMEM1);
    cudaFuncSetAttribute(gemm_mma<1, false, true,  0, false>, cudaFuncAttributeMaxDynamicSharedMemorySize, SMEM1);
    cudaFuncSetAttribute(gemm_mma<1, false, false, 0, false>, cudaFuncAttributeMaxDynamicSharedMemorySize, SMEM1);
    cudaFuncSetAttribute(gemm_mma<3, false, true,  0, false>, cudaFuncAttributeMaxDynamicSharedMemorySize, SMEM3);
    cudaFuncSetAttribute(gemm_mma<3, true,  false, 2, false>, cudaFuncAttributeMaxDynamicSharedMemorySize, SMEM3);

    const int MT  = (BQ + 127) / 128;    // 57
    const int MTV = (BS + 127) / 128;    // 831

#define CONV(src, dst, n) \
    conv_hi_kernel<<<((n) / 4 + 255) / 256, 256>>>((src), (dst), (n) / 4)
#define SPLIT(src, dst, n) \
    split_kernel<<<((n) / 4 + 255) / 256, 256>>>((src), (dst), (dst) + (n), (n) / 4)
#define HL(p, n) (p), (p) + (n)

    // ---- weight conversions + fused soaw bias ----
    CONV(ipw, p_ipw, 768 * 256);
    CONV(opw, p_opw, 256 * 256);
    CONV(vpw, p_vpw, 256 * 256);
    CONV(sow, p_soaw, 256 * 256);
    CONV(aww, p_soaw + 256 * 256, 128 * 256);
    SPLIT(oqw, p_oqw, 256 * 256);
    SPLIT(l1w, p_l1w, 1024 * 256);
    SPLIT(l2w, p_l2w, 256 * 1024);
    cudaMemcpyAsync(soawb,       sob, 256 * sizeof(float), cudaMemcpyDeviceToDevice);
    cudaMemcpyAsync(soawb + 256, awb, 128 * sizeof(float), cudaMemcpyDeviceToDevice);

    // 1. QKV projection (AFP32, x1, bf16 out)
    gemm_mma<1, false, false, 1, true><<<dim3(6, MT), 256, SMEM1>>>(
        tgt, nullptr, nullptr, p_ipw, nullptr, ipb, nullptr, nullptr, p_qkv, nullptr, BQ, 768, DM);
    // 2. flash self-attention
    attn_mma<<<dim3(8, NH, B_), 256>>>(p_qkv, p_sa);
    // 3. out-proj + residual (x1), 4. LN1 (hi split)
    gemm_mma<1, false, true, 0, false><<<dim3(2, MT), 256, SMEM1>>>(
        nullptr, p_sa, nullptr, p_opw, nullptr, opb, tgt, buf, nullptr, nullptr, BQ, DM, DM);
    ln_kernel<1><<<BQ / 8, 256>>>(buf, n1g, n1b, tgt1, p_tgt1, nullptr);
    // 5. value projection (AFP32, x1, bf16 out)
    gemm_mma<1, false, false, 1, true><<<dim3(2, MTV), 256, SMEM1>>>(
        mem, nullptr, nullptr, p_vpw, nullptr, vpb, nullptr, nullptr, p_val, nullptr, BS, DM, DM);
    // 6+7. fused sampling offsets + attention-weight logits (N=384)
    gemm_mma<1, false, false, 0, false><<<dim3(3, MT), 256, SMEM1>>>(
        nullptr, p_tgt1, nullptr, p_soaw, nullptr, soawb, nullptr, offaw, nullptr, nullptr, BQ, 384, DM);
    // 8. deformable sampling -> split ca
    deform_kernel<<<(B_ * Q_ * NH * 32 + 255) / 256, 256>>>(offaw, p_val, refp, HL(p_ca, BQ * DM));
    // 9. output proj + residual (x3), 10. LN2 (hi+lo split)
    gemm_mma<3, false, true, 0, false><<<dim3(2, MT), 256, SMEM3>>>(
        nullptr, HL(p_ca, BQ * DM), HL(p_oqw, 256 * 256), oqb, tgt1, buf, nullptr, nullptr, BQ, DM, DM);
    ln_kernel<2><<<BQ / 8, 256>>>(buf, n2g, n2b, tgt2, HL(p_tgt2, BQ * DM));
    // 11. FFN up + relu (x3, split out), 12. FFN down + residual (x3), 13. LN3 -> out
    gemm_mma<3, true, false, 2, false><<<dim3(8, MT), 256, SMEM3>>>(
        nullptr, HL(p_tgt2, BQ * DM), HL(p_l1w, 1024 * 256), l1b, nullptr, nullptr, HL(p_ffn1, BQ * DFFN), BQ, DFFN, DM);
    gemm_mma<3, false, true, 0, false><<<dim3(2, MT), 256, SMEM3>>>(
        nullptr, HL(p_ffn1, BQ * DFFN), HL(p_l2w, 256 * 1024), l2b, tgt2, buf, nullptr, nullptr, BQ, DM, DFFN);
    ln_kernel<0><<<BQ / 8, 256>>>(buf, n3g, n3b, out, nullptr, nullptr);
#undef HL
#undef SPLIT
#undef CONV
}

// round 8
// speedup vs baseline: 3.2261x; 1.0588x over previous
#include <cuda_runtime.h>
#include <cuda_bf16.h>
#include <math.h>
#include <stdint.h>

// ---------------- problem constants ----------------
#define B_      8
#define Q_      900
#define BQ      7200          // B*Q
#define DM      256
#define STOT    13294
#define BS      106352        // B*STOT
#define NH      8
#define HD      32
#define DFFN    1024

// ---------------- fp32 scratch ----------------
__device__ float g_buf  [BQ * DM];
__device__ float g_tgt1 [BQ * DM];
__device__ float g_tgt2 [BQ * DM];
__device__ float g_offaw[BQ * 384];
__device__ float g_soawb[384];

// ---------------- bf16 scratch ----------------
__device__ __nv_bfloat16 b_qkv [BQ * 768];
__device__ __nv_bfloat16 b_sa  [BQ * DM];
__device__ __nv_bfloat16 b_tgt1[BQ * DM];
__device__ __nv_bfloat16 b_val [(size_t)BS * DM];
__device__ __nv_bfloat16 b_ca  [2][BQ * DM];
__device__ __nv_bfloat16 b_tgt2[2][BQ * DM];
__device__ __nv_bfloat16 b_ffn1[2][BQ * DFFN];
__device__ __nv_bfloat16 b_ipw [768 * 256];
__device__ __nv_bfloat16 b_opw [256 * 256];
__device__ __nv_bfloat16 b_vpw [256 * 256];
__device__ __nv_bfloat16 b_soaw[384 * 256];      // sow (256 rows) ++ aww (128 rows)
__device__ __nv_bfloat16 b_oqw [2][256 * 256];
__device__ __nv_bfloat16 b_l1w [2][1024 * 256];
__device__ __nv_bfloat16 b_l2w [2][256 * 1024];

// ---------------- helpers ----------------
__device__ __forceinline__ uint32_t smem_u32(const void* p) {
    uint32_t a;
    asm("{ .reg .u64 t; cvta.to.shared.u64 t, %1; cvt.u32.u64 %0, t; }" : "=r"(a) : "l"(p));
    return a;
}
__device__ __forceinline__ void ldsm4(uint32_t* r, uint32_t addr) {
    asm volatile("ldmatrix.sync.aligned.m8n8.x4.shared.b16 {%0,%1,%2,%3}, [%4];"
        : "=r"(r[0]), "=r"(r[1]), "=r"(r[2]), "=r"(r[3]) : "r"(addr));
}
__device__ __forceinline__ void ldsm4t(uint32_t* r, uint32_t addr) {
    asm volatile("ldmatrix.sync.aligned.m8n8.x4.trans.shared.b16 {%0,%1,%2,%3}, [%4];"
        : "=r"(r[0]), "=r"(r[1]), "=r"(r[2]), "=r"(r[3]) : "r"(addr));
}
__device__ __forceinline__ void mma16816(float* c, const uint32_t* a, const uint32_t* b) {
    asm volatile("mma.sync.aligned.m16n8k16.row.col.f32.bf16.bf16.f32 "
        "{%0,%1,%2,%3}, {%4,%5,%6,%7}, {%8,%9}, {%0,%1,%2,%3};"
        : "+f"(c[0]), "+f"(c[1]), "+f"(c[2]), "+f"(c[3])
        : "r"(a[0]), "r"(a[1]), "r"(a[2]), "r"(a[3]), "r"(b[0]), "r"(b[1]));
}
__device__ __forceinline__ void cpasync16(uint32_t dst, const void* src, int sz) {
    asm volatile("cp.async.cg.shared.global [%0], [%1], 16, %2;" :: "r"(dst), "l"(src), "r"(sz));
}
__device__ __forceinline__ void split2(float a, float b, __nv_bfloat162& h, __nv_bfloat162& l) {
    h = __floats2bfloat162_rn(a, b);
    float2 hf = __bfloat1622float2(h);
    l = __floats2bfloat162_rn(a - hf.x, b - hf.y);
}
__device__ __forceinline__ uint32_t pack_bf16(float a, float b) {
    __nv_bfloat162 h = __floats2bfloat162_rn(a, b);
    return *reinterpret_cast<uint32_t*>(&h);
}

// ---------------- one-shot weight conversion (all weights + fused bias) ----------------
// segments in float4 units:
//  [0,49152)        ipw   -> hi
//  [49152,65536)    opw   -> hi
//  [65536,81920)    vpw   -> hi
//  [81920,98304)    sow   -> soaw hi
//  [98304,106496)   aww   -> soaw+65536 hi
//  [106496,122880)  oqw   -> hi+lo
//  [122880,188416)  l1w   -> hi+lo
//  [188416,253952)  l2w   -> hi+lo
//  [253952,254048)  sob/awb -> soawb (fp32 copy)
__global__ __launch_bounds__(256)
void convert_all(const float* __restrict__ ipw, const float* __restrict__ opw,
                 const float* __restrict__ vpw, const float* __restrict__ sow,
                 const float* __restrict__ aww, const float* __restrict__ oqw,
                 const float* __restrict__ l1w, const float* __restrict__ l2w,
                 const float* __restrict__ sob, const float* __restrict__ awb,
                 __nv_bfloat16* __restrict__ d_ipw, __nv_bfloat16* __restrict__ d_opw,
                 __nv_bfloat16* __restrict__ d_vpw, __nv_bfloat16* __restrict__ d_soaw,
                 __nv_bfloat16* __restrict__ d_oqw, __nv_bfloat16* __restrict__ d_l1w,
                 __nv_bfloat16* __restrict__ d_l2w, float* __restrict__ soawb)
{
    const int i = blockIdx.x * 256 + threadIdx.x;
    const float* src;
    __nv_bfloat16* hi;
    __nv_bfloat16* lo = nullptr;
    int base;
    if (i < 49152)       { src = ipw; hi = d_ipw; base = 0; }
    else if (i < 65536)  { src = opw; hi = d_opw; base = 49152; }
    else if (i < 81920)  { src = vpw; hi = d_vpw; base = 65536; }
    else if (i < 98304)  { src = sow; hi = d_soaw; base = 81920; }
    else if (i < 106496) { src = aww; hi = d_soaw + 65536; base = 98304; }
    else if (i < 122880) { src = oqw; hi = d_oqw; lo = d_oqw + 65536; base = 106496; }
    else if (i < 188416) { src = l1w; hi = d_l1w; lo = d_l1w + 262144; base = 122880; }
    else if (i < 253952) { src = l2w; hi = d_l2w; lo = d_l2w + 262144; base = 188416; }
    else if (i < 254048) {
        const int j = i - 253952;
        float4 v = (j < 64) ? ((const float4*)sob)[j] : ((const float4*)awb)[j - 64];
        ((float4*)soawb)[j] = v;
        return;
    } else return;

    const int j = i - base;
    float4 v = ((const float4*)src)[j];
    if (lo == nullptr) {
        ((__nv_bfloat162*)hi)[j * 2 + 0] = __floats2bfloat162_rn(v.x, v.y);
        ((__nv_bfloat162*)hi)[j * 2 + 1] = __floats2bfloat162_rn(v.z, v.w);
    } else {
        __nv_bfloat162 h0, l0, h1, l1;
        split2(v.x, v.y, h0, l0);
        split2(v.z, v.w, h1, l1);
        ((__nv_bfloat162*)hi)[j * 2 + 0] = h0;
        ((__nv_bfloat162*)hi)[j * 2 + 1] = h1;
        ((__nv_bfloat162*)lo)[j * 2 + 0] = l0;
        ((__nv_bfloat162*)lo)[j * 2 + 1] = l1;
    }
}

// ---------------- bf16 mma.sync GEMM ----------------
// C[M,N] = A[M,K] @ W[N,K]^T + bias (+R) (+relu).
// CTA tile 128x128, BK=32, 256 threads (8 warps, 4m x 2n -> warp tile 32x64).
// NPASS: 1 = plain bf16, 3 = hi/lo split x3.
// OUT: 0 = fp32 C, 1 = bf16 Ch, 2 = bf16 Ch+Cl.
// AFP32: A read as fp32 (Af) with register-pipelined inline conversion.
#define TILEB 10240

template<int NPASS, bool RELU, bool RESID, int OUT, bool AFP32>
__global__ __launch_bounds__(256)
void gemm_mma(const float* __restrict__ Af,
              const __nv_bfloat16* __restrict__ Ah, const __nv_bfloat16* __restrict__ Al,
              const __nv_bfloat16* __restrict__ Wh, const __nv_bfloat16* __restrict__ Wl,
              const float* __restrict__ bias, const float* __restrict__ R,
              float* __restrict__ C, __nv_bfloat16* __restrict__ Ch,
              __nv_bfloat16* __restrict__ Cl, int M, int N, int K)
{
    constexpr int NTIL = (NPASS == 3) ? 4 : 2;
    constexpr int STGB = NTIL * TILEB;
    constexpr int WOFF = (NPASS == 3 ? 2 : 1) * TILEB;

    extern __shared__ char smem[];
    const uint32_t sb = smem_u32(smem);
    const int tid = threadIdx.x, lane = tid & 31, wid = tid >> 5;
    const int am = (wid & 3) * 32;
    const int bn = (wid >> 2) * 64;
    const int m0 = blockIdx.y * 128, n0 = blockIdx.x * 128;

    float c[2][8][4] = {};

    float4 aReg[2][2];
    const int pr0 = tid >> 2, pq = tid & 3;

#define LDG_A(ch) do {                                                            \
    const int kb_ = (ch) * 32;                                                    \
    _Pragma("unroll")                                                             \
    for (int u_ = 0; u_ < 2; u_++) {                                              \
        int r_ = pr0 + u_ * 64;                                                   \
        int row_ = m0 + r_; if (row_ >= M) row_ = M - 1;                          \
        const float* p_ = Af + (size_t)row_ * K + kb_ + pq * 8;                   \
        aReg[u_][0] = *(const float4*)p_;                                         \
        aReg[u_][1] = *(const float4*)(p_ + 4);                                   \
    }                                                                             \
} while (0)

#define STS_A(st) do {                                                            \
    _Pragma("unroll")                                                             \
    for (int u_ = 0; u_ < 2; u_++) {                                              \
        int r_ = pr0 + u_ * 64;                                                   \
        uint4 w4_;                                                                \
        w4_.x = pack_bf16(aReg[u_][0].x, aReg[u_][0].y);                          \
        w4_.y = pack_bf16(aReg[u_][0].z, aReg[u_][0].w);                          \
        w4_.z = pack_bf16(aReg[u_][1].x, aReg[u_][1].y);                          \
        w4_.w = pack_bf16(aReg[u_][1].z, aReg[u_][1].w);                          \
        *(uint4*)(smem + (st) * STGB + r_ * 80 + pq * 16) = w4_;                  \
    }                                                                             \
} while (0)

#define ISSUE_W(st, ch) do {                                                      \
    const int kb_ = (ch) * 32;                                                    \
    const uint32_t so_ = sb + (st) * STGB;                                        \
    _Pragma("unroll")                                                             \
    for (int cix = tid; cix < (NPASS == 3 ? 1024 : 512); cix += 256) {            \
        int t_ = cix >> 9, idx_ = cix & 511, r_ = idx_ >> 2, q_ = idx_ & 3;       \
        const __nv_bfloat16* base_ = t_ ? Wl : Wh;                                \
        cpasync16(so_ + WOFF + t_ * TILEB + r_ * 80 + q_ * 16,                    \
                  base_ + (size_t)(n0 + r_) * K + kb_ + q_ * 8, 16);              \
    }                                                                             \
    asm volatile("cp.async.commit_group;" ::: "memory");                          \
} while (0)

#define ISSUE_AB(st, ch) do {                                                     \
    const int kb_ = (ch) * 32;                                                    \
    const uint32_t so_ = sb + (st) * STGB;                                        \
    _Pragma("unroll")                                                             \
    for (int cix = tid; cix < NTIL * 512; cix += 256) {                           \
        int t_ = cix >> 9, idx_ = cix & 511, r_ = idx_ >> 2, q_ = idx_ & 3;       \
        uint32_t d_ = so_ + t_ * TILEB + r_ * 80 + q_ * 16;                       \
        const __nv_bfloat16* base_;                                               \
        bool isA_;                                                                \
        if (NPASS == 1) { isA_ = (t_ == 0); base_ = isA_ ? Ah : Wh; }             \
        else { isA_ = (t_ < 2);                                                   \
               base_ = (t_ == 0 ? Ah : t_ == 1 ? Al : t_ == 2 ? Wh : Wl); }       \
        if (isA_) cpasync16(d_, base_ + (size_t)(m0 + r_) * K + kb_ + q_ * 8,     \
                            (m0 + r_) < M ? 16 : 0);                              \
        else      cpasync16(d_, base_ + (size_t)(n0 + r_) * K + kb_ + q_ * 8, 16);\
    }                                                                             \
    asm volatile("cp.async.commit_group;" ::: "memory");                          \
} while (0)

    const int nCh = K >> 5;
    if (AFP32) {
        LDG_A(0);
        ISSUE_W(0, 0);
    } else {
        ISSUE_AB(0, 0);
    }

    const int lar = lane & 15;
    const int lac = (lane >> 4) * 16;
    const int lbr = (lane & 7) + ((lane >> 4) & 1) * 8;
    const int lbc = ((lane >> 3) & 1) * 16;

    for (int ch = 0; ch < nCh; ch++) {
        if (AFP32) {
            STS_A(ch & 1);
            if (ch + 1 < nCh) {
                LDG_A(ch + 1);
                ISSUE_W((ch + 1) & 1, ch + 1);
                asm volatile("cp.async.wait_group 1;" ::: "memory");
            } else {
                asm volatile("cp.async.wait_group 0;" ::: "memory");
            }
        } else {
            if (ch + 1 < nCh) {
                ISSUE_AB((ch + 1) & 1, ch + 1);
                asm volatile("cp.async.wait_group 1;" ::: "memory");
            } else {
                asm volatile("cp.async.wait_group 0;" ::: "memory");
            }
        }
        __syncthreads();

        const uint32_t so = sb + (ch & 1) * STGB;
        #pragma unroll
        for (int ks = 0; ks < 2; ks++) {
            uint32_t ah[2][4], al[2][4], bb[4][4];
            const uint32_t acol = ks * 32 + lac;
            const uint32_t bcol = ks * 32 + lbc;
            ldsm4(ah[0], so + (am + lar) * 80 + acol);
            ldsm4(ah[1], so + (am + 16 + lar) * 80 + acol);
            if (NPASS == 3) {
                ldsm4(al[0], so + TILEB + (am + lar) * 80 + acol);
                ldsm4(al[1], so + TILEB + (am + 16 + lar) * 80 + acol);
            }
            #pragma unroll
            for (int p = 0; p < 4; p++)
                ldsm4(bb[p], so + WOFF + (bn + p * 16 + lbr) * 80 + bcol);
            #pragma unroll
            for (int fm = 0; fm < 2; fm++)
                #pragma unroll
                for (int p = 0; p < 4; p++) {
                    mma16816(c[fm][2 * p],     ah[fm], bb[p]);
                    mma16816(c[fm][2 * p + 1], ah[fm], bb[p] + 2);
                    if (NPASS == 3) {
                        mma16816(c[fm][2 * p],     al[fm], bb[p]);
                        mma16816(c[fm][2 * p + 1], al[fm], bb[p] + 2);
                    }
                }
            if (NPASS == 3) {
                #pragma unroll
                for (int p = 0; p < 4; p++)
                    ldsm4(bb[p], so + WOFF + TILEB + (bn + p * 16 + lbr) * 80 + bcol);
                #pragma unroll
                for (int fm = 0; fm < 2; fm++)
                    #pragma unroll
                    for (int p = 0; p < 4; p++) {
                        mma16816(c[fm][2 * p],     ah[fm], bb[p]);
                        mma16816(c[fm][2 * p + 1], ah[fm], bb[p] + 2);
                    }
            }
        }
        __syncthreads();
    }
#undef ISSUE_AB
#undef ISSUE_W
#undef STS_A
#undef LDG_A

    // epilogue
    const int r0 = m0 + am + (lane >> 2);
    const int colb = n0 + bn + (lane & 3) * 2;
    #pragma unroll
    for (int fm = 0; fm < 2; fm++) {
        #pragma unroll
        for (int p = 0; p < 8; p++) {
            const int col = colb + p * 8;
            const float2 bv = *(const float2*)(bias + col);
            #pragma unroll
            for (int hh = 0; hh < 2; hh++) {
                const int row = r0 + fm * 16 + hh * 8;
                if (row < M) {
                    float o0 = c[fm][p][hh * 2 + 0] + bv.x;
                    float o1 = c[fm][p][hh * 2 + 1] + bv.y;
                    if (RESID) {
                        float2 rv = *(const float2*)(R + (size_t)row * N + col);
                        o0 += rv.x; o1 += rv.y;
                    }
                    if (RELU) { o0 = fmaxf(o0, 0.f); o1 = fmaxf(o1, 0.f); }
                    if (OUT == 0) {
                        *(float2*)(C + (size_t)row * N + col) = make_float2(o0, o1);
                    } else if (OUT == 1) {
                        *(__nv_bfloat162*)(Ch + (size_t)row * N + col) = __floats2bfloat162_rn(o0, o1);
                    } else {
                        __nv_bfloat162 h, l;
                        split2(o0, o1, h, l);
                        *(__nv_bfloat162*)(Ch + (size_t)row * N + col) = h;
                        *(__nv_bfloat162*)(Cl + (size_t)row * N + col) = l;
                    }
                }
            }
        }
    }
}

// ---------------- flash self-attention, bf16 mma.sync, double-buffered K/V ----------------
// grid (8, NH, B), 256 threads (8 warps). Warp w owns query rows 16w..16w+15.
#define KVB 5120

__global__ __launch_bounds__(256)
void attn_mma(const __nv_bfloat16* __restrict__ qkv, __nv_bfloat16* __restrict__ sa)
{
    __shared__ __nv_bfloat16 Qs[128 * 40];       // 80B row stride
    __shared__ __nv_bfloat16 Ks[2][64 * 40];
    __shared__ __nv_bfloat16 Vs[2][64 * 40];
    const int b = blockIdx.z, h = blockIdx.y, q0 = blockIdx.x * 128;
    const int tid = threadIdx.x, lane = tid & 31, wid = tid >> 5;
    const uint32_t sQ = smem_u32(Qs), sK = smem_u32(Ks), sV = smem_u32(Vs);

#define ISSUE_KV(t, bufi) do {                                                    \
    const int kv0_ = (t) * 64;                                                    \
    _Pragma("unroll")                                                             \
    for (int i_ = tid; i_ < 512; i_ += 256) {                                     \
        int te_ = i_ >> 8, idx_ = i_ & 255, r_ = idx_ >> 2, cc_ = idx_ & 3;       \
        const __nv_bfloat16* src_ = qkv + (size_t)(b * Q_ + kv0_ + r_) * 768      \
                                    + 256 + te_ * 256 + h * HD + cc_ * 8;         \
        cpasync16((te_ ? sV : sK) + (bufi) * KVB + r_ * 80 + cc_ * 16, src_,      \
                  (kv0_ + r_) < Q_ ? 16 : 0);                                     \
    }                                                                             \
    asm volatile("cp.async.commit_group;" ::: "memory");                          \
} while (0)

    // issue Q, then KV tile 0; wait only for Q
    #pragma unroll
    for (int i = tid; i < 512; i += 256) {
        int r = i >> 2, cc = i & 3;
        const __nv_bfloat16* src = qkv + (size_t)(b * Q_ + q0 + r) * 768 + h * HD + cc * 8;
        cpasync16(sQ + r * 80 + cc * 16, src, (q0 + r) < Q_ ? 16 : 0);
    }
    asm volatile("cp.async.commit_group;" ::: "memory");
    ISSUE_KV(0, 0);
    asm volatile("cp.async.wait_group 1;" ::: "memory");
    __syncthreads();

    const int r8 = (lane & 7) + ((lane >> 3) & 1) * 8;
    const int c16 = (lane >> 4) * 16;

    uint32_t qf[2][4];
    {
        uint32_t qa = sQ + (wid * 16 + r8) * 80 + c16;
        ldsm4(qf[0], qa);
        ldsm4(qf[1], qa + 32);
    }

    float mr[2] = {-1e30f, -1e30f}, lr[2] = {0.f, 0.f};
    float o[4][4] = {};
    const float scale = 0.17677669529663687f;

    for (int t = 0; t < 15; t++) {
        const int kv0 = t * 64;
        if (t + 1 < 15) {
            ISSUE_KV(t + 1, (t + 1) & 1);
            asm volatile("cp.async.wait_group 1;" ::: "memory");
        } else {
            asm volatile("cp.async.wait_group 0;" ::: "memory");
        }
        __syncthreads();

        const uint32_t sKb = sK + (t & 1) * KVB;
        const uint32_t sVb = sV + (t & 1) * KVB;

        float c[8][4] = {};
        #pragma unroll
        for (int ks = 0; ks < 2; ks++) {
            #pragma unroll
            for (int p = 0; p < 4; p++) {
                uint32_t kf[4];
                ldsm4(kf, sKb + (p * 16 + r8) * 80 + c16 + ks * 32);
                uint32_t b0[2] = {kf[0], kf[2]}, b1[2] = {kf[1], kf[3]};
                mma16816(c[2 * p],     qf[ks], b0);
                mma16816(c[2 * p + 1], qf[ks], b1);
            }
        }
        #pragma unroll
        for (int p8 = 0; p8 < 8; p8++)
            #pragma unroll
            for (int j = 0; j < 4; j++) c[p8][j] *= scale;
        if (kv0 + 64 > Q_) {
            #pragma unroll
            for (int p8 = 0; p8 < 8; p8++)
                #pragma unroll
                for (int j = 0; j < 2; j++)
                    if (kv0 + p8 * 8 + 2 * (lane & 3) + j >= Q_) {
                        c[p8][j] = -1e30f;
                        c[p8][2 + j] = -1e30f;
                    }
        }
        #pragma unroll
        for (int rw = 0; rw < 2; rw++) {
            float mx = mr[rw];
            #pragma unroll
            for (int p8 = 0; p8 < 8; p8++)
                mx = fmaxf(mx, fmaxf(c[p8][2 * rw], c[p8][2 * rw + 1]));
            mx = fmaxf(mx, __shfl_xor_sync(0xffffffffu, mx, 1));
            mx = fmaxf(mx, __shfl_xor_sync(0xffffffffu, mx, 2));
            float corr = __expf(mr[rw] - mx);
            float s = 0.f;
            #pragma unroll
            for (int p8 = 0; p8 < 8; p8++) {
                c[p8][2 * rw]     = __expf(c[p8][2 * rw] - mx);
                c[p8][2 * rw + 1] = __expf(c[p8][2 * rw + 1] - mx);
                s += c[p8][2 * rw] + c[p8][2 * rw + 1];
            }
            s += __shfl_xor_sync(0xffffffffu, s, 1);
            s += __shfl_xor_sync(0xffffffffu, s, 2);
            lr[rw] = lr[rw] * corr + s;
            mr[rw] = mx;
            #pragma unroll
            for (int nt = 0; nt < 4; nt++) {
                o[nt][2 * rw] *= corr;
                o[nt][2 * rw + 1] *= corr;
            }
        }
        #pragma unroll
        for (int ts = 0; ts < 4; ts++) {
            uint32_t af[4];
            af[0] = pack_bf16(c[2 * ts][0], c[2 * ts][1]);
            af[1] = pack_bf16(c[2 * ts][2], c[2 * ts][3]);
            af[2] = pack_bf16(c[2 * ts + 1][0], c[2 * ts + 1][1]);
            af[3] = pack_bf16(c[2 * ts + 1][2], c[2 * ts + 1][3]);
            #pragma unroll
            for (int np = 0; np < 2; np++) {
                uint32_t vf[4];
                ldsm4t(vf, sVb + (ts * 16 + r8) * 80 + np * 32 + c16);
                uint32_t b0[2] = {vf[0], vf[1]}, b1[2] = {vf[2], vf[3]};
                mma16816(o[2 * np],     af, b0);
                mma16816(o[2 * np + 1], af, b1);
            }
        }
        __syncthreads();   // protect buffer (t&1) before iteration t+1 overwrites it
    }
#undef ISSUE_KV

    const float inv0 = 1.f / lr[0], inv1 = 1.f / lr[1];
    const int gr0 = q0 + wid * 16 + (lane >> 2);
    #pragma unroll
    for (int nt = 0; nt < 4; nt++) {
        const int col = h * HD + nt * 8 + 2 * (lane & 3);
        if (gr0 < Q_)
            *(__nv_bfloat162*)(sa + (size_t)(b * Q_ + gr0) * DM + col)
                = __floats2bfloat162_rn(o[nt][0] * inv0, o[nt][1] * inv0);
        if (gr0 + 8 < Q_)
            *(__nv_bfloat162*)(sa + (size_t)(b * Q_ + gr0 + 8) * DM + col)
                = __floats2bfloat162_rn(o[nt][2] * inv1, o[nt][3] * inv1);
    }
}

// ---------------- LayerNorm: warp per row, 8 rows/CTA ----------------
// OSPLIT: 0 none, 1 hi, 2 hi+lo
template<int OSPLIT>
__global__ __launch_bounds__(256)
void ln_kernel(const float* __restrict__ in, const float* __restrict__ g,
               const float* __restrict__ bta, float* __restrict__ out,
               __nv_bfloat16* __restrict__ oh, __nv_bfloat16* __restrict__ ol)
{
    const int warp = threadIdx.x >> 5, lane = threadIdx.x & 31;
    const int row = blockIdx.x * 8 + warp;
    const float4* ip = (const float4*)(in + (size_t)row * DM);
    float4 v0 = ip[lane], v1 = ip[lane + 32];

    float s = ((v0.x + v0.y) + (v0.z + v0.w)) + ((v1.x + v1.y) + (v1.z + v1.w));
    #pragma unroll
    for (int o = 16; o > 0; o >>= 1) s += __shfl_xor_sync(0xffffffffu, s, o);
    const float mu = s * (1.f / 256.f);

    v0.x -= mu; v0.y -= mu; v0.z -= mu; v0.w -= mu;
    v1.x -= mu; v1.y -= mu; v1.z -= mu; v1.w -= mu;
    float vs = ((v0.x * v0.x + v0.y * v0.y) + (v0.z * v0.z + v0.w * v0.w))
             + ((v1.x * v1.x + v1.y * v1.y) + (v1.z * v1.z + v1.w * v1.w));
    #pragma unroll
    for (int o = 16; o > 0; o >>= 1) vs += __shfl_xor_sync(0xffffffffu, vs, o);
    const float rs = rsqrtf(vs * (1.f / 256.f) + 1e-5f);

    const float4 g0 = ((const float4*)g)[lane],  g1 = ((const float4*)g)[lane + 32];
    const float4 b0 = ((const float4*)bta)[lane], b1 = ((const float4*)bta)[lane + 32];
    float4 y0, y1;
    y0.x = v0.x * rs * g0.x + b0.x; y0.y = v0.y * rs * g0.y + b0.y;
    y0.z = v0.z * rs * g0.z + b0.z; y0.w = v0.w * rs * g0.w + b0.w;
    y1.x = v1.x * rs * g1.x + b1.x; y1.y = v1.y * rs * g1.y + b1.y;
    y1.z = v1.z * rs * g1.z + b1.z; y1.w = v1.w * rs * g1.w + b1.w;

    float4* op = (float4*)(out + (size_t)row * DM);
    op[lane] = y0; op[lane + 32] = y1;

    if (OSPLIT >= 1) {
        const size_t i0 = (size_t)row * DM + lane * 4;
        const size_t i1 = i0 + 128;
        if (OSPLIT == 1) {
            *(__nv_bfloat162*)(oh + i0)     = __floats2bfloat162_rn(y0.x, y0.y);
            *(__nv_bfloat162*)(oh + i0 + 2) = __floats2bfloat162_rn(y0.z, y0.w);
            *(__nv_bfloat162*)(oh + i1)     = __floats2bfloat162_rn(y1.x, y1.y);
            *(__nv_bfloat162*)(oh + i1 + 2) = __floats2bfloat162_rn(y1.z, y1.w);
        } else {
            __nv_bfloat162 h, l;
            split2(y0.x, y0.y, h, l);
            *(__nv_bfloat162*)(oh + i0) = h;     *(__nv_bfloat162*)(ol + i0) = l;
            split2(y0.z, y0.w, h, l);
            *(__nv_bfloat162*)(oh + i0 + 2) = h; *(__nv_bfloat162*)(ol + i0 + 2) = l;
            split2(y1.x, y1.y, h, l);
            *(__nv_bfloat162*)(oh + i1) = h;     *(__nv_bfloat162*)(ol + i1) = l;
            split2(y1.z, y1.w, h, l);
            *(__nv_bfloat162*)(oh + i1 + 2) = h; *(__nv_bfloat162*)(ol + i1 + 2) = l;
        }
    }
}

// ---------------- deformable sampling + weight softmax (fused offaw buffer) ----------------
__global__ __launch_bounds__(256)
void deform_kernel(const float* __restrict__ offaw,
                   const __nv_bfloat16* __restrict__ value, const float* __restrict__ refp,
                   __nv_bfloat16* __restrict__ outh, __nv_bfloat16* __restrict__ outl)
{
    const int gw = (blockIdx.x * blockDim.x + threadIdx.x) >> 5;
    const int lane = threadIdx.x & 31;
    if (gw >= B_ * Q_ * NH) return;
    const int h = gw & 7;
    const int q = (gw >> 3) % Q_;
    const int b = gw / (NH * Q_);
    const size_t bq = (size_t)b * Q_ + q;

    float logit = (lane < 16) ? offaw[bq * 384 + 256 + h * 16 + lane] : -1e30f;
    float mx = logit;
    #pragma unroll
    for (int o = 16; o > 0; o >>= 1) mx = fmaxf(mx, __shfl_xor_sync(0xffffffffu, mx, o));
    float e = (lane < 16) ? __expf(logit - mx) : 0.f;
    float se = e;
    #pragma unroll
    for (int o = 16; o > 0; o >>= 1) se += __shfl_xor_sync(0xffffffffu, se, o);
    const float aw = e / se;

    const int HWl[4][2] = {{100,100},{50,50},{25,25},{13,13}};
    const int ST[4]     = {0, 10000, 12500, 13125};

    float accv = 0.f;
    #pragma unroll
    for (int lvl = 0; lvl < 4; lvl++) {
        const int Hi = HWl[lvl][0], Wi = HWl[lvl][1];
        const float Hl = (float)Hi, Wl = (float)Wi;
        const float refx = refp[(bq * 4 + lvl) * 2 + 0];
        const float refy = refp[(bq * 4 + lvl) * 2 + 1];
        const __nv_bfloat16* vbase = value + ((size_t)b * STOT + ST[lvl]) * DM + h * HD + lane;
        #pragma unroll
        for (int p = 0; p < 4; p++) {
            const int oidx = ((h * 4 + lvl) * 4 + p) * 2;
            const float ox = offaw[bq * 384 + oidx + 0];
            const float oy = offaw[bq * 384 + oidx + 1];
            const float x = (refx + ox / Wl) * Wl - 0.5f;
            const float y = (refy + oy / Hl) * Hl - 0.5f;
            const float x0 = floorf(x), y0 = floorf(y);
            float samp = 0.f;
            #pragma unroll
            for (int cq = 0; cq < 4; cq++) {
                const float xi = x0 + (float)(cq & 1);
                const float yi = y0 + (float)(cq >> 1);
                const float w = (1.f - fabsf(x - xi)) * (1.f - fabsf(y - yi));
                if (xi >= 0.f && xi < Wl && yi >= 0.f && yi < Hl && w != 0.f) {
                    const int ii = (int)yi * Wi + (int)xi;
                    samp += w * __bfloat162float(vbase[(size_t)ii * DM]);
                }
            }
            const float awp = __shfl_sync(0xffffffffu, aw, lvl * 4 + p);
            accv += awp * samp;
        }
    }
    const size_t oi = bq * DM + h * HD + lane;
    __nv_bfloat16 hv = __float2bfloat16(accv);
    outh[oi] = hv;
    outl[oi] = __float2bfloat16(accv - __bfloat162float(hv));
}

// ---------------- launch ----------------
extern "C" void kernel_launch(void* const* d_in, const int* in_sizes, int n_in,
                              void* d_out, int out_size)
{
    (void)in_sizes; (void)n_in; (void)out_size;
    const float* tgt   = (const float*)d_in[0];
    const float* mem   = (const float*)d_in[1];
    const float* refp  = (const float*)d_in[3];
    const float* ipw = (const float*)d_in[6],  *ipb = (const float*)d_in[7];
    const float* opw = (const float*)d_in[8],  *opb = (const float*)d_in[9];
    const float* n1g = (const float*)d_in[10], *n1b = (const float*)d_in[11];
    const float* n2g = (const float*)d_in[12], *n2b = (const float*)d_in[13];
    const float* n3g = (const float*)d_in[14], *n3b = (const float*)d_in[15];
    const float* sow = (const float*)d_in[16], *sob = (const float*)d_in[17];
    const float* aww = (const float*)d_in[18], *awb = (const float*)d_in[19];
    const float* vpw = (const float*)d_in[20], *vpb = (const float*)d_in[21];
    const float* oqw = (const float*)d_in[22], *oqb = (const float*)d_in[23];
    const float* l1w = (const float*)d_in[24], *l1b = (const float*)d_in[25];
    const float* l2w = (const float*)d_in[26], *l2b = (const float*)d_in[27];
    float* out = (float*)d_out;

    float *buf, *tgt1, *tgt2, *offaw, *soawb;
    cudaGetSymbolAddress((void**)&buf,   g_buf);
    cudaGetSymbolAddress((void**)&tgt1,  g_tgt1);
    cudaGetSymbolAddress((void**)&tgt2,  g_tgt2);
    cudaGetSymbolAddress((void**)&offaw, g_offaw);
    cudaGetSymbolAddress((void**)&soawb, g_soawb);

    __nv_bfloat16 *p_qkv, *p_sa, *p_tgt1, *p_val, *p_ca, *p_tgt2, *p_ffn1;
    __nv_bfloat16 *p_ipw, *p_opw, *p_vpw, *p_soaw, *p_oqw, *p_l1w, *p_l2w;
    cudaGetSymbolAddress((void**)&p_qkv,  b_qkv);
    cudaGetSymbolAddress((void**)&p_sa,   b_sa);
    cudaGetSymbolAddress((void**)&p_tgt1, b_tgt1);
    cudaGetSymbolAddress((void**)&p_val,  b_val);
    cudaGetSymbolAddress((void**)&p_ca,   b_ca);
    cudaGetSymbolAddress((void**)&p_tgt2, b_tgt2);
    cudaGetSymbolAddress((void**)&p_ffn1, b_ffn1);
    cudaGetSymbolAddress((void**)&p_ipw,  b_ipw);
    cudaGetSymbolAddress((void**)&p_opw,  b_opw);
    cudaGetSymbolAddress((void**)&p_vpw,  b_vpw);
    cudaGetSymbolAddress((void**)&p_soaw, b_soaw);
    cudaGetSymbolAddress((void**)&p_oqw,  b_oqw);
    cudaGetSymbolAddress((void**)&p_l1w,  b_l1w);
    cudaGetSymbolAddress((void**)&p_l2w,  b_l2w);

    const int SMEM1 = 2 * 2 * TILEB;   // 40960
    const int SMEM3 = 2 * 4 * TILEB;   // 81920
    cudaFuncSetAttribute(gemm_mma<1, false, false, 1, true >, cudaFuncAttributeMaxDynamicSharedMemorySize, SMEM1);
    cudaFuncSetAttribute(gemm_mma<1, false, true,  0, false>, cudaFuncAttributeMaxDynamicSharedMemorySize, SMEM1);
    cudaFuncSetAttribute(gemm_mma<1, false, false, 0, false>, cudaFuncAttributeMaxDynamicSharedMemorySize, SMEM1);
    cudaFuncSetAttribute(gemm_mma<3, false, true,  0, false>, cudaFuncAttributeMaxDynamicSharedMemorySize, SMEM3);
    cudaFuncSetAttribute(gemm_mma<3, true,  false, 2, false>, cudaFuncAttributeMaxDynamicSharedMemorySize, SMEM3);

    const int MT  = (BQ + 127) / 128;    // 57
    const int MTV = (BS + 127) / 128;    // 831

#define HL(p, n) (p), (p) + (n)

    // ---- all weight conversions + fused bias, ONE launch ----
    convert_all<<<(254048 + 255) / 256, 256>>>(
        ipw, opw, vpw, sow, aww, oqw, l1w, l2w, sob, awb,
        p_ipw, p_opw, p_vpw, p_soaw, p_oqw, p_l1w, p_l2w, soawb);

    // 1. QKV projection (AFP32, x1, bf16 out)
    gemm_mma<1, false, false, 1, true><<<dim3(6, MT), 256, SMEM1>>>(
        tgt, nullptr, nullptr, p_ipw, nullptr, ipb, nullptr, nullptr, p_qkv, nullptr, BQ, 768, DM);
    // 2. flash self-attention (double-buffered)
    attn_mma<<<dim3(8, NH, B_), 256>>>(p_qkv, p_sa);
    // 3. out-proj + residual (x1), 4. LN1 (hi split)
    gemm_mma<1, false, true, 0, false><<<dim3(2, MT), 256, SMEM1>>>(
        nullptr, p_sa, nullptr, p_opw, nullptr, opb, tgt, buf, nullptr, nullptr, BQ, DM, DM);
    ln_kernel<1><<<BQ / 8, 256>>>(buf, n1g, n1b, tgt1, p_tgt1, nullptr);
    // 5. value projection (AFP32, x1, bf16 out)
    gemm_mma<1, false, false, 1, true><<<dim3(2, MTV), 256, SMEM1>>>(
        mem, nullptr, nullptr, p_vpw, nullptr, vpb, nullptr, nullptr, p_val, nullptr, BS, DM, DM);
    // 6+7. fused sampling offsets + attention-weight logits (N=384)
    gemm_mma<1, false, false, 0, false><<<dim3(3, MT), 256, SMEM1>>>(
        nullptr, p_tgt1, nullptr, p_soaw, nullptr, soawb, nullptr, offaw, nullptr, nullptr, BQ, 384, DM);
    // 8. deformable sampling -> split ca
    deform_kernel<<<(B_ * Q_ * NH * 32 + 255) / 256, 256>>>(offaw, p_val, refp, HL(p_ca, BQ * DM));
    // 9. output proj + residual (x3), 10. LN2 (hi+lo split)
    gemm_mma<3, false, true, 0, false><<<dim3(2, MT), 256, SMEM3>>>(
        nullptr, HL(p_ca, BQ * DM), HL(p_oqw, 256 * 256), oqb, tgt1, buf, nullptr, nullptr, BQ, DM, DM);
    ln_kernel<2><<<BQ / 8, 256>>>(buf, n2g, n2b, tgt2, HL(p_tgt2, BQ * DM));
    // 11. FFN up + relu (x3, split out), 12. FFN down + residual (x3), 13. LN3 -> out
    gemm_mma<3, true, false, 2, false><<<dim3(8, MT), 256, SMEM3>>>(
        nullptr, HL(p_tgt2, BQ * DM), HL(p_l1w, 1024 * 256), l1b, nullptr, nullptr, HL(p_ffn1, BQ * DFFN), BQ, DFFN, DM);
    gemm_mma<3, false, true, 0, false><<<dim3(2, MT), 256, SMEM3>>>(
        nullptr, HL(p_ffn1, BQ * DFFN), HL(p_l2w, 256 * 1024), l2b, tgt2, buf, nullptr, nullptr, BQ, DM, DFFN);
    ln_kernel<0><<<BQ / 8, 256>>>(buf, n3g, n3b, out, nullptr, nullptr);
#undef HL
}

// round 9
// speedup vs baseline: 3.3330x; 1.0331x over previous
#include <cuda_runtime.h>
#include <cuda_bf16.h>
#include <math.h>
#include <stdint.h>

// ---------------- problem constants ----------------
#define B_      8
#define Q_      900
#define BQ      7200          // B*Q
#define DM      256
#define STOT    13294
#define BS      106352        // B*STOT
#define NH      8
#define HD      32
#define DFFN    1024

// ---------------- fp32 scratch ----------------
__device__ float g_buf  [BQ * DM];
__device__ float g_tgt1 [BQ * DM];
__device__ float g_tgt2 [BQ * DM];
__device__ float g_offaw[BQ * 384];
__device__ float g_soawb[384];

// ---------------- bf16 scratch ----------------
__device__ __nv_bfloat16 b_qkv [BQ * 768];
__device__ __nv_bfloat16 b_sa  [BQ * DM];
__device__ __nv_bfloat16 b_tgt1[BQ * DM];
__device__ __nv_bfloat16 b_val [(size_t)BS * DM];
__device__ __nv_bfloat16 b_ca  [BQ * DM];
__device__ __nv_bfloat16 b_tgt2[2][BQ * DM];
__device__ __nv_bfloat16 b_ffn1[2][BQ * DFFN];
__device__ __nv_bfloat16 b_ipw [768 * 256];
__device__ __nv_bfloat16 b_opw [256 * 256];
__device__ __nv_bfloat16 b_vpw [256 * 256];
__device__ __nv_bfloat16 b_soaw[384 * 256];      // sow (256 rows) ++ aww (128 rows)
__device__ __nv_bfloat16 b_oqw [256 * 256];
__device__ __nv_bfloat16 b_l1w [2][1024 * 256];
__device__ __nv_bfloat16 b_l2w [2][256 * 1024];

// ---------------- helpers ----------------
__device__ __forceinline__ uint32_t smem_u32(const void* p) {
    uint32_t a;
    asm("{ .reg .u64 t; cvta.to.shared.u64 t, %1; cvt.u32.u64 %0, t; }" : "=r"(a) : "l"(p));
    return a;
}
__device__ __forceinline__ void ldsm4(uint32_t* r, uint32_t addr) {
    asm volatile("ldmatrix.sync.aligned.m8n8.x4.shared.b16 {%0,%1,%2,%3}, [%4];"
        : "=r"(r[0]), "=r"(r[1]), "=r"(r[2]), "=r"(r[3]) : "r"(addr));
}
__device__ __forceinline__ void ldsm4t(uint32_t* r, uint32_t addr) {
    asm volatile("ldmatrix.sync.aligned.m8n8.x4.trans.shared.b16 {%0,%1,%2,%3}, [%4];"
        : "=r"(r[0]), "=r"(r[1]), "=r"(r[2]), "=r"(r[3]) : "r"(addr));
}
__device__ __forceinline__ void mma16816(float* c, const uint32_t* a, const uint32_t* b) {
    asm volatile("mma.sync.aligned.m16n8k16.row.col.f32.bf16.bf16.f32 "
        "{%0,%1,%2,%3}, {%4,%5,%6,%7}, {%8,%9}, {%0,%1,%2,%3};"
        : "+f"(c[0]), "+f"(c[1]), "+f"(c[2]), "+f"(c[3])
        : "r"(a[0]), "r"(a[1]), "r"(a[2]), "r"(a[3]), "r"(b[0]), "r"(b[1]));
}
__device__ __forceinline__ void cpasync16(uint32_t dst, const void* src, int sz) {
    asm volatile("cp.async.cg.shared.global [%0], [%1], 16, %2;" :: "r"(dst), "l"(src), "r"(sz));
}
__device__ __forceinline__ void split2(float a, float b, __nv_bfloat162& h, __nv_bfloat162& l) {
    h = __floats2bfloat162_rn(a, b);
    float2 hf = __bfloat1622float2(h);
    l = __floats2bfloat162_rn(a - hf.x, b - hf.y);
}
__device__ __forceinline__ uint32_t pack_bf16(float a, float b) {
    __nv_bfloat162 h = __floats2bfloat162_rn(a, b);
    return *reinterpret_cast<uint32_t*>(&h);
}

// ---------------- one-shot weight conversion (all weights + fused bias) ----------------
__global__ __launch_bounds__(256)
void convert_all(const float* __restrict__ ipw, const float* __restrict__ opw,
                 const float* __restrict__ vpw, const float* __restrict__ sow,
                 const float* __restrict__ aww, const float* __restrict__ oqw,
                 const float* __restrict__ l1w, const float* __restrict__ l2w,
                 const float* __restrict__ sob, const float* __restrict__ awb,
                 __nv_bfloat16* __restrict__ d_ipw, __nv_bfloat16* __restrict__ d_opw,
                 __nv_bfloat16* __restrict__ d_vpw, __nv_bfloat16* __restrict__ d_soaw,
                 __nv_bfloat16* __restrict__ d_oqw, __nv_bfloat16* __restrict__ d_l1w,
                 __nv_bfloat16* __restrict__ d_l2w, float* __restrict__ soawb)
{
    const int i = blockIdx.x * 256 + threadIdx.x;
    const float* src;
    __nv_bfloat16* hi;
    __nv_bfloat16* lo = nullptr;
    int base;
    if (i < 49152)       { src = ipw; hi = d_ipw; base = 0; }
    else if (i < 65536)  { src = opw; hi = d_opw; base = 49152; }
    else if (i < 81920)  { src = vpw; hi = d_vpw; base = 65536; }
    else if (i < 98304)  { src = sow; hi = d_soaw; base = 81920; }
    else if (i < 106496) { src = aww; hi = d_soaw + 65536; base = 98304; }
    else if (i < 122880) { src = oqw; hi = d_oqw; base = 106496; }
    else if (i < 188416) { src = l1w; hi = d_l1w; lo = d_l1w + 262144; base = 122880; }
    else if (i < 253952) { src = l2w; hi = d_l2w; lo = d_l2w + 262144; base = 188416; }
    else if (i < 254048) {
        const int j = i - 253952;
        float4 v = (j < 64) ? ((const float4*)sob)[j] : ((const float4*)awb)[j - 64];
        ((float4*)soawb)[j] = v;
        return;
    } else return;

    const int j = i - base;
    float4 v = ((const float4*)src)[j];
    if (lo == nullptr) {
        ((__nv_bfloat162*)hi)[j * 2 + 0] = __floats2bfloat162_rn(v.x, v.y);
        ((__nv_bfloat162*)hi)[j * 2 + 1] = __floats2bfloat162_rn(v.z, v.w);
    } else {
        __nv_bfloat162 h0, l0, h1, l1;
        split2(v.x, v.y, h0, l0);
        split2(v.z, v.w, h1, l1);
        ((__nv_bfloat162*)hi)[j * 2 + 0] = h0;
        ((__nv_bfloat162*)hi)[j * 2 + 1] = h1;
        ((__nv_bfloat162*)lo)[j * 2 + 0] = l0;
        ((__nv_bfloat162*)lo)[j * 2 + 1] = l1;
    }
}

// ---------------- bf16 mma.sync GEMM ----------------
#define TILEB 10240

template<int NPASS, bool RELU, bool RESID, int OUT, bool AFP32>
__global__ __launch_bounds__(256)
void gemm_mma(const float* __restrict__ Af,
              const __nv_bfloat16* __restrict__ Ah, const __nv_bfloat16* __restrict__ Al,
              const __nv_bfloat16* __restrict__ Wh, const __nv_bfloat16* __restrict__ Wl,
              const float* __restrict__ bias, const float* __restrict__ R,
              float* __restrict__ C, __nv_bfloat16* __restrict__ Ch,
              __nv_bfloat16* __restrict__ Cl, int M, int N, int K)
{
    constexpr int NTIL = (NPASS == 3) ? 4 : 2;
    constexpr int STGB = NTIL * TILEB;
    constexpr int WOFF = (NPASS == 3 ? 2 : 1) * TILEB;

    extern __shared__ char smem[];
    const uint32_t sb = smem_u32(smem);
    const int tid = threadIdx.x, lane = tid & 31, wid = tid >> 5;
    const int am = (wid & 3) * 32;
    const int bn = (wid >> 2) * 64;
    const int m0 = blockIdx.y * 128, n0 = blockIdx.x * 128;

    float c[2][8][4] = {};

    float4 aReg[2][2];
    const int pr0 = tid >> 2, pq = tid & 3;

#define LDG_A(ch) do {                                                            \
    const int kb_ = (ch) * 32;                                                    \
    _Pragma("unroll")                                                             \
    for (int u_ = 0; u_ < 2; u_++) {                                              \
        int r_ = pr0 + u_ * 64;                                                   \
        int row_ = m0 + r_; if (row_ >= M) row_ = M - 1;                          \
        const float* p_ = Af + (size_t)row_ * K + kb_ + pq * 8;                   \
        aReg[u_][0] = *(const float4*)p_;                                         \
        aReg[u_][1] = *(const float4*)(p_ + 4);                                   \
    }                                                                             \
} while (0)

#define STS_A(st) do {                                                            \
    _Pragma("unroll")                                                             \
    for (int u_ = 0; u_ < 2; u_++) {                                              \
        int r_ = pr0 + u_ * 64;                                                   \
        uint4 w4_;                                                                \
        w4_.x = pack_bf16(aReg[u_][0].x, aReg[u_][0].y);                          \
        w4_.y = pack_bf16(aReg[u_][0].z, aReg[u_][0].w);                          \
        w4_.z = pack_bf16(aReg[u_][1].x, aReg[u_][1].y);                          \
        w4_.w = pack_bf16(aReg[u_][1].z, aReg[u_][1].w);                          \
        *(uint4*)(smem + (st) * STGB + r_ * 80 + pq * 16) = w4_;                  \
    }                                                                             \
} while (0)

#define ISSUE_W(st, ch) do {                                                      \
    const int kb_ = (ch) * 32;                                                    \
    const uint32_t so_ = sb + (st) * STGB;                                        \
    _Pragma("unroll")                                                             \
    for (int cix = tid; cix < (NPASS == 3 ? 1024 : 512); cix += 256) {            \
        int t_ = cix >> 9, idx_ = cix & 511, r_ = idx_ >> 2, q_ = idx_ & 3;       \
        const __nv_bfloat16* base_ = t_ ? Wl : Wh;                                \
        cpasync16(so_ + WOFF + t_ * TILEB + r_ * 80 + q_ * 16,                    \
                  base_ + (size_t)(n0 + r_) * K + kb_ + q_ * 8, 16);              \
    }                                                                             \
    asm volatile("cp.async.commit_group;" ::: "memory");                          \
} while (0)

#define ISSUE_AB(st, ch) do {                                                     \
    const int kb_ = (ch) * 32;                                                    \
    const uint32_t so_ = sb + (st) * STGB;                                        \
    _Pragma("unroll")                                                             \
    for (int cix = tid; cix < NTIL * 512; cix += 256) {                           \
        int t_ = cix >> 9, idx_ = cix & 511, r_ = idx_ >> 2, q_ = idx_ & 3;       \
        uint32_t d_ = so_ + t_ * TILEB + r_ * 80 + q_ * 16;                       \
        const __nv_bfloat16* base_;                                               \
        bool isA_;                                                                \
        if (NPASS == 1) { isA_ = (t_ == 0); base_ = isA_ ? Ah : Wh; }             \
        else { isA_ = (t_ < 2);                                                   \
               base_ = (t_ == 0 ? Ah : t_ == 1 ? Al : t_ == 2 ? Wh : Wl); }       \
        if (isA_) cpasync16(d_, base_ + (size_t)(m0 + r_) * K + kb_ + q_ * 8,     \
                            (m0 + r_) < M ? 16 : 0);                              \
        else      cpasync16(d_, base_ + (size_t)(n0 + r_) * K + kb_ + q_ * 8, 16);\
    }                                                                             \
    asm volatile("cp.async.commit_group;" ::: "memory");                          \
} while (0)

    const int nCh = K >> 5;
    if (AFP32) {
        LDG_A(0);
        ISSUE_W(0, 0);
    } else {
        ISSUE_AB(0, 0);
    }

    const int lar = lane & 15;
    const int lac = (lane >> 4) * 16;
    const int lbr = (lane & 7) + ((lane >> 4) & 1) * 8;
    const int lbc = ((lane >> 3) & 1) * 16;

    for (int ch = 0; ch < nCh; ch++) {
        if (AFP32) {
            STS_A(ch & 1);
            if (ch + 1 < nCh) {
                LDG_A(ch + 1);
                ISSUE_W((ch + 1) & 1, ch + 1);
                asm volatile("cp.async.wait_group 1;" ::: "memory");
            } else {
                asm volatile("cp.async.wait_group 0;" ::: "memory");
            }
        } else {
            if (ch + 1 < nCh) {
                ISSUE_AB((ch + 1) & 1, ch + 1);
                asm volatile("cp.async.wait_group 1;" ::: "memory");
            } else {
                asm volatile("cp.async.wait_group 0;" ::: "memory");
            }
        }
        __syncthreads();

        const uint32_t so = sb + (ch & 1) * STGB;
        #pragma unroll
        for (int ks = 0; ks < 2; ks++) {
            uint32_t ah[2][4], al[2][4], bb[4][4];
            const uint32_t acol = ks * 32 + lac;
            const uint32_t bcol = ks * 32 + lbc;
            ldsm4(ah[0], so + (am + lar) * 80 + acol);
            ldsm4(ah[1], so + (am + 16 + lar) * 80 + acol);
            if (NPASS == 3) {
                ldsm4(al[0], so + TILEB + (am + lar) * 80 + acol);
                ldsm4(al[1], so + TILEB + (am + 16 + lar) * 80 + acol);
            }
            #pragma unroll
            for (int p = 0; p < 4; p++)
                ldsm4(bb[p], so + WOFF + (bn + p * 16 + lbr) * 80 + bcol);
            #pragma unroll
            for (int fm = 0; fm < 2; fm++)
                #pragma unroll
                for (int p = 0; p < 4; p++) {
                    mma16816(c[fm][2 * p],     ah[fm], bb[p]);
                    mma16816(c[fm][2 * p + 1], ah[fm], bb[p] + 2);
                    if (NPASS == 3) {
                        mma16816(c[fm][2 * p],     al[fm], bb[p]);
                        mma16816(c[fm][2 * p + 1], al[fm], bb[p] + 2);
                    }
                }
            if (NPASS == 3) {
                #pragma unroll
                for (int p = 0; p < 4; p++)
                    ldsm4(bb[p], so + WOFF + TILEB + (bn + p * 16 + lbr) * 80 + bcol);
                #pragma unroll
                for (int fm = 0; fm < 2; fm++)
                    #pragma unroll
                    for (int p = 0; p < 4; p++) {
                        mma16816(c[fm][2 * p],     ah[fm], bb[p]);
                        mma16816(c[fm][2 * p + 1], ah[fm], bb[p] + 2);
                    }
            }
        }
        __syncthreads();
    }
#undef ISSUE_AB
#undef ISSUE_W
#undef STS_A
#undef LDG_A

    // epilogue
    const int r0 = m0 + am + (lane >> 2);
    const int colb = n0 + bn + (lane & 3) * 2;
    #pragma unroll
    for (int fm = 0; fm < 2; fm++) {
        #pragma unroll
        for (int p = 0; p < 8; p++) {
            const int col = colb + p * 8;
            const float2 bv = *(const float2*)(bias + col);
            #pragma unroll
            for (int hh = 0; hh < 2; hh++) {
                const int row = r0 + fm * 16 + hh * 8;
                if (row < M) {
                    float o0 = c[fm][p][hh * 2 + 0] + bv.x;
                    float o1 = c[fm][p][hh * 2 + 1] + bv.y;
                    if (RESID) {
                        float2 rv = *(const float2*)(R + (size_t)row * N + col);
                        o0 += rv.x; o1 += rv.y;
                    }
                    if (RELU) { o0 = fmaxf(o0, 0.f); o1 = fmaxf(o1, 0.f); }
                    if (OUT == 0) {
                        *(float2*)(C + (size_t)row * N + col) = make_float2(o0, o1);
                    } else if (OUT == 1) {
                        *(__nv_bfloat162*)(Ch + (size_t)row * N + col) = __floats2bfloat162_rn(o0, o1);
                    } else {
                        __nv_bfloat162 h, l;
                        split2(o0, o1, h, l);
                        *(__nv_bfloat162*)(Ch + (size_t)row * N + col) = h;
                        *(__nv_bfloat162*)(Cl + (size_t)row * N + col) = l;
                    }
                }
            }
        }
    }
}

// ---------------- flash self-attention, bf16 mma.sync, double-buffered K/V ----------------
#define KVB 5120

__global__ __launch_bounds__(256)
void attn_mma(const __nv_bfloat16* __restrict__ qkv, __nv_bfloat16* __restrict__ sa)
{
    __shared__ __nv_bfloat16 Qs[128 * 40];
    __shared__ __nv_bfloat16 Ks[2][64 * 40];
    __shared__ __nv_bfloat16 Vs[2][64 * 40];
    const int b = blockIdx.z, h = blockIdx.y, q0 = blockIdx.x * 128;
    const int tid = threadIdx.x, lane = tid & 31, wid = tid >> 5;
    const uint32_t sQ = smem_u32(Qs), sK = smem_u32(Ks), sV = smem_u32(Vs);

#define ISSUE_KV(t, bufi) do {                                                    \
    const int kv0_ = (t) * 64;                                                    \
    _Pragma("unroll")                                                             \
    for (int i_ = tid; i_ < 512; i_ += 256) {                                     \
        int te_ = i_ >> 8, idx_ = i_ & 255, r_ = idx_ >> 2, cc_ = idx_ & 3;       \
        const __nv_bfloat16* src_ = qkv + (size_t)(b * Q_ + kv0_ + r_) * 768      \
                                    + 256 + te_ * 256 + h * HD + cc_ * 8;         \
        cpasync16((te_ ? sV : sK) + (bufi) * KVB + r_ * 80 + cc_ * 16, src_,      \
                  (kv0_ + r_) < Q_ ? 16 : 0);                                     \
    }                                                                             \
    asm volatile("cp.async.commit_group;" ::: "memory");                          \
} while (0)

    #pragma unroll
    for (int i = tid; i < 512; i += 256) {
        int r = i >> 2, cc = i & 3;
        const __nv_bfloat16* src = qkv + (size_t)(b * Q_ + q0 + r) * 768 + h * HD + cc * 8;
        cpasync16(sQ + r * 80 + cc * 16, src, (q0 + r) < Q_ ? 16 : 0);
    }
    asm volatile("cp.async.commit_group;" ::: "memory");
    ISSUE_KV(0, 0);
    asm volatile("cp.async.wait_group 1;" ::: "memory");
    __syncthreads();

    const int r8 = (lane & 7) + ((lane >> 3) & 1) * 8;
    const int c16 = (lane >> 4) * 16;

    uint32_t qf[2][4];
    {
        uint32_t qa = sQ + (wid * 16 + r8) * 80 + c16;
        ldsm4(qf[0], qa);
        ldsm4(qf[1], qa + 32);
    }

    float mr[2] = {-1e30f, -1e30f}, lr[2] = {0.f, 0.f};
    float o[4][4] = {};
    const float scale = 0.17677669529663687f;

    for (int t = 0; t < 15; t++) {
        const int kv0 = t * 64;
        if (t + 1 < 15) {
            ISSUE_KV(t + 1, (t + 1) & 1);
            asm volatile("cp.async.wait_group 1;" ::: "memory");
        } else {
            asm volatile("cp.async.wait_group 0;" ::: "memory");
        }
        __syncthreads();

        const uint32_t sKb = sK + (t & 1) * KVB;
        const uint32_t sVb = sV + (t & 1) * KVB;

        float c[8][4] = {};
        #pragma unroll
        for (int ks = 0; ks < 2; ks++) {
            #pragma unroll
            for (int p = 0; p < 4; p++) {
                uint32_t kf[4];
                ldsm4(kf, sKb + (p * 16 + r8) * 80 + c16 + ks * 32);
                uint32_t b0[2] = {kf[0], kf[2]}, b1[2] = {kf[1], kf[3]};
                mma16816(c[2 * p],     qf[ks], b0);
                mma16816(c[2 * p + 1], qf[ks], b1);
            }
        }
        #pragma unroll
        for (int p8 = 0; p8 < 8; p8++)
            #pragma unroll
            for (int j = 0; j < 4; j++) c[p8][j] *= scale;
        if (kv0 + 64 > Q_) {
            #pragma unroll
            for (int p8 = 0; p8 < 8; p8++)
                #pragma unroll
                for (int j = 0; j < 2; j++)
                    if (kv0 + p8 * 8 + 2 * (lane & 3) + j >= Q_) {
                        c[p8][j] = -1e30f;
                        c[p8][2 + j] = -1e30f;
                    }
        }
        #pragma unroll
        for (int rw = 0; rw < 2; rw++) {
            float mx = mr[rw];
            #pragma unroll
            for (int p8 = 0; p8 < 8; p8++)
                mx = fmaxf(mx, fmaxf(c[p8][2 * rw], c[p8][2 * rw + 1]));
            mx = fmaxf(mx, __shfl_xor_sync(0xffffffffu, mx, 1));
            mx = fmaxf(mx, __shfl_xor_sync(0xffffffffu, mx, 2));
            float corr = __expf(mr[rw] - mx);
            float s = 0.f;
            #pragma unroll
            for (int p8 = 0; p8 < 8; p8++) {
                c[p8][2 * rw]     = __expf(c[p8][2 * rw] - mx);
                c[p8][2 * rw + 1] = __expf(c[p8][2 * rw + 1] - mx);
                s += c[p8][2 * rw] + c[p8][2 * rw + 1];
            }
            s += __shfl_xor_sync(0xffffffffu, s, 1);
            s += __shfl_xor_sync(0xffffffffu, s, 2);
            lr[rw] = lr[rw] * corr + s;
            mr[rw] = mx;
            #pragma unroll
            for (int nt = 0; nt < 4; nt++) {
                o[nt][2 * rw] *= corr;
                o[nt][2 * rw + 1] *= corr;
            }
        }
        #pragma unroll
        for (int ts = 0; ts < 4; ts++) {
            uint32_t af[4];
            af[0] = pack_bf16(c[2 * ts][0], c[2 * ts][1]);
            af[1] = pack_bf16(c[2 * ts][2], c[2 * ts][3]);
            af[2] = pack_bf16(c[2 * ts + 1][0], c[2 * ts + 1][1]);
            af[3] = pack_bf16(c[2 * ts + 1][2], c[2 * ts + 1][3]);
            #pragma unroll
            for (int np = 0; np < 2; np++) {
                uint32_t vf[4];
                ldsm4t(vf, sVb + (ts * 16 + r8) * 80 + np * 32 + c16);
                uint32_t b0[2] = {vf[0], vf[1]}, b1[2] = {vf[2], vf[3]};
                mma16816(o[2 * np],     af, b0);
                mma16816(o[2 * np + 1], af, b1);
            }
        }
        __syncthreads();
    }
#undef ISSUE_KV

    const float inv0 = 1.f / lr[0], inv1 = 1.f / lr[1];
    const int gr0 = q0 + wid * 16 + (lane >> 2);
    #pragma unroll
    for (int nt = 0; nt < 4; nt++) {
        const int col = h * HD + nt * 8 + 2 * (lane & 3);
        if (gr0 < Q_)
            *(__nv_bfloat162*)(sa + (size_t)(b * Q_ + gr0) * DM + col)
                = __floats2bfloat162_rn(o[nt][0] * inv0, o[nt][1] * inv0);
        if (gr0 + 8 < Q_)
            *(__nv_bfloat162*)(sa + (size_t)(b * Q_ + gr0 + 8) * DM + col)
                = __floats2bfloat162_rn(o[nt][2] * inv1, o[nt][3] * inv1);
    }
}

// ---------------- LayerNorm: warp per row, 8 rows/CTA ----------------
template<int OSPLIT>
__global__ __launch_bounds__(256)
void ln_kernel(const float* __restrict__ in, const float* __restrict__ g,
               const float* __restrict__ bta, float* __restrict__ out,
               __nv_bfloat16* __restrict__ oh, __nv_bfloat16* __restrict__ ol)
{
    const int warp = threadIdx.x >> 5, lane = threadIdx.x & 31;
    const int row = blockIdx.x * 8 + warp;
    const float4* ip = (const float4*)(in + (size_t)row * DM);
    float4 v0 = ip[lane], v1 = ip[lane + 32];

    float s = ((v0.x + v0.y) + (v0.z + v0.w)) + ((v1.x + v1.y) + (v1.z + v1.w));
    #pragma unroll
    for (int o = 16; o > 0; o >>= 1) s += __shfl_xor_sync(0xffffffffu, s, o);
    const float mu = s * (1.f / 256.f);

    v0.x -= mu; v0.y -= mu; v0.z -= mu; v0.w -= mu;
    v1.x -= mu; v1.y -= mu; v1.z -= mu; v1.w -= mu;
    float vs = ((v0.x * v0.x + v0.y * v0.y) + (v0.z * v0.z + v0.w * v0.w))
             + ((v1.x * v1.x + v1.y * v1.y) + (v1.z * v1.z + v1.w * v1.w));
    #pragma unroll
    for (int o = 16; o > 0; o >>= 1) vs += __shfl_xor_sync(0xffffffffu, vs, o);
    const float rs = rsqrtf(vs * (1.f / 256.f) + 1e-5f);

    const float4 g0 = ((const float4*)g)[lane],  g1 = ((const float4*)g)[lane + 32];
    const float4 b0 = ((const float4*)bta)[lane], b1 = ((const float4*)bta)[lane + 32];
    float4 y0, y1;
    y0.x = v0.x * rs * g0.x + b0.x; y0.y = v0.y * rs * g0.y + b0.y;
    y0.z = v0.z * rs * g0.z + b0.z; y0.w = v0.w * rs * g0.w + b0.w;
    y1.x = v1.x * rs * g1.x + b1.x; y1.y = v1.y * rs * g1.y + b1.y;
    y1.z = v1.z * rs * g1.z + b1.z; y1.w = v1.w * rs * g1.w + b1.w;

    float4* op = (float4*)(out + (size_t)row * DM);
    op[lane] = y0; op[lane + 32] = y1;

    if (OSPLIT >= 1) {
        const size_t i0 = (size_t)row * DM + lane * 4;
        const size_t i1 = i0 + 128;
        if (OSPLIT == 1) {
            *(__nv_bfloat162*)(oh + i0)     = __floats2bfloat162_rn(y0.x, y0.y);
            *(__nv_bfloat162*)(oh + i0 + 2) = __floats2bfloat162_rn(y0.z, y0.w);
            *(__nv_bfloat162*)(oh + i1)     = __floats2bfloat162_rn(y1.x, y1.y);
            *(__nv_bfloat162*)(oh + i1 + 2) = __floats2bfloat162_rn(y1.z, y1.w);
        } else {
            __nv_bfloat162 h, l;
            split2(y0.x, y0.y, h, l);
            *(__nv_bfloat162*)(oh + i0) = h;     *(__nv_bfloat162*)(ol + i0) = l;
            split2(y0.z, y0.w, h, l);
            *(__nv_bfloat162*)(oh + i0 + 2) = h; *(__nv_bfloat162*)(ol + i0 + 2) = l;
            split2(y1.x, y1.y, h, l);
            *(__nv_bfloat162*)(oh + i1) = h;     *(__nv_bfloat162*)(ol + i1) = l;
            split2(y1.z, y1.w, h, l);
            *(__nv_bfloat162*)(oh + i1 + 2) = h; *(__nv_bfloat162*)(ol + i1 + 2) = l;
        }
    }
}

// ---------------- deformable sampling + weight softmax ----------------
__global__ __launch_bounds__(256)
void deform_kernel(const float* __restrict__ offaw,
                   const __nv_bfloat16* __restrict__ value, const float* __restrict__ refp,
                   __nv_bfloat16* __restrict__ outh)
{
    const int gw = (blockIdx.x * blockDim.x + threadIdx.x) >> 5;
    const int lane = threadIdx.x & 31;
    if (gw >= B_ * Q_ * NH) return;
    const int h = gw & 7;
    const int q = (gw >> 3) % Q_;
    const int b = gw / (NH * Q_);
    const size_t bq = (size_t)b * Q_ + q;

    float logit = (lane < 16) ? offaw[bq * 384 + 256 + h * 16 + lane] : -1e30f;
    float mx = logit;
    #pragma unroll
    for (int o = 16; o > 0; o >>= 1) mx = fmaxf(mx, __shfl_xor_sync(0xffffffffu, mx, o));
    float e = (lane < 16) ? __expf(logit - mx) : 0.f;
    float se = e;
    #pragma unroll
    for (int o = 16; o > 0; o >>= 1) se += __shfl_xor_sync(0xffffffffu, se, o);
    const float aw = e / se;

    const int HWl[4][2] = {{100,100},{50,50},{25,25},{13,13}};
    const int ST[4]     = {0, 10000, 12500, 13125};

    float accv = 0.f;
    #pragma unroll
    for (int lvl = 0; lvl < 4; lvl++) {
        const int Hi = HWl[lvl][0], Wi = HWl[lvl][1];
        const float Hl = (float)Hi, Wl = (float)Wi;
        const float refx = refp[(bq * 4 + lvl) * 2 + 0];
        const float refy = refp[(bq * 4 + lvl) * 2 + 1];
        const __nv_bfloat16* vbase = value + ((size_t)b * STOT + ST[lvl]) * DM + h * HD + lane;
        #pragma unroll
        for (int p = 0; p < 4; p++) {
            const int oidx = ((h * 4 + lvl) * 4 + p) * 2;
            const float ox = offaw[bq * 384 + oidx + 0];
            const float oy = offaw[bq * 384 + oidx + 1];
            const float x = (refx + ox / Wl) * Wl - 0.5f;
            const float y = (refy + oy / Hl) * Hl - 0.5f;
            const float x0 = floorf(x), y0 = floorf(y);
            float samp = 0.f;
            #pragma unroll
            for (int cq = 0; cq < 4; cq++) {
                const float xi = x0 + (float)(cq & 1);
                const float yi = y0 + (float)(cq >> 1);
                const float w = (1.f - fabsf(x - xi)) * (1.f - fabsf(y - yi));
                if (xi >= 0.f && xi < Wl && yi >= 0.f && yi < Hl && w != 0.f) {
                    const int ii = (int)yi * Wi + (int)xi;
                    samp += w * __bfloat162float(vbase[(size_t)ii * DM]);
                }
            }
            const float awp = __shfl_sync(0xffffffffu, aw, lvl * 4 + p);
            accv += awp * samp;
        }
    }
    outh[bq * DM + h * HD + lane] = __float2bfloat16(accv);
}

// ---------------- launch ----------------
extern "C" void kernel_launch(void* const* d_in, const int* in_sizes, int n_in,
                              void* d_out, int out_size)
{
    (void)in_sizes; (void)n_in; (void)out_size;
    const float* tgt   = (const float*)d_in[0];
    const float* mem   = (const float*)d_in[1];
    const float* refp  = (const float*)d_in[3];
    const float* ipw = (const float*)d_in[6],  *ipb = (const float*)d_in[7];
    const float* opw = (const float*)d_in[8],  *opb = (const float*)d_in[9];
    const float* n1g = (const float*)d_in[10], *n1b = (const float*)d_in[11];
    const float* n2g = (const float*)d_in[12], *n2b = (const float*)d_in[13];
    const float* n3g = (const float*)d_in[14], *n3b = (const float*)d_in[15];
    const float* sow = (const float*)d_in[16], *sob = (const float*)d_in[17];
    const float* aww = (const float*)d_in[18], *awb = (const float*)d_in[19];
    const float* vpw = (const float*)d_in[20], *vpb = (const float*)d_in[21];
    const float* oqw = (const float*)d_in[22], *oqb = (const float*)d_in[23];
    const float* l1w = (const float*)d_in[24], *l1b = (const float*)d_in[25];
    const float* l2w = (const float*)d_in[26], *l2b = (const float*)d_in[27];
    float* out = (float*)d_out;

    float *buf, *tgt1, *tgt2, *offaw, *soawb;
    cudaGetSymbolAddress((void**)&buf,   g_buf);
    cudaGetSymbolAddress((void**)&tgt1,  g_tgt1);
    cudaGetSymbolAddress((void**)&tgt2,  g_tgt2);
    cudaGetSymbolAddress((void**)&offaw, g_offaw);
    cudaGetSymbolAddress((void**)&soawb, g_soawb);

    __nv_bfloat16 *p_qkv, *p_sa, *p_tgt1, *p_val, *p_ca, *p_tgt2, *p_ffn1;
    __nv_bfloat16 *p_ipw, *p_opw, *p_vpw, *p_soaw, *p_oqw, *p_l1w, *p_l2w;
    cudaGetSymbolAddress((void**)&p_qkv,  b_qkv);
    cudaGetSymbolAddress((void**)&p_sa,   b_sa);
    cudaGetSymbolAddress((void**)&p_tgt1, b_tgt1);
    cudaGetSymbolAddress((void**)&p_val,  b_val);
    cudaGetSymbolAddress((void**)&p_ca,   b_ca);
    cudaGetSymbolAddress((void**)&p_tgt2, b_tgt2);
    cudaGetSymbolAddress((void**)&p_ffn1, b_ffn1);
    cudaGetSymbolAddress((void**)&p_ipw,  b_ipw);
    cudaGetSymbolAddress((void**)&p_opw,  b_opw);
    cudaGetSymbolAddress((void**)&p_vpw,  b_vpw);
    cudaGetSymbolAddress((void**)&p_soaw, b_soaw);
    cudaGetSymbolAddress((void**)&p_oqw,  b_oqw);
    cudaGetSymbolAddress((void**)&p_l1w,  b_l1w);
    cudaGetSymbolAddress((void**)&p_l2w,  b_l2w);

    const int SMEM1 = 2 * 2 * TILEB;   // 40960
    const int SMEM3 = 2 * 4 * TILEB;   // 81920
    cudaFuncSetAttribute(gemm_mma<1, false, false, 1, true >, cudaFuncAttributeMaxDynamicSharedMemorySize, SMEM1);
    cudaFuncSetAttribute(gemm_mma<1, false, true,  0, false>, cudaFuncAttributeMaxDynamicSharedMemorySize, SMEM1);
    cudaFuncSetAttribute(gemm_mma<1, false, false, 0, false>, cudaFuncAttributeMaxDynamicSharedMemorySize, SMEM1);
    cudaFuncSetAttribute(gemm_mma<3, false, true,  0, false>, cudaFuncAttributeMaxDynamicSharedMemorySize, SMEM3);
    cudaFuncSetAttribute(gemm_mma<3, true,  false, 2, false>, cudaFuncAttributeMaxDynamicSharedMemorySize, SMEM3);

    const int MT  = (BQ + 127) / 128;    // 57
    const int MTV = (BS + 127) / 128;    // 831

    // fork/join infrastructure (created fresh each call; kernel_launch only
    // runs a handful of times outside the timed graph replays)
    cudaStream_t s2;
    cudaStreamCreateWithFlags(&s2, cudaStreamNonBlocking);
    cudaEvent_t evA, evB;
    cudaEventCreateWithFlags(&evA, cudaEventDisableTiming);
    cudaEventCreateWithFlags(&evB, cudaEventDisableTiming);

#define HL(p, n) (p), (p) + (n)

    // ---- all weight conversions + fused bias, ONE launch ----
    convert_all<<<(254048 + 255) / 256, 256>>>(
        ipw, opw, vpw, sow, aww, oqw, l1w, l2w, sob, awb,
        p_ipw, p_opw, p_vpw, p_soaw, p_oqw, p_l1w, p_l2w, soawb);

    // fork: value projection on s2, concurrent with the attention path
    cudaEventRecord(evA, 0);
    cudaStreamWaitEvent(s2, evA, 0);
    gemm_mma<1, false, false, 1, true><<<dim3(2, MTV), 256, SMEM1, s2>>>(
        mem, nullptr, nullptr, p_vpw, nullptr, vpb, nullptr, nullptr, p_val, nullptr, BS, DM, DM);
    cudaEventRecord(evB, s2);

    // main path (default stream)
    // 1. QKV projection (AFP32, x1, bf16 out)
    gemm_mma<1, false, false, 1, true><<<dim3(6, MT), 256, SMEM1>>>(
        tgt, nullptr, nullptr, p_ipw, nullptr, ipb, nullptr, nullptr, p_qkv, nullptr, BQ, 768, DM);
    // 2. flash self-attention
    attn_mma<<<dim3(8, NH, B_), 256>>>(p_qkv, p_sa);
    // 3. out-proj + residual (x1), 4. LN1 (hi split)
    gemm_mma<1, false, true, 0, false><<<dim3(2, MT), 256, SMEM1>>>(
        nullptr, p_sa, nullptr, p_opw, nullptr, opb, tgt, buf, nullptr, nullptr, BQ, DM, DM);
    ln_kernel<1><<<BQ / 8, 256>>>(buf, n1g, n1b, tgt1, p_tgt1, nullptr);
    // 5+6. fused sampling offsets + attention-weight logits (N=384)
    gemm_mma<1, false, false, 0, false><<<dim3(3, MT), 256, SMEM1>>>(
        nullptr, p_tgt1, nullptr, p_soaw, nullptr, soawb, nullptr, offaw, nullptr, nullptr, BQ, 384, DM);

    // join: need value tensor before sampling
    cudaStreamWaitEvent((cudaStream_t)0, evB, 0);
    // 7. deformable sampling -> bf16 ca
    deform_kernel<<<(B_ * Q_ * NH * 32 + 255) / 256, 256>>>(offaw, p_val, refp, p_ca);
    // 8. output proj + residual (x1), 9. LN2 (hi+lo split for FFN x3)
    gemm_mma<1, false, true, 0, false><<<dim3(2, MT), 256, SMEM1>>>(
        nullptr, p_ca, nullptr, p_oqw, nullptr, oqb, tgt1, buf, nullptr, nullptr, BQ, DM, DM);
    ln_kernel<2><<<BQ / 8, 256>>>(buf, n2g, n2b, tgt2, HL(p_tgt2, BQ * DM));
    // 10. FFN up + relu (x3, split out), 11. FFN down + residual (x3), 12. LN3 -> out
    gemm_mma<3, true, false, 2, false><<<dim3(8, MT), 256, SMEM3>>>(
        nullptr, HL(p_tgt2, BQ * DM), HL(p_l1w, 1024 * 256), l1b, nullptr, nullptr, HL(p_ffn1, BQ * DFFN), BQ, DFFN, DM);
    gemm_mma<3, false, true, 0, false><<<dim3(2, MT), 256, SMEM3>>>(
        nullptr, HL(p_ffn1, BQ * DFFN), HL(p_l2w, 256 * 1024), l2b, tgt2, buf, nullptr, nullptr, BQ, DM, DFFN);
    ln_kernel<0><<<BQ / 8, 256>>>(buf, n3g, n3b, out, nullptr, nullptr);
#undef HL
}

// round 10
// speedup vs baseline: 3.5856x; 1.0758x over previous
#include <cuda_runtime.h>
#include <cuda_bf16.h>
#include <math.h>
#include <stdint.h>

// ---------------- problem constants ----------------
#define B_      8
#define Q_      900
#define BQ      7200          // B*Q
#define DM      256
#define STOT    13294
#define BS      106352        // B*STOT
#define NH      8
#define HD      32
#define DFFN    1024

// ---------------- fp32 scratch ----------------
__device__ float g_buf  [BQ * DM];
__device__ float g_tgt1 [BQ * DM];
__device__ float g_tgt2 [BQ * DM];
__device__ float g_offaw[BQ * 384];
__device__ float g_soawb[384];

// ---------------- bf16 scratch ----------------
__device__ __nv_bfloat16 b_qkv [BQ * 768];
__device__ __nv_bfloat16 b_sa  [BQ * DM];
__device__ __nv_bfloat16 b_tgt1[BQ * DM];
__device__ __nv_bfloat16 b_val [(size_t)BS * DM];
__device__ __nv_bfloat16 b_ca  [BQ * DM];
__device__ __nv_bfloat16 b_tgt2[BQ * DM];
__device__ __nv_bfloat16 b_ffn1[BQ * DFFN];
__device__ __nv_bfloat16 b_ipw [768 * 256];
__device__ __nv_bfloat16 b_opw [256 * 256];
__device__ __nv_bfloat16 b_vpw [256 * 256];
__device__ __nv_bfloat16 b_soaw[384 * 256];      // sow (256 rows) ++ aww (128 rows)
__device__ __nv_bfloat16 b_oqw [256 * 256];
__device__ __nv_bfloat16 b_l1w [2][1024 * 256];
__device__ __nv_bfloat16 b_l2w [2][256 * 1024];

// ---------------- helpers ----------------
__device__ __forceinline__ uint32_t smem_u32(const void* p) {
    uint32_t a;
    asm("{ .reg .u64 t; cvta.to.shared.u64 t, %1; cvt.u32.u64 %0, t; }" : "=r"(a) : "l"(p));
    return a;
}
__device__ __forceinline__ float ex2f(float x) {
    float y;
    asm("ex2.approx.f32 %0, %1;" : "=f"(y) : "f"(x));
    return y;
}
__device__ __forceinline__ void ldsm4(uint32_t* r, uint32_t addr) {
    asm volatile("ldmatrix.sync.aligned.m8n8.x4.shared.b16 {%0,%1,%2,%3}, [%4];"
        : "=r"(r[0]), "=r"(r[1]), "=r"(r[2]), "=r"(r[3]) : "r"(addr));
}
__device__ __forceinline__ void ldsm4t(uint32_t* r, uint32_t addr) {
    asm volatile("ldmatrix.sync.aligned.m8n8.x4.trans.shared.b16 {%0,%1,%2,%3}, [%4];"
        : "=r"(r[0]), "=r"(r[1]), "=r"(r[2]), "=r"(r[3]) : "r"(addr));
}
__device__ __forceinline__ void mma16816(float* c, const uint32_t* a, const uint32_t* b) {
    asm volatile("mma.sync.aligned.m16n8k16.row.col.f32.bf16.bf16.f32 "
        "{%0,%1,%2,%3}, {%4,%5,%6,%7}, {%8,%9}, {%0,%1,%2,%3};"
        : "+f"(c[0]), "+f"(c[1]), "+f"(c[2]), "+f"(c[3])
        : "r"(a[0]), "r"(a[1]), "r"(a[2]), "r"(a[3]), "r"(b[0]), "r"(b[1]));
}
__device__ __forceinline__ void cpasync16(uint32_t dst, const void* src, int sz) {
    asm volatile("cp.async.cg.shared.global [%0], [%1], 16, %2;" :: "r"(dst), "l"(src), "r"(sz));
}
__device__ __forceinline__ void split2(float a, float b, __nv_bfloat162& h, __nv_bfloat162& l) {
    h = __floats2bfloat162_rn(a, b);
    float2 hf = __bfloat1622float2(h);
    l = __floats2bfloat162_rn(a - hf.x, b - hf.y);
}
__device__ __forceinline__ uint32_t pack_bf16(float a, float b) {
    __nv_bfloat162 h = __floats2bfloat162_rn(a, b);
    return *reinterpret_cast<uint32_t*>(&h);
}

// ---------------- one-shot weight conversion (all weights + fused bias) ----------------
__global__ __launch_bounds__(256)
void convert_all(const float* __restrict__ ipw, const float* __restrict__ opw,
                 const float* __restrict__ vpw, const float* __restrict__ sow,
                 const float* __restrict__ aww, const float* __restrict__ oqw,
                 const float* __restrict__ l1w, const float* __restrict__ l2w,
                 const float* __restrict__ sob, const float* __restrict__ awb,
                 __nv_bfloat16* __restrict__ d_ipw, __nv_bfloat16* __restrict__ d_opw,
                 __nv_bfloat16* __restrict__ d_vpw, __nv_bfloat16* __restrict__ d_soaw,
                 __nv_bfloat16* __restrict__ d_oqw, __nv_bfloat16* __restrict__ d_l1w,
                 __nv_bfloat16* __restrict__ d_l2w, float* __restrict__ soawb)
{
    const int i = blockIdx.x * 256 + threadIdx.x;
    const float* src;
    __nv_bfloat16* hi;
    __nv_bfloat16* lo = nullptr;
    int base;
    if (i < 49152)       { src = ipw; hi = d_ipw; base = 0; }
    else if (i < 65536)  { src = opw; hi = d_opw; base = 49152; }
    else if (i < 81920)  { src = vpw; hi = d_vpw; base = 65536; }
    else if (i < 98304)  { src = sow; hi = d_soaw; base = 81920; }
    else if (i < 106496) { src = aww; hi = d_soaw + 65536; base = 98304; }
    else if (i < 122880) { src = oqw; hi = d_oqw; base = 106496; }
    else if (i < 188416) { src = l1w; hi = d_l1w; lo = d_l1w + 262144; base = 122880; }
    else if (i < 253952) { src = l2w; hi = d_l2w; lo = d_l2w + 262144; base = 188416; }
    else if (i < 254048) {
        const int j = i - 253952;
        float4 v = (j < 64) ? ((const float4*)sob)[j] : ((const float4*)awb)[j - 64];
        ((float4*)soawb)[j] = v;
        return;
    } else return;

    const int j = i - base;
    float4 v = ((const float4*)src)[j];
    if (lo == nullptr) {
        ((__nv_bfloat162*)hi)[j * 2 + 0] = __floats2bfloat162_rn(v.x, v.y);
        ((__nv_bfloat162*)hi)[j * 2 + 1] = __floats2bfloat162_rn(v.z, v.w);
    } else {
        __nv_bfloat162 h0, l0, h1, l1;
        split2(v.x, v.y, h0, l0);
        split2(v.z, v.w, h1, l1);
        ((__nv_bfloat162*)hi)[j * 2 + 0] = h0;
        ((__nv_bfloat162*)hi)[j * 2 + 1] = h1;
        ((__nv_bfloat162*)lo)[j * 2 + 0] = l0;
        ((__nv_bfloat162*)lo)[j * 2 + 1] = l1;
    }
}

// ---------------- bf16 mma.sync GEMM ----------------
// NPASS: 1 = Ah*Wh; 2 = Ah*Wh + Ah*Wl; 3 = Ah*Wh + Al*Wh + Ah*Wl.
// OUT: 0 = fp32 C, 1 = bf16 Ch, 2 = bf16 Ch+Cl.
// AFP32: A read fp32 with register-pipelined inline conversion.
// QS: scale output columns < 256 by softmax_scale*log2(e) (QKV Q-fold).
#define TILEB 10240

template<int NPASS, bool RELU, bool RESID, int OUT, bool AFP32, bool QS>
__global__ __launch_bounds__(256)
void gemm_mma(const float* __restrict__ Af,
              const __nv_bfloat16* __restrict__ Ah, const __nv_bfloat16* __restrict__ Al,
              const __nv_bfloat16* __restrict__ Wh, const __nv_bfloat16* __restrict__ Wl,
              const float* __restrict__ bias, const float* __restrict__ R,
              float* __restrict__ C, __nv_bfloat16* __restrict__ Ch,
              __nv_bfloat16* __restrict__ Cl, int M, int N, int K)
{
    constexpr int NTIL = (NPASS == 3) ? 4 : (NPASS == 2 ? 3 : 2);
    constexpr int STGB = NTIL * TILEB;
    constexpr int WOFF = (NPASS == 3 ? 2 : 1) * TILEB;

    extern __shared__ char smem[];
    const uint32_t sb = smem_u32(smem);
    const int tid = threadIdx.x, lane = tid & 31, wid = tid >> 5;
    const int am = (wid & 3) * 32;
    const int bn = (wid >> 2) * 64;
    const int m0 = blockIdx.y * 128, n0 = blockIdx.x * 128;

    float c[2][8][4] = {};

    float4 aReg[2][2];
    const int pr0 = tid >> 2, pq = tid & 3;

#define LDG_A(ch) do {                                                            \
    const int kb_ = (ch) * 32;                                                    \
    _Pragma("unroll")                                                             \
    for (int u_ = 0; u_ < 2; u_++) {                                              \
        int r_ = pr0 + u_ * 64;                                                   \
        int row_ = m0 + r_; if (row_ >= M) row_ = M - 1;                          \
        const float* p_ = Af + (size_t)row_ * K + kb_ + pq * 8;                   \
        aReg[u_][0] = *(const float4*)p_;                                         \
        aReg[u_][1] = *(const float4*)(p_ + 4);                                   \
    }                                                                             \
} while (0)

#define STS_A(st) do {                                                            \
    _Pragma("unroll")                                                             \
    for (int u_ = 0; u_ < 2; u_++) {                                              \
        int r_ = pr0 + u_ * 64;                                                   \
        uint4 w4_;                                                                \
        w4_.x = pack_bf16(aReg[u_][0].x, aReg[u_][0].y);                          \
        w4_.y = pack_bf16(aReg[u_][0].z, aReg[u_][0].w);                          \
        w4_.z = pack_bf16(aReg[u_][1].x, aReg[u_][1].y);                          \
        w4_.w = pack_bf16(aReg[u_][1].z, aReg[u_][1].w);                          \
        *(uint4*)(smem + (st) * STGB + r_ * 80 + pq * 16) = w4_;                  \
    }                                                                             \
} while (0)

#define ISSUE_W(st, ch) do {                                                      \
    const int kb_ = (ch) * 32;                                                    \
    const uint32_t so_ = sb + (st) * STGB;                                        \
    _Pragma("unroll")                                                             \
    for (int cix = tid; cix < (NPASS >= 2 ? 1024 : 512); cix += 256) {            \
        int t_ = cix >> 9, idx_ = cix & 511, r_ = idx_ >> 2, q_ = idx_ & 3;       \
        const __nv_bfloat16* base_ = t_ ? Wl : Wh;                                \
        cpasync16(so_ + WOFF + t_ * TILEB + r_ * 80 + q_ * 16,                    \
                  base_ + (size_t)(n0 + r_) * K + kb_ + q_ * 8, 16);              \
    }                                                                             \
    asm volatile("cp.async.commit_group;" ::: "memory");                          \
} while (0)

#define ISSUE_AB(st, ch) do {                                                     \
    const int kb_ = (ch) * 32;                                                    \
    const uint32_t so_ = sb + (st) * STGB;                                        \
    _Pragma("unroll")                                                             \
    for (int cix = tid; cix < NTIL * 512; cix += 256) {                           \
        int t_ = cix >> 9, idx_ = cix & 511, r_ = idx_ >> 2, q_ = idx_ & 3;       \
        uint32_t d_ = so_ + t_ * TILEB + r_ * 80 + q_ * 16;                       \
        const __nv_bfloat16* base_;                                               \
        bool isA_;                                                                \
        if (NPASS == 1) { isA_ = (t_ == 0); base_ = isA_ ? Ah : Wh; }             \
        else if (NPASS == 2) { isA_ = (t_ == 0);                                  \
               base_ = (t_ == 0 ? Ah : t_ == 1 ? Wh : Wl); }                      \
        else { isA_ = (t_ < 2);                                                   \
               base_ = (t_ == 0 ? Ah : t_ == 1 ? Al : t_ == 2 ? Wh : Wl); }       \
        if (isA_) cpasync16(d_, base_ + (size_t)(m0 + r_) * K + kb_ + q_ * 8,     \
                            (m0 + r_) < M ? 16 : 0);                              \
        else      cpasync16(d_, base_ + (size_t)(n0 + r_) * K + kb_ + q_ * 8, 16);\
    }                                                                             \
    asm volatile("cp.async.commit_group;" ::: "memory");                          \
} while (0)

    const int nCh = K >> 5;
    if (AFP32) {
        LDG_A(0);
        ISSUE_W(0, 0);
    } else {
        ISSUE_AB(0, 0);
    }

    const int lar = lane & 15;
    const int lac = (lane >> 4) * 16;
    const int lbr = (lane & 7) + ((lane >> 4) & 1) * 8;
    const int lbc = ((lane >> 3) & 1) * 16;

    for (int ch = 0; ch < nCh; ch++) {
        if (AFP32) {
            STS_A(ch & 1);
            if (ch + 1 < nCh) {
                LDG_A(ch + 1);
                ISSUE_W((ch + 1) & 1, ch + 1);
                asm volatile("cp.async.wait_group 1;" ::: "memory");
            } else {
                asm volatile("cp.async.wait_group 0;" ::: "memory");
            }
        } else {
            if (ch + 1 < nCh) {
                ISSUE_AB((ch + 1) & 1, ch + 1);
                asm volatile("cp.async.wait_group 1;" ::: "memory");
            } else {
                asm volatile("cp.async.wait_group 0;" ::: "memory");
            }
        }
        __syncthreads();

        const uint32_t so = sb + (ch & 1) * STGB;
        #pragma unroll
        for (int ks = 0; ks < 2; ks++) {
            uint32_t ah[2][4], al[2][4], bb[4][4];
            const uint32_t acol = ks * 32 + lac;
            const uint32_t bcol = ks * 32 + lbc;
            ldsm4(ah[0], so + (am + lar) * 80 + acol);
            ldsm4(ah[1], so + (am + 16 + lar) * 80 + acol);
            if (NPASS == 3) {
                ldsm4(al[0], so + TILEB + (am + lar) * 80 + acol);
                ldsm4(al[1], so + TILEB + (am + 16 + lar) * 80 + acol);
            }
            #pragma unroll
            for (int p = 0; p < 4; p++)
                ldsm4(bb[p], so + WOFF + (bn + p * 16 + lbr) * 80 + bcol);
            #pragma unroll
            for (int fm = 0; fm < 2; fm++)
                #pragma unroll
                for (int p = 0; p < 4; p++) {
                    mma16816(c[fm][2 * p],     ah[fm], bb[p]);
                    mma16816(c[fm][2 * p + 1], ah[fm], bb[p] + 2);
                    if (NPASS == 3) {
                        mma16816(c[fm][2 * p],     al[fm], bb[p]);
                        mma16816(c[fm][2 * p + 1], al[fm], bb[p] + 2);
                    }
                }
            if (NPASS >= 2) {
                #pragma unroll
                for (int p = 0; p < 4; p++)
                    ldsm4(bb[p], so + WOFF + TILEB + (bn + p * 16 + lbr) * 80 + bcol);
                #pragma unroll
                for (int fm = 0; fm < 2; fm++)
                    #pragma unroll
                    for (int p = 0; p < 4; p++) {
                        mma16816(c[fm][2 * p],     ah[fm], bb[p]);
                        mma16816(c[fm][2 * p + 1], ah[fm], bb[p] + 2);
                    }
            }
        }
        __syncthreads();
    }
#undef ISSUE_AB
#undef ISSUE_W
#undef STS_A
#undef LDG_A

    // epilogue
    const int r0 = m0 + am + (lane >> 2);
    const int colb = n0 + bn + (lane & 3) * 2;
    #pragma unroll
    for (int fm = 0; fm < 2; fm++) {
        #pragma unroll
        for (int p = 0; p < 8; p++) {
            const int col = colb + p * 8;
            const float2 bv = *(const float2*)(bias + col);
            #pragma unroll
            for (int hh = 0; hh < 2; hh++) {
                const int row = r0 + fm * 16 + hh * 8;
                if (row < M) {
                    float o0 = c[fm][p][hh * 2 + 0] + bv.x;
                    float o1 = c[fm][p][hh * 2 + 1] + bv.y;
                    if (QS && col < 256) {
                        const float qsf = 0.17677669529663687f * 1.4426950408889634f;
                        o0 *= qsf; o1 *= qsf;
                    }
                    if (RESID) {
                        float2 rv = *(const float2*)(R + (size_t)row * N + col);
                        o0 += rv.x; o1 += rv.y;
                    }
                    if (RELU) { o0 = fmaxf(o0, 0.f); o1 = fmaxf(o1, 0.f); }
                    if (OUT == 0) {
                        *(float2*)(C + (size_t)row * N + col) = make_float2(o0, o1);
                    } else if (OUT == 1) {
                        *(__nv_bfloat162*)(Ch + (size_t)row * N + col) = __floats2bfloat162_rn(o0, o1);
                    } else {
                        __nv_bfloat162 h, l;
                        split2(o0, o1, h, l);
                        *(__nv_bfloat162*)(Ch + (size_t)row * N + col) = h;
                        *(__nv_bfloat162*)(Cl + (size_t)row * N + col) = l;
                    }
                }
            }
        }
    }
}

// ---------------- flash self-attention, bf16 mma.sync, log2-domain softmax ----------------
// Q pre-scaled by softmax_scale*log2(e) in QKV epilogue.
#define KVB 5120

__global__ __launch_bounds__(256)
void attn_mma(const __nv_bfloat16* __restrict__ qkv, __nv_bfloat16* __restrict__ sa)
{
    __shared__ __nv_bfloat16 Qs[128 * 40];
    __shared__ __nv_bfloat16 Ks[2][64 * 40];
    __shared__ __nv_bfloat16 Vs[2][64 * 40];
    const int b = blockIdx.z, h = blockIdx.y, q0 = blockIdx.x * 128;
    const int tid = threadIdx.x, lane = tid & 31, wid = tid >> 5;
    const uint32_t sQ = smem_u32(Qs), sK = smem_u32(Ks), sV = smem_u32(Vs);

#define ISSUE_KV(t, bufi) do {                                                    \
    const int kv0_ = (t) * 64;                                                    \
    _Pragma("unroll")                                                             \
    for (int i_ = tid; i_ < 512; i_ += 256) {                                     \
        int te_ = i_ >> 8, idx_ = i_ & 255, r_ = idx_ >> 2, cc_ = idx_ & 3;       \
        const __nv_bfloat16* src_ = qkv + (size_t)(b * Q_ + kv0_ + r_) * 768      \
                                    + 256 + te_ * 256 + h * HD + cc_ * 8;         \
        cpasync16((te_ ? sV : sK) + (bufi) * KVB + r_ * 80 + cc_ * 16, src_,      \
                  (kv0_ + r_) < Q_ ? 16 : 0);                                     \
    }                                                                             \
    asm volatile("cp.async.commit_group;" ::: "memory");                          \
} while (0)

    #pragma unroll
    for (int i = tid; i < 512; i += 256) {
        int r = i >> 2, cc = i & 3;
        const __nv_bfloat16* src = qkv + (size_t)(b * Q_ + q0 + r) * 768 + h * HD + cc * 8;
        cpasync16(sQ + r * 80 + cc * 16, src, (q0 + r) < Q_ ? 16 : 0);
    }
    asm volatile("cp.async.commit_group;" ::: "memory");
    ISSUE_KV(0, 0);
    asm volatile("cp.async.wait_group 1;" ::: "memory");
    __syncthreads();

    const int r8 = (lane & 7) + ((lane >> 3) & 1) * 8;
    const int c16 = (lane >> 4) * 16;

    uint32_t qf[2][4];
    {
        uint32_t qa = sQ + (wid * 16 + r8) * 80 + c16;
        ldsm4(qf[0], qa);
        ldsm4(qf[1], qa + 32);
    }

    float mr[2] = {-1e30f, -1e30f}, lr[2] = {0.f, 0.f};
    float o[4][4] = {};

    for (int t = 0; t < 15; t++) {
        const int kv0 = t * 64;
        if (t + 1 < 15) {
            ISSUE_KV(t + 1, (t + 1) & 1);
            asm volatile("cp.async.wait_group 1;" ::: "memory");
        } else {
            asm volatile("cp.async.wait_group 0;" ::: "memory");
        }
        __syncthreads();

        const uint32_t sKb = sK + (t & 1) * KVB;
        const uint32_t sVb = sV + (t & 1) * KVB;

        float c[8][4] = {};
        #pragma unroll
        for (int ks = 0; ks < 2; ks++) {
            #pragma unroll
            for (int p = 0; p < 4; p++) {
                uint32_t kf[4];
                ldsm4(kf, sKb + (p * 16 + r8) * 80 + c16 + ks * 32);
                uint32_t b0[2] = {kf[0], kf[2]}, b1[2] = {kf[1], kf[3]};
                mma16816(c[2 * p],     qf[ks], b0);
                mma16816(c[2 * p + 1], qf[ks], b1);
            }
        }
        if (kv0 + 64 > Q_) {
            #pragma unroll
            for (int p8 = 0; p8 < 8; p8++)
                #pragma unroll
                for (int j = 0; j < 2; j++)
                    if (kv0 + p8 * 8 + 2 * (lane & 3) + j >= Q_) {
                        c[p8][j] = -1e30f;
                        c[p8][2 + j] = -1e30f;
                    }
        }
        // online softmax in log2 domain (scores already scaled by scale*log2e)
        #pragma unroll
        for (int rw = 0; rw < 2; rw++) {
            float mx = mr[rw];
            #pragma unroll
            for (int p8 = 0; p8 < 8; p8++)
                mx = fmaxf(mx, fmaxf(c[p8][2 * rw], c[p8][2 * rw + 1]));
            mx = fmaxf(mx, __shfl_xor_sync(0xffffffffu, mx, 1));
            mx = fmaxf(mx, __shfl_xor_sync(0xffffffffu, mx, 2));
            float corr = ex2f(mr[rw] - mx);
            float s = 0.f;
            #pragma unroll
            for (int p8 = 0; p8 < 8; p8++) {
                c[p8][2 * rw]     = ex2f(c[p8][2 * rw] - mx);
                c[p8][2 * rw + 1] = ex2f(c[p8][2 * rw + 1] - mx);
                s += c[p8][2 * rw] + c[p8][2 * rw + 1];
            }
            s += __shfl_xor_sync(0xffffffffu, s, 1);
            s += __shfl_xor_sync(0xffffffffu, s, 2);
            lr[rw] = lr[rw] * corr + s;
            mr[rw] = mx;
            #pragma unroll
            for (int nt = 0; nt < 4; nt++) {
                o[nt][2 * rw] *= corr;
                o[nt][2 * rw + 1] *= corr;
            }
        }
        #pragma unroll
        for (int ts = 0; ts < 4; ts++) {
            uint32_t af[4];
            af[0] = pack_bf16(c[2 * ts][0], c[2 * ts][1]);
            af[1] = pack_bf16(c[2 * ts][2], c[2 * ts][3]);
            af[2] = pack_bf16(c[2 * ts + 1][0], c[2 * ts + 1][1]);
            af[3] = pack_bf16(c[2 * ts + 1][2], c[2 * ts + 1][3]);
            #pragma unroll
            for (int np = 0; np < 2; np++) {
                uint32_t vf[4];
                ldsm4t(vf, sVb + (ts * 16 + r8) * 80 + np * 32 + c16);
                uint32_t b0[2] = {vf[0], vf[1]}, b1[2] = {vf[2], vf[3]};
                mma16816(o[2 * np],     af, b0);
                mma16816(o[2 * np + 1], af, b1);
            }
        }
        __syncthreads();
    }
#undef ISSUE_KV

    const float inv0 = 1.f / lr[0], inv1 = 1.f / lr[1];
    const int gr0 = q0 + wid * 16 + (lane >> 2);
    #pragma unroll
    for (int nt = 0; nt < 4; nt++) {
        const int col = h * HD + nt * 8 + 2 * (lane & 3);
        if (gr0 < Q_)
            *(__nv_bfloat162*)(sa + (size_t)(b * Q_ + gr0) * DM + col)
                = __floats2bfloat162_rn(o[nt][0] * inv0, o[nt][1] * inv0);
        if (gr0 + 8 < Q_)
            *(__nv_bfloat162*)(sa + (size_t)(b * Q_ + gr0 + 8) * DM + col)
                = __floats2bfloat162_rn(o[nt][2] * inv1, o[nt][3] * inv1);
    }
}

// ---------------- LayerNorm: warp per row, 8 rows/CTA ----------------
template<int OSPLIT>
__global__ __launch_bounds__(256)
void ln_kernel(const float* __restrict__ in, const float* __restrict__ g,
               const float* __restrict__ bta, float* __restrict__ out,
               __nv_bfloat16* __restrict__ oh, __nv_bfloat16* __restrict__ ol)
{
    const int warp = threadIdx.x >> 5, lane = threadIdx.x & 31;
    const int row = blockIdx.x * 8 + warp;
    const float4* ip = (const float4*)(in + (size_t)row * DM);
    float4 v0 = ip[lane], v1 = ip[lane + 32];

    float s = ((v0.x + v0.y) + (v0.z + v0.w)) + ((v1.x + v1.y) + (v1.z + v1.w));
    #pragma unroll
    for (int o = 16; o > 0; o >>= 1) s += __shfl_xor_sync(0xffffffffu, s, o);
    const float mu = s * (1.f / 256.f);

    v0.x -= mu; v0.y -= mu; v0.z -= mu; v0.w -= mu;
    v1.x -= mu; v1.y -= mu; v1.z -= mu; v1.w -= mu;
    float vs = ((v0.x * v0.x + v0.y * v0.y) + (v0.z * v0.z + v0.w * v0.w))
             + ((v1.x * v1.x + v1.y * v1.y) + (v1.z * v1.z + v1.w * v1.w));
    #pragma unroll
    for (int o = 16; o > 0; o >>= 1) vs += __shfl_xor_sync(0xffffffffu, vs, o);
    const float rs = rsqrtf(vs * (1.f / 256.f) + 1e-5f);

    const float4 g0 = ((const float4*)g)[lane],  g1 = ((const float4*)g)[lane + 32];
    const float4 b0 = ((const float4*)bta)[lane], b1 = ((const float4*)bta)[lane + 32];
    float4 y0, y1;
    y0.x = v0.x * rs * g0.x + b0.x; y0.y = v0.y * rs * g0.y + b0.y;
    y0.z = v0.z * rs * g0.z + b0.z; y0.w = v0.w * rs * g0.w + b0.w;
    y1.x = v1.x * rs * g1.x + b1.x; y1.y = v1.y * rs * g1.y + b1.y;
    y1.z = v1.z * rs * g1.z + b1.z; y1.w = v1.w * rs * g1.w + b1.w;

    float4* op = (float4*)(out + (size_t)row * DM);
    op[lane] = y0; op[lane + 32] = y1;

    if (OSPLIT >= 1) {
        const size_t i0 = (size_t)row * DM + lane * 4;
        const size_t i1 = i0 + 128;
        if (OSPLIT == 1) {
            *(__nv_bfloat162*)(oh + i0)     = __floats2bfloat162_rn(y0.x, y0.y);
            *(__nv_bfloat162*)(oh + i0 + 2) = __floats2bfloat162_rn(y0.z, y0.w);
            *(__nv_bfloat162*)(oh + i1)     = __floats2bfloat162_rn(y1.x, y1.y);
            *(__nv_bfloat162*)(oh + i1 + 2) = __floats2bfloat162_rn(y1.z, y1.w);
        } else {
            __nv_bfloat162 h, l;
            split2(y0.x, y0.y, h, l);
            *(__nv_bfloat162*)(oh + i0) = h;     *(__nv_bfloat162*)(ol + i0) = l;
            split2(y0.z, y0.w, h, l);
            *(__nv_bfloat162*)(oh + i0 + 2) = h; *(__nv_bfloat162*)(ol + i0 + 2) = l;
            split2(y1.x, y1.y, h, l);
            *(__nv_bfloat162*)(oh + i1) = h;     *(__nv_bfloat162*)(ol + i1) = l;
            split2(y1.z, y1.w, h, l);
            *(__nv_bfloat162*)(oh + i1 + 2) = h; *(__nv_bfloat162*)(ol + i1 + 2) = l;
        }
    }
}

// ---------------- deformable sampling + weight softmax ----------------
__global__ __launch_bounds__(256)
void deform_kernel(const float* __restrict__ offaw,
                   const __nv_bfloat16* __restrict__ value, const float* __restrict__ refp,
                   __nv_bfloat16* __restrict__ outh)
{
    const int gw = (blockIdx.x * blockDim.x + threadIdx.x) >> 5;
    const int lane = threadIdx.x & 31;
    if (gw >= B_ * Q_ * NH) return;
    const int h = gw & 7;
    const int q = (gw >> 3) % Q_;
    const int b = gw / (NH * Q_);
    const size_t bq = (size_t)b * Q_ + q;

    float logit = (lane < 16) ? offaw[bq * 384 + 256 + h * 16 + lane] : -1e30f;
    float mx = logit;
    #pragma unroll
    for (int o = 16; o > 0; o >>= 1) mx = fmaxf(mx, __shfl_xor_sync(0xffffffffu, mx, o));
    float e = (lane < 16) ? __expf(logit - mx) : 0.f;
    float se = e;
    #pragma unroll
    for (int o = 16; o > 0; o >>= 1) se += __shfl_xor_sync(0xffffffffu, se, o);
    const float aw = e / se;

    const int HWl[4][2] = {{100,100},{50,50},{25,25},{13,13}};
    const int ST[4]     = {0, 10000, 12500, 13125};

    float accv = 0.f;
    #pragma unroll
    for (int lvl = 0; lvl < 4; lvl++) {
        const int Hi = HWl[lvl][0], Wi = HWl[lvl][1];
        const float Hl = (float)Hi, Wl = (float)Wi;
        const float refx = refp[(bq * 4 + lvl) * 2 + 0];
        const float refy = refp[(bq * 4 + lvl) * 2 + 1];
        const __nv_bfloat16* vbase = value + ((size_t)b * STOT + ST[lvl]) * DM + h * HD + lane;
        #pragma unroll
        for (int p = 0; p < 4; p++) {
            const int oidx = ((h * 4 + lvl) * 4 + p) * 2;
            const float ox = offaw[bq * 384 + oidx + 0];
            const float oy = offaw[bq * 384 + oidx + 1];
            const float x = (refx + ox / Wl) * Wl - 0.5f;
            const float y = (refy + oy / Hl) * Hl - 0.5f;
            const float x0 = floorf(x), y0 = floorf(y);
            float samp = 0.f;
            #pragma unroll
            for (int cq = 0; cq < 4; cq++) {
                const float xi = x0 + (float)(cq & 1);
                const float yi = y0 + (float)(cq >> 1);
                const float w = (1.f - fabsf(x - xi)) * (1.f - fabsf(y - yi));
                if (xi >= 0.f && xi < Wl && yi >= 0.f && yi < Hl && w != 0.f) {
                    const int ii = (int)yi * Wi + (int)xi;
                    samp += w * __bfloat162float(vbase[(size_t)ii * DM]);
                }
            }
            const float awp = __shfl_sync(0xffffffffu, aw, lvl * 4 + p);
            accv += awp * samp;
        }
    }
    outh[bq * DM + h * HD + lane] = __float2bfloat16(accv);
}

// ---------------- launch ----------------
extern "C" void kernel_launch(void* const* d_in, const int* in_sizes, int n_in,
                              void* d_out, int out_size)
{
    (void)in_sizes; (void)n_in; (void)out_size;
    const float* tgt   = (const float*)d_in[0];
    const float* mem   = (const float*)d_in[1];
    const float* refp  = (const float*)d_in[3];
    const float* ipw = (const float*)d_in[6],  *ipb = (const float*)d_in[7];
    const float* opw = (const float*)d_in[8],  *opb = (const float*)d_in[9];
    const float* n1g = (const float*)d_in[10], *n1b = (const float*)d_in[11];
    const float* n2g = (const float*)d_in[12], *n2b = (const float*)d_in[13];
    const float* n3g = (const float*)d_in[14], *n3b = (const float*)d_in[15];
    const float* sow = (const float*)d_in[16], *sob = (const float*)d_in[17];
    const float* aww = (const float*)d_in[18], *awb = (const float*)d_in[19];
    const float* vpw = (const float*)d_in[20], *vpb = (const float*)d_in[21];
    const float* oqw = (const float*)d_in[22], *oqb = (const float*)d_in[23];
    const float* l1w = (const float*)d_in[24], *l1b = (const float*)d_in[25];
    const float* l2w = (const float*)d_in[26], *l2b = (const float*)d_in[27];
    float* out = (float*)d_out;

    float *buf, *tgt1, *tgt2, *offaw, *soawb;
    cudaGetSymbolAddress((void**)&buf,   g_buf);
    cudaGetSymbolAddress((void**)&tgt1,  g_tgt1);
    cudaGetSymbolAddress((void**)&tgt2,  g_tgt2);
    cudaGetSymbolAddress((void**)&offaw, g_offaw);
    cudaGetSymbolAddress((void**)&soawb, g_soawb);

    __nv_bfloat16 *p_qkv, *p_sa, *p_tgt1, *p_val, *p_ca, *p_tgt2, *p_ffn1;
    __nv_bfloat16 *p_ipw, *p_opw, *p_vpw, *p_soaw, *p_oqw, *p_l1w, *p_l2w;
    cudaGetSymbolAddress((void**)&p_qkv,  b_qkv);
    cudaGetSymbolAddress((void**)&p_sa,   b_sa);
    cudaGetSymbolAddress((void**)&p_tgt1, b_tgt1);
    cudaGetSymbolAddress((void**)&p_val,  b_val);
    cudaGetSymbolAddress((void**)&p_ca,   b_ca);
    cudaGetSymbolAddress((void**)&p_tgt2, b_tgt2);
    cudaGetSymbolAddress((void**)&p_ffn1, b_ffn1);
    cudaGetSymbolAddress((void**)&p_ipw,  b_ipw);
    cudaGetSymbolAddress((void**)&p_opw,  b_opw);
    cudaGetSymbolAddress((void**)&p_vpw,  b_vpw);
    cudaGetSymbolAddress((void**)&p_soaw, b_soaw);
    cudaGetSymbolAddress((void**)&p_oqw,  b_oqw);
    cudaGetSymbolAddress((void**)&p_l1w,  b_l1w);
    cudaGetSymbolAddress((void**)&p_l2w,  b_l2w);

    const int SMEM1 = 2 * 2 * TILEB;   // 40960
    const int SMEM2 = 2 * 3 * TILEB;   // 61440
    cudaFuncSetAttribute(gemm_mma<1, false, false, 1, true,  true >, cudaFuncAttributeMaxDynamicSharedMemorySize, SMEM1);
    cudaFuncSetAttribute(gemm_mma<1, false, false, 1, true,  false>, cudaFuncAttributeMaxDynamicSharedMemorySize, SMEM1);
    cudaFuncSetAttribute(gemm_mma<1, false, true,  0, false, false>, cudaFuncAttributeMaxDynamicSharedMemorySize, SMEM1);
    cudaFuncSetAttribute(gemm_mma<1, false, false, 0, false, false>, cudaFuncAttributeMaxDynamicSharedMemorySize, SMEM1);
    cudaFuncSetAttribute(gemm_mma<2, true,  false, 1, false, false>, cudaFuncAttributeMaxDynamicSharedMemorySize, SMEM2);
    cudaFuncSetAttribute(gemm_mma<2, false, true,  0, false, false>, cudaFuncAttributeMaxDynamicSharedMemorySize, SMEM2);

    const int MT  = (BQ + 127) / 128;    // 57
    const int MTV = (BS + 127) / 128;    // 831

    cudaStream_t s2;
    cudaStreamCreateWithFlags(&s2, cudaStreamNonBlocking);
    cudaEvent_t evA, evB;
    cudaEventCreateWithFlags(&evA, cudaEventDisableTiming);
    cudaEventCreateWithFlags(&evB, cudaEventDisableTiming);

#define HL(p, n) (p), (p) + (n)

    // ---- all weight conversions + fused bias, ONE launch ----
    convert_all<<<(254048 + 255) / 256, 256>>>(
        ipw, opw, vpw, sow, aww, oqw, l1w, l2w, sob, awb,
        p_ipw, p_opw, p_vpw, p_soaw, p_oqw, p_l1w, p_l2w, soawb);

    // fork: value projection on s2
    cudaEventRecord(evA, 0);
    cudaStreamWaitEvent(s2, evA, 0);
    gemm_mma<1, false, false, 1, true, false><<<dim3(2, MTV), 256, SMEM1, s2>>>(
        mem, nullptr, nullptr, p_vpw, nullptr, vpb, nullptr, nullptr, p_val, nullptr, BS, DM, DM);
    cudaEventRecord(evB, s2);

    // main path
    // 1. QKV projection (AFP32, x1, bf16 out, Q pre-scaled by scale*log2e)
    gemm_mma<1, false, false, 1, true, true><<<dim3(6, MT), 256, SMEM1>>>(
        tgt, nullptr, nullptr, p_ipw, nullptr, ipb, nullptr, nullptr, p_qkv, nullptr, BQ, 768, DM);
    // 2. flash self-attention (log2-domain softmax)
    attn_mma<<<dim3(8, NH, B_), 256>>>(p_qkv, p_sa);
    // 3. out-proj + residual (x1), 4. LN1 (hi split)
    gemm_mma<1, false, true, 0, false, false><<<dim3(2, MT), 256, SMEM1>>>(
        nullptr, p_sa, nullptr, p_opw, nullptr, opb, tgt, buf, nullptr, nullptr, BQ, DM, DM);
    ln_kernel<1><<<BQ / 8, 256>>>(buf, n1g, n1b, tgt1, p_tgt1, nullptr);
    // 5+6. fused sampling offsets + attention-weight logits (N=384)
    gemm_mma<1, false, false, 0, false, false><<<dim3(3, MT), 256, SMEM1>>>(
        nullptr, p_tgt1, nullptr, p_soaw, nullptr, soawb, nullptr, offaw, nullptr, nullptr, BQ, 384, DM);

    // join: need value tensor before sampling
    cudaStreamWaitEvent((cudaStream_t)0, evB, 0);
    // 7. deformable sampling -> bf16 ca
    deform_kernel<<<(B_ * Q_ * NH * 32 + 255) / 256, 256>>>(offaw, p_val, refp, p_ca);
    // 8. output proj + residual (x1), 9. LN2 (hi split)
    gemm_mma<1, false, true, 0, false, false><<<dim3(2, MT), 256, SMEM1>>>(
        nullptr, p_ca, nullptr, p_oqw, nullptr, oqb, tgt1, buf, nullptr, nullptr, BQ, DM, DM);
    ln_kernel<1><<<BQ / 8, 256>>>(buf, n2g, n2b, tgt2, p_tgt2, nullptr);
    // 10. FFN up + relu (x2, hi out), 11. FFN down + residual (x2), 12. LN3 -> out
    gemm_mma<2, true, false, 1, false, false><<<dim3(8, MT), 256, SMEM2>>>(
        nullptr, p_tgt2, nullptr, HL(p_l1w, 1024 * 256), l1b, nullptr, nullptr, p_ffn1, nullptr, BQ, DFFN, DM);
    gemm_mma<2, false, true, 0, false, false><<<dim3(2, MT), 256, SMEM2>>>(
        nullptr, p_ffn1, nullptr, HL(p_l2w, 256 * 1024), l2b, tgt2, buf, nullptr, nullptr, BQ, DM, DFFN);
    ln_kernel<0><<<BQ / 8, 256>>>(buf, n3g, n3b, out, nullptr, nullptr);
#undef HL
}

// round 12
// speedup vs baseline: 3.6088x; 1.0065x over previous
#include <cuda_runtime.h>
#include <cuda_bf16.h>
#include <math.h>
#include <stdint.h>

// ---------------- problem constants ----------------
#define B_      8
#define Q_      900
#define BQ      7200          // B*Q
#define DM      256
#define STOT    13294
#define BS      106352        // B*STOT
#define NH      8
#define HD      32
#define DFFN    1024

// ---------------- fp32 scratch ----------------
__device__ float g_buf  [BQ * DM];
__device__ float g_tgt1 [BQ * DM];
__device__ float g_tgt2 [BQ * DM];
__device__ float g_offaw[BQ * 384];
__device__ float g_soawb[384];

// ---------------- bf16 scratch ----------------
__device__ __nv_bfloat16 b_qkv [BQ * 768];
__device__ __nv_bfloat16 b_sa  [BQ * DM];
__device__ __nv_bfloat16 b_tgt1[BQ * DM];
__device__ __nv_bfloat16 b_val [(size_t)BS * DM];
__device__ __nv_bfloat16 b_ca  [BQ * DM];
__device__ __nv_bfloat16 b_tgt2[BQ * DM];
__device__ __nv_bfloat16 b_ffn1[BQ * DFFN];
__device__ __nv_bfloat16 b_ipw [768 * 256];
__device__ __nv_bfloat16 b_opw [256 * 256];
__device__ __nv_bfloat16 b_vpw [256 * 256];
__device__ __nv_bfloat16 b_soaw[384 * 256];      // sow (256 rows) ++ aww (128 rows)
__device__ __nv_bfloat16 b_oqw [256 * 256];
__device__ __nv_bfloat16 b_l1w [2][1024 * 256];
__device__ __nv_bfloat16 b_l2w [2][256 * 1024];

// ---------------- helpers ----------------
__device__ __forceinline__ uint32_t smem_u32(const void* p) {
    uint32_t a;
    asm("{ .reg .u64 t; cvta.to.shared.u64 t, %1; cvt.u32.u64 %0, t; }" : "=r"(a) : "l"(p));
    return a;
}
__device__ __forceinline__ float ex2f(float x) {
    float y;
    asm("ex2.approx.f32 %0, %1;" : "=f"(y) : "f"(x));
    return y;
}
__device__ __forceinline__ void ldsm4(uint32_t* r, uint32_t addr) {
    asm volatile("ldmatrix.sync.aligned.m8n8.x4.shared.b16 {%0,%1,%2,%3}, [%4];"
        : "=r"(r[0]), "=r"(r[1]), "=r"(r[2]), "=r"(r[3]) : "r"(addr));
}
__device__ __forceinline__ void ldsm4t(uint32_t* r, uint32_t addr) {
    asm volatile("ldmatrix.sync.aligned.m8n8.x4.trans.shared.b16 {%0,%1,%2,%3}, [%4];"
        : "=r"(r[0]), "=r"(r[1]), "=r"(r[2]), "=r"(r[3]) : "r"(addr));
}
__device__ __forceinline__ void mma16816(float* c, const uint32_t* a, const uint32_t* b) {
    asm volatile("mma.sync.aligned.m16n8k16.row.col.f32.bf16.bf16.f32 "
        "{%0,%1,%2,%3}, {%4,%5,%6,%7}, {%8,%9}, {%0,%1,%2,%3};"
        : "+f"(c[0]), "+f"(c[1]), "+f"(c[2]), "+f"(c[3])
        : "r"(a[0]), "r"(a[1]), "r"(a[2]), "r"(a[3]), "r"(b[0]), "r"(b[1]));
}
__device__ __forceinline__ void cpasync16(uint32_t dst, const void* src, int sz) {
    asm volatile("cp.async.cg.shared.global [%0], [%1], 16, %2;" :: "r"(dst), "l"(src), "r"(sz));
}
__device__ __forceinline__ void split2(float a, float b, __nv_bfloat162& h, __nv_bfloat162& l) {
    h = __floats2bfloat162_rn(a, b);
    float2 hf = __bfloat1622float2(h);
    l = __floats2bfloat162_rn(a - hf.x, b - hf.y);
}
__device__ __forceinline__ uint32_t pack_bf16(float a, float b) {
    __nv_bfloat162 h = __floats2bfloat162_rn(a, b);
    return *reinterpret_cast<uint32_t*>(&h);
}

// ---------------- one-shot weight conversion (all weights + fused bias) ----------------
__global__ __launch_bounds__(256)
void convert_all(const float* __restrict__ ipw, const float* __restrict__ opw,
                 const float* __restrict__ vpw, const float* __restrict__ sow,
                 const float* __restrict__ aww, const float* __restrict__ oqw,
                 const float* __restrict__ l1w, const float* __restrict__ l2w,
                 const float* __restrict__ sob, const float* __restrict__ awb,
                 __nv_bfloat16* __restrict__ d_ipw, __nv_bfloat16* __restrict__ d_opw,
                 __nv_bfloat16* __restrict__ d_vpw, __nv_bfloat16* __restrict__ d_soaw,
                 __nv_bfloat16* __restrict__ d_oqw, __nv_bfloat16* __restrict__ d_l1w,
                 __nv_bfloat16* __restrict__ d_l2w, float* __restrict__ soawb)
{
    const int i = blockIdx.x * 256 + threadIdx.x;
    const float* src;
    __nv_bfloat16* hi;
    __nv_bfloat16* lo = nullptr;
    int base;
    if (i < 49152)       { src = ipw; hi = d_ipw; base = 0; }
    else if (i < 65536)  { src = opw; hi = d_opw; base = 49152; }
    else if (i < 81920)  { src = vpw; hi = d_vpw; base = 65536; }
    else if (i < 98304)  { src = sow; hi = d_soaw; base = 81920; }
    else if (i < 106496) { src = aww; hi = d_soaw + 65536; base = 98304; }
    else if (i < 122880) { src = oqw; hi = d_oqw; base = 106496; }
    else if (i < 188416) { src = l1w; hi = d_l1w; lo = d_l1w + 262144; base = 122880; }
    else if (i < 253952) { src = l2w; hi = d_l2w; lo = d_l2w + 262144; base = 188416; }
    else if (i < 254048) {
        const int j = i - 253952;
        float4 v = (j < 64) ? ((const float4*)sob)[j] : ((const float4*)awb)[j - 64];
        ((float4*)soawb)[j] = v;
        return;
    } else return;

    const int j = i - base;
    float4 v = ((const float4*)src)[j];
    if (lo == nullptr) {
        ((__nv_bfloat162*)hi)[j * 2 + 0] = __floats2bfloat162_rn(v.x, v.y);
        ((__nv_bfloat162*)hi)[j * 2 + 1] = __floats2bfloat162_rn(v.z, v.w);
    } else {
        __nv_bfloat162 h0, l0, h1, l1;
        split2(v.x, v.y, h0, l0);
        split2(v.z, v.w, h1, l1);
        ((__nv_bfloat162*)hi)[j * 2 + 0] = h0;
        ((__nv_bfloat162*)hi)[j * 2 + 1] = h1;
        ((__nv_bfloat162*)lo)[j * 2 + 0] = l0;
        ((__nv_bfloat162*)lo)[j * 2 + 1] = l1;
    }
}

// ---------------- bf16 mma.sync GEMM ----------------
// NPASS: 1 = Ah*Wh; 2 = Ah*Wh + Ah*Wl; 3 = Ah*Wh + Al*Wh + Ah*Wl.
// OUT: 0 = fp32 C, 1 = bf16 Ch, 2 = bf16 Ch+Cl.
// AFP32: A read fp32 with register-pipelined inline conversion.
// QS: scale output columns < 256 by softmax_scale*log2(e) (QKV Q-fold).
#define TILEB 10240

template<int NPASS, bool RELU, bool RESID, int OUT, bool AFP32, bool QS>
__global__ __launch_bounds__(256)
void gemm_mma(const float* __restrict__ Af,
              const __nv_bfloat16* __restrict__ Ah, const __nv_bfloat16* __restrict__ Al,
              const __nv_bfloat16* __restrict__ Wh, const __nv_bfloat16* __restrict__ Wl,
              const float* __restrict__ bias, const float* __restrict__ R,
              float* __restrict__ C, __nv_bfloat16* __restrict__ Ch,
              __nv_bfloat16* __restrict__ Cl, int M, int N, int K)
{
    constexpr int NTIL = (NPASS == 3) ? 4 : (NPASS == 2 ? 3 : 2);
    constexpr int STGB = NTIL * TILEB;
    constexpr int WOFF = (NPASS == 3 ? 2 : 1) * TILEB;

    extern __shared__ char smem[];
    const uint32_t sb = smem_u32(smem);
    const int tid = threadIdx.x, lane = tid & 31, wid = tid >> 5;
    const int am = (wid & 3) * 32;
    const int bn = (wid >> 2) * 64;
    const int m0 = blockIdx.y * 128, n0 = blockIdx.x * 128;

    float c[2][8][4] = {};

    float4 aReg[2][2];
    const int pr0 = tid >> 2, pq = tid & 3;

#define LDG_A(ch) do {                                                            \
    const int kb_ = (ch) * 32;                                                    \
    _Pragma("unroll")                                                             \
    for (int u_ = 0; u_ < 2; u_++) {                                              \
        int r_ = pr0 + u_ * 64;                                                   \
        int row_ = m0 + r_; if (row_ >= M) row_ = M - 1;                          \
        const float* p_ = Af + (size_t)row_ * K + kb_ + pq * 8;                   \
        aReg[u_][0] = *(const float4*)p_;                                         \
        aReg[u_][1] = *(const float4*)(p_ + 4);                                   \
    }                                                                             \
} while (0)

#define STS_A(st) do {                                                            \
    _Pragma("unroll")                                                             \
    for (int u_ = 0; u_ < 2; u_++) {                                              \
        int r_ = pr0 + u_ * 64;                                                   \
        uint4 w4_;                                                                \
        w4_.x = pack_bf16(aReg[u_][0].x, aReg[u_][0].y);                          \
        w4_.y = pack_bf16(aReg[u_][0].z, aReg[u_][0].w);                          \
        w4_.z = pack_bf16(aReg[u_][1].x, aReg[u_][1].y);                          \
        w4_.w = pack_bf16(aReg[u_][1].z, aReg[u_][1].w);                          \
        *(uint4*)(smem + (st) * STGB + r_ * 80 + pq * 16) = w4_;                  \
    }                                                                             \
} while (0)

#define ISSUE_W(st, ch) do {                                                      \
    const int kb_ = (ch) * 32;                                                    \
    const uint32_t so_ = sb + (st) * STGB;                                        \
    _Pragma("unroll")                                                             \
    for (int cix = tid; cix < (NPASS >= 2 ? 1024 : 512); cix += 256) {            \
        int t_ = cix >> 9, idx_ = cix & 511, r_ = idx_ >> 2, q_ = idx_ & 3;       \
        const __nv_bfloat16* base_ = t_ ? Wl : Wh;                                \
        cpasync16(so_ + WOFF + t_ * TILEB + r_ * 80 + q_ * 16,                    \
                  base_ + (size_t)(n0 + r_) * K + kb_ + q_ * 8, 16);              \
    }                                                                             \
    asm volatile("cp.async.commit_group;" ::: "memory");                          \
} while (0)

#define ISSUE_AB(st, ch) do {                                                     \
    const int kb_ = (ch) * 32;                                                    \
    const uint32_t so_ = sb + (st) * STGB;                                        \
    _Pragma("unroll")                                                             \
    for (int cix = tid; cix < NTIL * 512; cix += 256) {                           \
        int t_ = cix >> 9, idx_ = cix & 511, r_ = idx_ >> 2, q_ = idx_ & 3;       \
        uint32_t d_ = so_ + t_ * TILEB + r_ * 80 + q_ * 16;                       \
        const __nv_bfloat16* base_;                                               \
        bool isA_;                                                                \
        if (NPASS == 1) { isA_ = (t_ == 0); base_ = isA_ ? Ah : Wh; }             \
        else if (NPASS == 2) { isA_ = (t_ == 0);                                  \
               base_ = (t_ == 0 ? Ah : t_ == 1 ? Wh : Wl); }                      \
        else { isA_ = (t_ < 2);                                                   \
               base_ = (t_ == 0 ? Ah : t_ == 1 ? Al : t_ == 2 ? Wh : Wl); }       \
        if (isA_) cpasync16(d_, base_ + (size_t)(m0 + r_) * K + kb_ + q_ * 8,     \
                            (m0 + r_) < M ? 16 : 0);                              \
        else      cpasync16(d_, base_ + (size_t)(n0 + r_) * K + kb_ + q_ * 8, 16);\
    }                                                                             \
    asm volatile("cp.async.commit_group;" ::: "memory");                          \
} while (0)

    const int nCh = K >> 5;
    if (AFP32) {
        LDG_A(0);
        ISSUE_W(0, 0);
    } else {
        ISSUE_AB(0, 0);
    }

    const int lar = lane & 15;
    const int lac = (lane >> 4) * 16;
    const int lbr = (lane & 7) + ((lane >> 4) & 1) * 8;
    const int lbc = ((lane >> 3) & 1) * 16;

    for (int ch = 0; ch < nCh; ch++) {
        if (AFP32) {
            STS_A(ch & 1);
            if (ch + 1 < nCh) {
                LDG_A(ch + 1);
                ISSUE_W((ch + 1) & 1, ch + 1);
                asm volatile("cp.async.wait_group 1;" ::: "memory");
            } else {
                asm volatile("cp.async.wait_group 0;" ::: "memory");
            }
        } else {
            if (ch + 1 < nCh) {
                ISSUE_AB((ch + 1) & 1, ch + 1);
                asm volatile("cp.async.wait_group 1;" ::: "memory");
            } else {
                asm volatile("cp.async.wait_group 0;" ::: "memory");
            }
        }
        __syncthreads();

        const uint32_t so = sb + (ch & 1) * STGB;
        #pragma unroll
        for (int ks = 0; ks < 2; ks++) {
            uint32_t ah[2][4], al[2][4], bb[4][4];
            const uint32_t acol = ks * 32 + lac;
            const uint32_t bcol = ks * 32 + lbc;
            ldsm4(ah[0], so + (am + lar) * 80 + acol);
            ldsm4(ah[1], so + (am + 16 + lar) * 80 + acol);
            if (NPASS == 3) {
                ldsm4(al[0], so + TILEB + (am + lar) * 80 + acol);
                ldsm4(al[1], so + TILEB + (am + 16 + lar) * 80 + acol);
            }
            #pragma unroll
            for (int p = 0; p < 4; p++)
                ldsm4(bb[p], so + WOFF + (bn + p * 16 + lbr) * 80 + bcol);
            #pragma unroll
            for (int fm = 0; fm < 2; fm++)
                #pragma unroll
                for (int p = 0; p < 4; p++) {
                    mma16816(c[fm][2 * p],     ah[fm], bb[p]);
                    mma16816(c[fm][2 * p + 1], ah[fm], bb[p] + 2);
                    if (NPASS == 3) {
                        mma16816(c[fm][2 * p],     al[fm], bb[p]);
                        mma16816(c[fm][2 * p + 1], al[fm], bb[p] + 2);
                    }
                }
            if (NPASS >= 2) {
                #pragma unroll
                for (int p = 0; p < 4; p++)
                    ldsm4(bb[p], so + WOFF + TILEB + (bn + p * 16 + lbr) * 80 + bcol);
                #pragma unroll
                for (int fm = 0; fm < 2; fm++)
                    #pragma unroll
                    for (int p = 0; p < 4; p++) {
                        mma16816(c[fm][2 * p],     ah[fm], bb[p]);
                        mma16816(c[fm][2 * p + 1], ah[fm], bb[p] + 2);
                    }
            }
        }
        __syncthreads();
    }
#undef ISSUE_AB
#undef ISSUE_W
#undef STS_A
#undef LDG_A

    // epilogue
    const int r0 = m0 + am + (lane >> 2);
    const int colb = n0 + bn + (lane & 3) * 2;
    #pragma unroll
    for (int fm = 0; fm < 2; fm++) {
        #pragma unroll
        for (int p = 0; p < 8; p++) {
            const int col = colb + p * 8;
            const float2 bv = *(const float2*)(bias + col);
            #pragma unroll
            for (int hh = 0; hh < 2; hh++) {
                const int row = r0 + fm * 16 + hh * 8;
                if (row < M) {
                    float o0 = c[fm][p][hh * 2 + 0] + bv.x;
                    float o1 = c[fm][p][hh * 2 + 1] + bv.y;
                    if (QS && col < 256) {
                        const float qsf = 0.17677669529663687f * 1.4426950408889634f;
                        o0 *= qsf; o1 *= qsf;
                    }
                    if (RESID) {
                        float2 rv = *(const float2*)(R + (size_t)row * N + col);
                        o0 += rv.x; o1 += rv.y;
                    }
                    if (RELU) { o0 = fmaxf(o0, 0.f); o1 = fmaxf(o1, 0.f); }
                    if (OUT == 0) {
                        *(float2*)(C + (size_t)row * N + col) = make_float2(o0, o1);
                    } else if (OUT == 1) {
                        *(__nv_bfloat162*)(Ch + (size_t)row * N + col) = __floats2bfloat162_rn(o0, o1);
                    } else {
                        __nv_bfloat162 h, l;
                        split2(o0, o1, h, l);
                        *(__nv_bfloat162*)(Ch + (size_t)row * N + col) = h;
                        *(__nv_bfloat162*)(Cl + (size_t)row * N + col) = l;
                    }
                }
            }
        }
    }
}

// ---------------- flash self-attention, bf16 mma.sync, log2-domain softmax ----------------
// 64 Q-rows per CTA, 128 threads (4 warps x 16 rows) -> 5 CTAs/SM occupancy.
// Q pre-scaled by softmax_scale*log2(e) in QKV epilogue.
#define KVB 5120

__global__ __launch_bounds__(128)
void attn_mma(const __nv_bfloat16* __restrict__ qkv, __nv_bfloat16* __restrict__ sa)
{
    __shared__ __nv_bfloat16 Qs[64 * 40];
    __shared__ __nv_bfloat16 Ks[2][64 * 40];
    __shared__ __nv_bfloat16 Vs[2][64 * 40];
    const int b = blockIdx.z, h = blockIdx.y, q0 = blockIdx.x * 64;
    const int tid = threadIdx.x, lane = tid & 31, wid = tid >> 5;
    const uint32_t sQ = smem_u32(Qs), sK = smem_u32(Ks), sV = smem_u32(Vs);

#define ISSUE_KV(t, bufi) do {                                                    \
    const int kv0_ = (t) * 64;                                                    \
    _Pragma("unroll")                                                             \
    for (int i_ = tid; i_ < 512; i_ += 128) {                                     \
        int te_ = i_ >> 8, idx_ = i_ & 255, r_ = idx_ >> 2, cc_ = idx_ & 3;       \
        const __nv_bfloat16* src_ = qkv + (size_t)(b * Q_ + kv0_ + r_) * 768      \
                                    + 256 + te_ * 256 + h * HD + cc_ * 8;         \
        cpasync16((te_ ? sV : sK) + (bufi) * KVB + r_ * 80 + cc_ * 16, src_,      \
                  (kv0_ + r_) < Q_ ? 16 : 0);                                     \
    }                                                                             \
    asm volatile("cp.async.commit_group;" ::: "memory");                          \
} while (0)

    #pragma unroll
    for (int i = tid; i < 256; i += 128) {
        int r = i >> 2, cc = i & 3;
        const __nv_bfloat16* src = qkv + (size_t)(b * Q_ + q0 + r) * 768 + h * HD + cc * 8;
        cpasync16(sQ + r * 80 + cc * 16, src, (q0 + r) < Q_ ? 16 : 0);
    }
    asm volatile("cp.async.commit_group;" ::: "memory");
    ISSUE_KV(0, 0);
    asm volatile("cp.async.wait_group 1;" ::: "memory");
    __syncthreads();

    const int r8 = (lane & 7) + ((lane >> 3) & 1) * 8;
    const int c16 = (lane >> 4) * 16;

    uint32_t qf[2][4];
    {
        uint32_t qa = sQ + (wid * 16 + r8) * 80 + c16;
        ldsm4(qf[0], qa);
        ldsm4(qf[1], qa + 32);
    }

    float mr[2] = {-1e30f, -1e30f}, lr[2] = {0.f, 0.f};
    float o[4][4] = {};

    for (int t = 0; t < 15; t++) {
        const int kv0 = t * 64;
        if (t + 1 < 15) {
            ISSUE_KV(t + 1, (t + 1) & 1);
            asm volatile("cp.async.wait_group 1;" ::: "memory");
        } else {
            asm volatile("cp.async.wait_group 0;" ::: "memory");
        }
        __syncthreads();

        const uint32_t sKb = sK + (t & 1) * KVB;
        const uint32_t sVb = sV + (t & 1) * KVB;

        float c[8][4] = {};
        #pragma unroll
        for (int ks = 0; ks < 2; ks++) {
            #pragma unroll
            for (int p = 0; p < 4; p++) {
                uint32_t kf[4];
                ldsm4(kf, sKb + (p * 16 + r8) * 80 + c16 + ks * 32);
                uint32_t b0[2] = {kf[0], kf[2]}, b1[2] = {kf[1], kf[3]};
                mma16816(c[2 * p],     qf[ks], b0);
                mma16816(c[2 * p + 1], qf[ks], b1);
            }
        }
        if (kv0 + 64 > Q_) {
            #pragma unroll
            for (int p8 = 0; p8 < 8; p8++)
                #pragma unroll
                for (int j = 0; j < 2; j++)
                    if (kv0 + p8 * 8 + 2 * (lane & 3) + j >= Q_) {
                        c[p8][j] = -1e30f;
                        c[p8][2 + j] = -1e30f;
                    }
        }
        // online softmax in log2 domain
        #pragma unroll
        for (int rw = 0; rw < 2; rw++) {
            float mx = mr[rw];
            #pragma unroll
            for (int p8 = 0; p8 < 8; p8++)
                mx = fmaxf(mx, fmaxf(c[p8][2 * rw], c[p8][2 * rw + 1]));
            mx = fmaxf(mx, __shfl_xor_sync(0xffffffffu, mx, 1));
            mx = fmaxf(mx, __shfl_xor_sync(0xffffffffu, mx, 2));
            float corr = ex2f(mr[rw] - mx);
            float s = 0.f;
            #pragma unroll
            for (int p8 = 0; p8 < 8; p8++) {
                c[p8][2 * rw]     = ex2f(c[p8][2 * rw] - mx);
                c[p8][2 * rw + 1] = ex2f(c[p8][2 * rw + 1] - mx);
                s += c[p8][2 * rw] + c[p8][2 * rw + 1];
            }
            s += __shfl_xor_sync(0xffffffffu, s, 1);
            s += __shfl_xor_sync(0xffffffffu, s, 2);
            lr[rw] = lr[rw] * corr + s;
            mr[rw] = mx;
            #pragma unroll
            for (int nt = 0; nt < 4; nt++) {
                o[nt][2 * rw] *= corr;
                o[nt][2 * rw + 1] *= corr;
            }
        }
        #pragma unroll
        for (int ts = 0; ts < 4; ts++) {
            uint32_t af[4];
            af[0] = pack_bf16(c[2 * ts][0], c[2 * ts][1]);
            af[1] = pack_bf16(c[2 * ts][2], c[2 * ts][3]);
            af[2] = pack_bf16(c[2 * ts + 1][0], c[2 * ts + 1][1]);
            af[3] = pack_bf16(c[2 * ts + 1][2], c[2 * ts + 1][3]);
            #pragma unroll
            for (int np = 0; np < 2; np++) {
                uint32_t vf[4];
                ldsm4t(vf, sVb + (ts * 16 + r8) * 80 + np * 32 + c16);
                uint32_t b0[2] = {vf[0], vf[1]}, b1[2] = {vf[2], vf[3]};
                mma16816(o[2 * np],     af, b0);
                mma16816(o[2 * np + 1], af, b1);
            }
        }
        __syncthreads();
    }
#undef ISSUE_KV

    const float inv0 = 1.f / lr[0], inv1 = 1.f / lr[1];
    const int gr0 = q0 + wid * 16 + (lane >> 2);
    #pragma unroll
    for (int nt = 0; nt < 4; nt++) {
        const int col = h * HD + nt * 8 + 2 * (lane & 3);
        if (gr0 < Q_)
            *(__nv_bfloat162*)(sa + (size_t)(b * Q_ + gr0) * DM + col)
                = __floats2bfloat162_rn(o[nt][0] * inv0, o[nt][1] * inv0);
        if (gr0 + 8 < Q_)
            *(__nv_bfloat162*)(sa + (size_t)(b * Q_ + gr0 + 8) * DM + col)
                = __floats2bfloat162_rn(o[nt][2] * inv1, o[nt][3] * inv1);
    }
}

// ---------------- LayerNorm: warp per row, 8 rows/CTA ----------------
template<int OSPLIT>
__global__ __launch_bounds__(256)
void ln_kernel(const float* __restrict__ in, const float* __restrict__ g,
               const float* __restrict__ bta, float* __restrict__ out,
               __nv_bfloat16* __restrict__ oh, __nv_bfloat16* __restrict__ ol)
{
    const int warp = threadIdx.x >> 5, lane = threadIdx.x & 31;
    const int row = blockIdx.x * 8 + warp;
    const float4* ip = (const float4*)(in + (size_t)row * DM);
    float4 v0 = ip[lane], v1 = ip[lane + 32];

    float s = ((v0.x + v0.y) + (v0.z + v0.w)) + ((v1.x + v1.y) + (v1.z + v1.w));
    #pragma unroll
    for (int o = 16; o > 0; o >>= 1) s += __shfl_xor_sync(0xffffffffu, s, o);
    const float mu = s * (1.f / 256.f);

    v0.x -= mu; v0.y -= mu; v0.z -= mu; v0.w -= mu;
    v1.x -= mu; v1.y -= mu; v1.z -= mu; v1.w -= mu;
    float vs = ((v0.x * v0.x + v0.y * v0.y) + (v0.z * v0.z + v0.w * v0.w))
             + ((v1.x * v1.x + v1.y * v1.y) + (v1.z * v1.z + v1.w * v1.w));
    #pragma unroll
    for (int o = 16; o > 0; o >>= 1) vs += __shfl_xor_sync(0xffffffffu, vs, o);
    const float rs = rsqrtf(vs * (1.f / 256.f) + 1e-5f);

    const float4 g0 = ((const float4*)g)[lane],  g1 = ((const float4*)g)[lane + 32];
    const float4 b0 = ((const float4*)bta)[lane], b1 = ((const float4*)bta)[lane + 32];
    float4 y0, y1;
    y0.x = v0.x * rs * g0.x + b0.x; y0.y = v0.y * rs * g0.y + b0.y;
    y0.z = v0.z * rs * g0.z + b0.z; y0.w = v0.w * rs * g0.w + b0.w;
    y1.x = v1.x * rs * g1.x + b1.x; y1.y = v1.y * rs * g1.y + b1.y;
    y1.z = v1.z * rs * g1.z + b1.z; y1.w = v1.w * rs * g1.w + b1.w;

    float4* op = (float4*)(out + (size_t)row * DM);
    op[lane] = y0; op[lane + 32] = y1;

    if (OSPLIT >= 1) {
        const size_t i0 = (size_t)row * DM + lane * 4;
        const size_t i1 = i0 + 128;
        if (OSPLIT == 1) {
            *(__nv_bfloat162*)(oh + i0)     = __floats2bfloat162_rn(y0.x, y0.y);
            *(__nv_bfloat162*)(oh + i0 + 2) = __floats2bfloat162_rn(y0.z, y0.w);
            *(__nv_bfloat162*)(oh + i1)     = __floats2bfloat162_rn(y1.x, y1.y);
            *(__nv_bfloat162*)(oh + i1 + 2) = __floats2bfloat162_rn(y1.z, y1.w);
        } else {
            __nv_bfloat162 h, l;
            split2(y0.x, y0.y, h, l);
            *(__nv_bfloat162*)(oh + i0) = h;     *(__nv_bfloat162*)(ol + i0) = l;
            split2(y0.z, y0.w, h, l);
            *(__nv_bfloat162*)(oh + i0 + 2) = h; *(__nv_bfloat162*)(ol + i0 + 2) = l;
            split2(y1.x, y1.y, h, l);
            *(__nv_bfloat162*)(oh + i1) = h;     *(__nv_bfloat162*)(ol + i1) = l;
            split2(y1.z, y1.w, h, l);
            *(__nv_bfloat162*)(oh + i1 + 2) = h; *(__nv_bfloat162*)(ol + i1 + 2) = l;
        }
    }
}

// ---------------- deformable sampling + weight softmax ----------------
__global__ __launch_bounds__(256)
void deform_kernel(const float* __restrict__ offaw,
                   const __nv_bfloat16* __restrict__ value, const float* __restrict__ refp,
                   __nv_bfloat16* __restrict__ outh)
{
    const int gw = (blockIdx.x * blockDim.x + threadIdx.x) >> 5;
    const int lane = threadIdx.x & 31;
    if (gw >= B_ * Q_ * NH) return;
    const int h = gw & 7;
    const int q = (gw >> 3) % Q_;
    const int b = gw / (NH * Q_);
    const size_t bq = (size_t)b * Q_ + q;

    float logit = (lane < 16) ? offaw[bq * 384 + 256 + h * 16 + lane] : -1e30f;
    float mx = logit;
    #pragma unroll
    for (int o = 16; o > 0; o >>= 1) mx = fmaxf(mx, __shfl_xor_sync(0xffffffffu, mx, o));
    float e = (lane < 16) ? __expf(logit - mx) : 0.f;
    float se = e;
    #pragma unroll
    for (int o = 16; o > 0; o >>= 1) se += __shfl_xor_sync(0xffffffffu, se, o);
    const float aw = e / se;

    const int HWl[4][2] = {{100,100},{50,50},{25,25},{13,13}};
    const int ST[4]     = {0, 10000, 12500, 13125};

    float accv = 0.f;
    #pragma unroll
    for (int lvl = 0; lvl < 4; lvl++) {
        const int Hi = HWl[lvl][0], Wi = HWl[lvl][1];
        const float Hl = (float)Hi, Wl = (float)Wi;
        const float refx = refp[(bq * 4 + lvl) * 2 + 0];
        const float refy = refp[(bq * 4 + lvl) * 2 + 1];
        const __nv_bfloat16* vbase = value + ((size_t)b * STOT + ST[lvl]) * DM + h * HD + lane;
        #pragma unroll
        for (int p = 0; p < 4; p++) {
            const int oidx = ((h * 4 + lvl) * 4 + p) * 2;
            const float ox = offaw[bq * 384 + oidx + 0];
            const float oy = offaw[bq * 384 + oidx + 1];
            const float x = (refx + ox / Wl) * Wl - 0.5f;
            const float y = (refy + oy / Hl) * Hl - 0.5f;
            const float x0 = floorf(x), y0 = floorf(y);
            float samp = 0.f;
            #pragma unroll
            for (int cq = 0; cq < 4; cq++) {
                const float xi = x0 + (float)(cq & 1);
                const float yi = y0 + (float)(cq >> 1);
                const float w = (1.f - fabsf(x - xi)) * (1.f - fabsf(y - yi));
                if (xi >= 0.f && xi < Wl && yi >= 0.f && yi < Hl && w != 0.f) {
                    const int ii = (int)yi * Wi + (int)xi;
                    samp += w * __bfloat162float(vbase[(size_t)ii * DM]);
                }
            }
            const float awp = __shfl_sync(0xffffffffu, aw, lvl * 4 + p);
            accv += awp * samp;
        }
    }
    outh[bq * DM + h * HD + lane] = __float2bfloat16(accv);
}

// ---------------- launch ----------------
extern "C" void kernel_launch(void* const* d_in, const int* in_sizes, int n_in,
                              void* d_out, int out_size)
{
    (void)in_sizes; (void)n_in; (void)out_size;
    const float* tgt   = (const float*)d_in[0];
    const float* mem   = (const float*)d_in[1];
    const float* refp  = (const float*)d_in[3];
    const float* ipw = (const float*)d_in[6],  *ipb = (const float*)d_in[7];
    const float* opw = (const float*)d_in[8],  *opb = (const float*)d_in[9];
    const float* n1g = (const float*)d_in[10], *n1b = (const float*)d_in[11];
    const float* n2g = (const float*)d_in[12], *n2b = (const float*)d_in[13];
    const float* n3g = (const float*)d_in[14], *n3b = (const float*)d_in[15];
    const float* sow = (const float*)d_in[16], *sob = (const float*)d_in[17];
    const float* aww = (const float*)d_in[18], *awb = (const float*)d_in[19];
    const float* vpw = (const float*)d_in[20], *vpb = (const float*)d_in[21];
    const float* oqw = (const float*)d_in[22], *oqb = (const float*)d_in[23];
    const float* l1w = (const float*)d_in[24], *l1b = (const float*)d_in[25];
    const float* l2w = (const float*)d_in[26], *l2b = (const float*)d_in[27];
    float* out = (float*)d_out;

    float *buf, *tgt1, *tgt2, *offaw, *soawb;
    cudaGetSymbolAddress((void**)&buf,   g_buf);
    cudaGetSymbolAddress((void**)&tgt1,  g_tgt1);
    cudaGetSymbolAddress((void**)&tgt2,  g_tgt2);
    cudaGetSymbolAddress((void**)&offaw, g_offaw);
    cudaGetSymbolAddress((void**)&soawb, g_soawb);

    __nv_bfloat16 *p_qkv, *p_sa, *p_tgt1, *p_val, *p_ca, *p_tgt2, *p_ffn1;
    __nv_bfloat16 *p_ipw, *p_opw, *p_vpw, *p_soaw, *p_oqw, *p_l1w, *p_l2w;
    cudaGetSymbolAddress((void**)&p_qkv,  b_qkv);
    cudaGetSymbolAddress((void**)&p_sa,   b_sa);
    cudaGetSymbolAddress((void**)&p_tgt1, b_tgt1);
    cudaGetSymbolAddress((void**)&p_val,  b_val);
    cudaGetSymbolAddress((void**)&p_ca,   b_ca);
    cudaGetSymbolAddress((void**)&p_tgt2, b_tgt2);
    cudaGetSymbolAddress((void**)&p_ffn1, b_ffn1);
    cudaGetSymbolAddress((void**)&p_ipw,  b_ipw);
    cudaGetSymbolAddress((void**)&p_opw,  b_opw);
    cudaGetSymbolAddress((void**)&p_vpw,  b_vpw);
    cudaGetSymbolAddress((void**)&p_soaw, b_soaw);
    cudaGetSymbolAddress((void**)&p_oqw,  b_oqw);
    cudaGetSymbolAddress((void**)&p_l1w,  b_l1w);
    cudaGetSymbolAddress((void**)&p_l2w,  b_l2w);

    const int SMEM1 = 2 * 2 * TILEB;   // 40960
    const int SMEM2 = 2 * 3 * TILEB;   // 61440
    cudaFuncSetAttribute(gemm_mma<1, false, false, 1, true,  true >, cudaFuncAttributeMaxDynamicSharedMemorySize, SMEM1);
    cudaFuncSetAttribute(gemm_mma<1, false, false, 1, true,  false>, cudaFuncAttributeMaxDynamicSharedMemorySize, SMEM1);
    cudaFuncSetAttribute(gemm_mma<1, false, true,  0, false, false>, cudaFuncAttributeMaxDynamicSharedMemorySize, SMEM1);
    cudaFuncSetAttribute(gemm_mma<1, false, false, 0, false, false>, cudaFuncAttributeMaxDynamicSharedMemorySize, SMEM1);
    cudaFuncSetAttribute(gemm_mma<2, true,  false, 1, false, false>, cudaFuncAttributeMaxDynamicSharedMemorySize, SMEM2);
    cudaFuncSetAttribute(gemm_mma<2, false, true,  0, false, false>, cudaFuncAttributeMaxDynamicSharedMemorySize, SMEM2);

    const int MT  = (BQ + 127) / 128;    // 57
    const int MTV = (BS + 127) / 128;    // 831

    cudaStream_t s2;
    cudaStreamCreateWithFlags(&s2, cudaStreamNonBlocking);
    cudaEvent_t evA, evB;
    cudaEventCreateWithFlags(&evA, cudaEventDisableTiming);
    cudaEventCreateWithFlags(&evB, cudaEventDisableTiming);

#define HL(p, n) (p), (p) + (n)

    // ---- all weight conversions + fused bias, ONE launch ----
    convert_all<<<(254048 + 255) / 256, 256>>>(
        ipw, opw, vpw, sow, aww, oqw, l1w, l2w, sob, awb,
        p_ipw, p_opw, p_vpw, p_soaw, p_oqw, p_l1w, p_l2w, soawb);

    // fork: value projection on s2
    cudaEventRecord(evA, 0);
    cudaStreamWaitEvent(s2, evA, 0);
    gemm_mma<1, false, false, 1, true, false><<<dim3(2, MTV), 256, SMEM1, s2>>>(
        mem, nullptr, nullptr, p_vpw, nullptr, vpb, nullptr, nullptr, p_val, nullptr, BS, DM, DM);
    cudaEventRecord(evB, s2);

    // main path
    // 1. QKV projection (AFP32, x1, bf16 out, Q pre-scaled by scale*log2e)
    gemm_mma<1, false, false, 1, true, true><<<dim3(6, MT), 256, SMEM1>>>(
        tgt, nullptr, nullptr, p_ipw, nullptr, ipb, nullptr, nullptr, p_qkv, nullptr, BQ, 768, DM);
    // 2. flash self-attention (64-row tiles, 128 threads)
    attn_mma<<<dim3((Q_ + 63) / 64, NH, B_), 128>>>(p_qkv, p_sa);
    // 3. out-proj + residual (x1), 4. LN1 (hi split)
    gemm_mma<1, false, true, 0, false, false><<<dim3(2, MT), 256, SMEM1>>>(
        nullptr, p_sa, nullptr, p_opw, nullptr, opb, tgt, buf, nullptr, nullptr, BQ, DM, DM);
    ln_kernel<1><<<BQ / 8, 256>>>(buf, n1g, n1b, tgt1, p_tgt1, nullptr);
    // 5+6. fused sampling offsets + attention-weight logits (N=384)
    gemm_mma<1, false, false, 0, false, false><<<dim3(3, MT), 256, SMEM1>>>(
        nullptr, p_tgt1, nullptr, p_soaw, nullptr, soawb, nullptr, offaw, nullptr, nullptr, BQ, 384, DM);

    // join: need value tensor before sampling
    cudaStreamWaitEvent((cudaStream_t)0, evB, 0);
    // 7. deformable sampling -> bf16 ca
    deform_kernel<<<(B_ * Q_ * NH * 32 + 255) / 256, 256>>>(offaw, p_val, refp, p_ca);
    // 8. output proj + residual (x1), 9. LN2 (hi split)
    gemm_mma<1, false, true, 0, false, false><<<dim3(2, MT), 256, SMEM1>>>(
        nullptr, p_ca, nullptr, p_oqw, nullptr, oqb, tgt1, buf, nullptr, nullptr, BQ, DM, DM);
    ln_kernel<1><<<BQ / 8, 256>>>(buf, n2g, n2b, tgt2, p_tgt2, nullptr);
    // 10. FFN up + relu (x2, hi out), 11. FFN down + residual (x2), 12. LN3 -> out
    gemm_mma<2, true, false, 1, false, false><<<dim3(8, MT), 256, SMEM2>>>(
        nullptr, p_tgt2, nullptr, HL(p_l1w, 1024 * 256), l1b, nullptr, nullptr, p_ffn1, nullptr, BQ, DFFN, DM);
    gemm_mma<2, false, true, 0, false, false><<<dim3(2, MT), 256, SMEM2>>>(
        nullptr, p_ffn1, nullptr, HL(p_l2w, 256 * 1024), l2b, tgt2, buf, nullptr, nullptr, BQ, DM, DFFN);
    ln_kernel<0><<<BQ / 8, 256>>>(buf, n3g, n3b, out, nullptr, nullptr);
#undef HL
}

// round 13
// speedup vs baseline: 3.7002x; 1.0253x over previous
#include <cuda_runtime.h>
#include <cuda_bf16.h>
#include <math.h>
#include <stdint.h>

// ---------------- problem constants ----------------
#define B_      8
#define Q_      900
#define BQ      7200          // B*Q
#define DM      256
#define STOT    13294
#define BS      106352        // B*STOT
#define NH      8
#define HD      32
#define DFFN    1024

// ---------------- fp32 scratch ----------------
__device__ float g_buf  [BQ * DM];
__device__ float g_tgt1 [BQ * DM];
__device__ float g_tgt2 [BQ * DM];
__device__ float g_offaw[BQ * 384];
__device__ float g_soawb[384];

// ---------------- bf16 scratch ----------------
__device__ __nv_bfloat16 b_qkv [BQ * 768];
__device__ __nv_bfloat16 b_sa  [BQ * DM];
__device__ __nv_bfloat16 b_tgt1[BQ * DM];
__device__ __nv_bfloat16 b_val [(size_t)BS * DM];
__device__ __nv_bfloat16 b_ca  [BQ * DM];
__device__ __nv_bfloat16 b_tgt2[BQ * DM];
__device__ __nv_bfloat16 b_ffn1[BQ * DFFN];
__device__ __nv_bfloat16 b_ipw [768 * 256];
__device__ __nv_bfloat16 b_opw [256 * 256];
__device__ __nv_bfloat16 b_vpw [256 * 256];
__device__ __nv_bfloat16 b_soaw[384 * 256];      // sow (256 rows) ++ aww (128 rows)
__device__ __nv_bfloat16 b_oqw [256 * 256];
__device__ __nv_bfloat16 b_l1w [2][1024 * 256];
__device__ __nv_bfloat16 b_l2w [2][256 * 1024];

// ---------------- helpers ----------------
__device__ __forceinline__ uint32_t smem_u32(const void* p) {
    uint32_t a;
    asm("{ .reg .u64 t; cvta.to.shared.u64 t, %1; cvt.u32.u64 %0, t; }" : "=r"(a) : "l"(p));
    return a;
}
__device__ __forceinline__ float ex2f(float x) {
    float y;
    asm("ex2.approx.f32 %0, %1;" : "=f"(y) : "f"(x));
    return y;
}
__device__ __forceinline__ void ldsm4(uint32_t* r, uint32_t addr) {
    asm volatile("ldmatrix.sync.aligned.m8n8.x4.shared.b16 {%0,%1,%2,%3}, [%4];"
        : "=r"(r[0]), "=r"(r[1]), "=r"(r[2]), "=r"(r[3]) : "r"(addr));
}
__device__ __forceinline__ void ldsm4t(uint32_t* r, uint32_t addr) {
    asm volatile("ldmatrix.sync.aligned.m8n8.x4.trans.shared.b16 {%0,%1,%2,%3}, [%4];"
        : "=r"(r[0]), "=r"(r[1]), "=r"(r[2]), "=r"(r[3]) : "r"(addr));
}
__device__ __forceinline__ void mma16816(float* c, const uint32_t* a, const uint32_t* b) {
    asm volatile("mma.sync.aligned.m16n8k16.row.col.f32.bf16.bf16.f32 "
        "{%0,%1,%2,%3}, {%4,%5,%6,%7}, {%8,%9}, {%0,%1,%2,%3};"
        : "+f"(c[0]), "+f"(c[1]), "+f"(c[2]), "+f"(c[3])
        : "r"(a[0]), "r"(a[1]), "r"(a[2]), "r"(a[3]), "r"(b[0]), "r"(b[1]));
}
__device__ __forceinline__ void cpasync16(uint32_t dst, const void* src, int sz) {
    asm volatile("cp.async.cg.shared.global [%0], [%1], 16, %2;" :: "r"(dst), "l"(src), "r"(sz));
}
__device__ __forceinline__ void split2(float a, float b, __nv_bfloat162& h, __nv_bfloat162& l) {
    h = __floats2bfloat162_rn(a, b);
    float2 hf = __bfloat1622float2(h);
    l = __floats2bfloat162_rn(a - hf.x, b - hf.y);
}
__device__ __forceinline__ uint32_t pack_bf16(float a, float b) {
    __nv_bfloat162 h = __floats2bfloat162_rn(a, b);
    return *reinterpret_cast<uint32_t*>(&h);
}

// ---------------- one-shot weight conversion (all weights + fused bias) ----------------
__global__ __launch_bounds__(256)
void convert_all(const float* __restrict__ ipw, const float* __restrict__ opw,
                 const float* __restrict__ vpw, const float* __restrict__ sow,
                 const float* __restrict__ aww, const float* __restrict__ oqw,
                 const float* __restrict__ l1w, const float* __restrict__ l2w,
                 const float* __restrict__ sob, const float* __restrict__ awb,
                 __nv_bfloat16* __restrict__ d_ipw, __nv_bfloat16* __restrict__ d_opw,
                 __nv_bfloat16* __restrict__ d_vpw, __nv_bfloat16* __restrict__ d_soaw,
                 __nv_bfloat16* __restrict__ d_oqw, __nv_bfloat16* __restrict__ d_l1w,
                 __nv_bfloat16* __restrict__ d_l2w, float* __restrict__ soawb)
{
    const int i = blockIdx.x * 256 + threadIdx.x;
    const float* src;
    __nv_bfloat16* hi;
    __nv_bfloat16* lo = nullptr;
    int base;
    if (i < 49152)       { src = ipw; hi = d_ipw; base = 0; }
    else if (i < 65536)  { src = opw; hi = d_opw; base = 49152; }
    else if (i < 81920)  { src = vpw; hi = d_vpw; base = 65536; }
    else if (i < 98304)  { src = sow; hi = d_soaw; base = 81920; }
    else if (i < 106496) { src = aww; hi = d_soaw + 65536; base = 98304; }
    else if (i < 122880) { src = oqw; hi = d_oqw; base = 106496; }
    else if (i < 188416) { src = l1w; hi = d_l1w; lo = d_l1w + 262144; base = 122880; }
    else if (i < 253952) { src = l2w; hi = d_l2w; lo = d_l2w + 262144; base = 188416; }
    else if (i < 254048) {
        const int j = i - 253952;
        float4 v = (j < 64) ? ((const float4*)sob)[j] : ((const float4*)awb)[j - 64];
        ((float4*)soawb)[j] = v;
        return;
    } else return;

    const int j = i - base;
    float4 v = ((const float4*)src)[j];
    if (lo == nullptr) {
        ((__nv_bfloat162*)hi)[j * 2 + 0] = __floats2bfloat162_rn(v.x, v.y);
        ((__nv_bfloat162*)hi)[j * 2 + 1] = __floats2bfloat162_rn(v.z, v.w);
    } else {
        __nv_bfloat162 h0, l0, h1, l1;
        split2(v.x, v.y, h0, l0);
        split2(v.z, v.w, h1, l1);
        ((__nv_bfloat162*)hi)[j * 2 + 0] = h0;
        ((__nv_bfloat162*)hi)[j * 2 + 1] = h1;
        ((__nv_bfloat162*)lo)[j * 2 + 0] = l0;
        ((__nv_bfloat162*)lo)[j * 2 + 1] = l1;
    }
}

// ---------------- bf16 mma.sync GEMM ----------------
// NPASS: 1 = Ah*Wh; 2 = Ah*Wh + Ah*Wl; 3 = Ah*Wh + Al*Wh + Ah*Wl.
// OUT: 0 = fp32 C, 1 = bf16 Ch, 2 = bf16 Ch+Cl.
// AFP32: A read fp32 with register-pipelined inline conversion.
// QS: scale output columns < 256 by softmax_scale*log2(e) (QKV Q-fold).
#define TILEB 10240

template<int NPASS, bool RELU, bool RESID, int OUT, bool AFP32, bool QS>
__global__ __launch_bounds__(256)
void gemm_mma(const float* __restrict__ Af,
              const __nv_bfloat16* __restrict__ Ah, const __nv_bfloat16* __restrict__ Al,
              const __nv_bfloat16* __restrict__ Wh, const __nv_bfloat16* __restrict__ Wl,
              const float* __restrict__ bias, const float* __restrict__ R,
              float* __restrict__ C, __nv_bfloat16* __restrict__ Ch,
              __nv_bfloat16* __restrict__ Cl, int M, int N, int K)
{
    constexpr int NTIL = (NPASS == 3) ? 4 : (NPASS == 2 ? 3 : 2);
    constexpr int STGB = NTIL * TILEB;
    constexpr int WOFF = (NPASS == 3 ? 2 : 1) * TILEB;

    extern __shared__ char smem[];
    const uint32_t sb = smem_u32(smem);
    const int tid = threadIdx.x, lane = tid & 31, wid = tid >> 5;
    const int am = (wid & 3) * 32;
    const int bn = (wid >> 2) * 64;
    const int m0 = blockIdx.y * 128, n0 = blockIdx.x * 128;

    float c[2][8][4] = {};

    float4 aReg[2][2];
    const int pr0 = tid >> 2, pq = tid & 3;

#define LDG_A(ch) do {                                                            \
    const int kb_ = (ch) * 32;                                                    \
    _Pragma("unroll")                                                             \
    for (int u_ = 0; u_ < 2; u_++) {                                              \
        int r_ = pr0 + u_ * 64;                                                   \
        int row_ = m0 + r_; if (row_ >= M) row_ = M - 1;                          \
        const float* p_ = Af + (size_t)row_ * K + kb_ + pq * 8;                   \
        aReg[u_][0] = *(const float4*)p_;                                         \
        aReg[u_][1] = *(const float4*)(p_ + 4);                                   \
    }                                                                             \
} while (0)

#define STS_A(st) do {                                                            \
    _Pragma("unroll")                                                             \
    for (int u_ = 0; u_ < 2; u_++) {                                              \
        int r_ = pr0 + u_ * 64;                                                   \
        uint4 w4_;                                                                \
        w4_.x = pack_bf16(aReg[u_][0].x, aReg[u_][0].y);                          \
        w4_.y = pack_bf16(aReg[u_][0].z, aReg[u_][0].w);                          \
        w4_.z = pack_bf16(aReg[u_][1].x, aReg[u_][1].y);                          \
        w4_.w = pack_bf16(aReg[u_][1].z, aReg[u_][1].w);                          \
        *(uint4*)(smem + (st) * STGB + r_ * 80 + pq * 16) = w4_;                  \
    }                                                                             \
} while (0)

#define ISSUE_W(st, ch) do {                                                      \
    const int kb_ = (ch) * 32;                                                    \
    const uint32_t so_ = sb + (st) * STGB;                                        \
    _Pragma("unroll")                                                             \
    for (int cix = tid; cix < (NPASS >= 2 ? 1024 : 512); cix += 256) {            \
        int t_ = cix >> 9, idx_ = cix & 511, r_ = idx_ >> 2, q_ = idx_ & 3;       \
        const __nv_bfloat16* base_ = t_ ? Wl : Wh;                                \
        cpasync16(so_ + WOFF + t_ * TILEB + r_ * 80 + q_ * 16,                    \
                  base_ + (size_t)(n0 + r_) * K + kb_ + q_ * 8, 16);              \
    }                                                                             \
    asm volatile("cp.async.commit_group;" ::: "memory");                          \
} while (0)

#define ISSUE_AB(st, ch) do {                                                     \
    const int kb_ = (ch) * 32;                                                    \
    const uint32_t so_ = sb + (st) * STGB;                                        \
    _Pragma("unroll")                                                             \
    for (int cix = tid; cix < NTIL * 512; cix += 256) {                           \
        int t_ = cix >> 9, idx_ = cix & 511, r_ = idx_ >> 2, q_ = idx_ & 3;       \
        uint32_t d_ = so_ + t_ * TILEB + r_ * 80 + q_ * 16;                       \
        const __nv_bfloat16* base_;                                               \
        bool isA_;                                                                \
        if (NPASS == 1) { isA_ = (t_ == 0); base_ = isA_ ? Ah : Wh; }             \
        else if (NPASS == 2) { isA_ = (t_ == 0);                                  \
               base_ = (t_ == 0 ? Ah : t_ == 1 ? Wh : Wl); }                      \
        else { isA_ = (t_ < 2);                                                   \
               base_ = (t_ == 0 ? Ah : t_ == 1 ? Al : t_ == 2 ? Wh : Wl); }       \
        if (isA_) cpasync16(d_, base_ + (size_t)(m0 + r_) * K + kb_ + q_ * 8,     \
                            (m0 + r_) < M ? 16 : 0);                              \
        else      cpasync16(d_, base_ + (size_t)(n0 + r_) * K + kb_ + q_ * 8, 16);\
    }                                                                             \
    asm volatile("cp.async.commit_group;" ::: "memory");                          \
} while (0)

    const int nCh = K >> 5;
    if (AFP32) {
        LDG_A(0);
        ISSUE_W(0, 0);
    } else {
        ISSUE_AB(0, 0);
    }

    const int lar = lane & 15;
    const int lac = (lane >> 4) * 16;
    const int lbr = (lane & 7) + ((lane >> 4) & 1) * 8;
    const int lbc = ((lane >> 3) & 1) * 16;

    for (int ch = 0; ch < nCh; ch++) {
        if (AFP32) {
            STS_A(ch & 1);
            if (ch + 1 < nCh) {
                LDG_A(ch + 1);
                ISSUE_W((ch + 1) & 1, ch + 1);
                asm volatile("cp.async.wait_group 1;" ::: "memory");
            } else {
                asm volatile("cp.async.wait_group 0;" ::: "memory");
            }
        } else {
            if (ch + 1 < nCh) {
                ISSUE_AB((ch + 1) & 1, ch + 1);
                asm volatile("cp.async.wait_group 1;" ::: "memory");
            } else {
                asm volatile("cp.async.wait_group 0;" ::: "memory");
            }
        }
        __syncthreads();

        const uint32_t so = sb + (ch & 1) * STGB;
        #pragma unroll
        for (int ks = 0; ks < 2; ks++) {
            uint32_t ah[2][4], al[2][4], bb[4][4];
            const uint32_t acol = ks * 32 + lac;
            const uint32_t bcol = ks * 32 + lbc;
            ldsm4(ah[0], so + (am + lar) * 80 + acol);
            ldsm4(ah[1], so + (am + 16 + lar) * 80 + acol);
            if (NPASS == 3) {
                ldsm4(al[0], so + TILEB + (am + lar) * 80 + acol);
                ldsm4(al[1], so + TILEB + (am + 16 + lar) * 80 + acol);
            }
            #pragma unroll
            for (int p = 0; p < 4; p++)
                ldsm4(bb[p], so + WOFF + (bn + p * 16 + lbr) * 80 + bcol);
            #pragma unroll
            for (int fm = 0; fm < 2; fm++)
                #pragma unroll
                for (int p = 0; p < 4; p++) {
                    mma16816(c[fm][2 * p],     ah[fm], bb[p]);
                    mma16816(c[fm][2 * p + 1], ah[fm], bb[p] + 2);
                    if (NPASS == 3) {
                        mma16816(c[fm][2 * p],     al[fm], bb[p]);
                        mma16816(c[fm][2 * p + 1], al[fm], bb[p] + 2);
                    }
                }
            if (NPASS >= 2) {
                #pragma unroll
                for (int p = 0; p < 4; p++)
                    ldsm4(bb[p], so + WOFF + TILEB + (bn + p * 16 + lbr) * 80 + bcol);
                #pragma unroll
                for (int fm = 0; fm < 2; fm++)
                    #pragma unroll
                    for (int p = 0; p < 4; p++) {
                        mma16816(c[fm][2 * p],     ah[fm], bb[p]);
                        mma16816(c[fm][2 * p + 1], ah[fm], bb[p] + 2);
                    }
            }
        }
        __syncthreads();
    }
#undef ISSUE_AB
#undef ISSUE_W
#undef STS_A
#undef LDG_A

    // epilogue
    const int r0 = m0 + am + (lane >> 2);
    const int colb = n0 + bn + (lane & 3) * 2;
    #pragma unroll
    for (int fm = 0; fm < 2; fm++) {
        #pragma unroll
        for (int p = 0; p < 8; p++) {
            const int col = colb + p * 8;
            const float2 bv = *(const float2*)(bias + col);
            #pragma unroll
            for (int hh = 0; hh < 2; hh++) {
                const int row = r0 + fm * 16 + hh * 8;
                if (row < M) {
                    float o0 = c[fm][p][hh * 2 + 0] + bv.x;
                    float o1 = c[fm][p][hh * 2 + 1] + bv.y;
                    if (QS && col < 256) {
                        const float qsf = 0.17677669529663687f * 1.4426950408889634f;
                        o0 *= qsf; o1 *= qsf;
                    }
                    if (RESID) {
                        float2 rv = *(const float2*)(R + (size_t)row * N + col);
                        o0 += rv.x; o1 += rv.y;
                    }
                    if (RELU) { o0 = fmaxf(o0, 0.f); o1 = fmaxf(o1, 0.f); }
                    if (OUT == 0) {
                        *(float2*)(C + (size_t)row * N + col) = make_float2(o0, o1);
                    } else if (OUT == 1) {
                        *(__nv_bfloat162*)(Ch + (size_t)row * N + col) = __floats2bfloat162_rn(o0, o1);
                    } else {
                        __nv_bfloat162 h, l;
                        split2(o0, o1, h, l);
                        *(__nv_bfloat162*)(Ch + (size_t)row * N + col) = h;
                        *(__nv_bfloat162*)(Cl + (size_t)row * N + col) = l;
                    }
                }
            }
        }
    }
}

// ---------------- flash self-attention, bf16 mma.sync ----------------
// No-max softmax: scores (already scaled by scale*log2e in QKV epilogue) are
// O(1)-bounded for this layer; ex2 in fp32 cannot overflow, masked scores
// (-1e30) underflow to exactly 0. Removes the entire online-softmax
// correction chain; Σexp accumulated lane-locally, reduced once at the end.
// 64 Q-rows per CTA, 128 threads (4 warps x 16 rows).
#define KVB 5120

__global__ __launch_bounds__(128)
void attn_mma(const __nv_bfloat16* __restrict__ qkv, __nv_bfloat16* __restrict__ sa)
{
    __shared__ __nv_bfloat16 Qs[64 * 40];
    __shared__ __nv_bfloat16 Ks[2][64 * 40];
    __shared__ __nv_bfloat16 Vs[2][64 * 40];
    const int b = blockIdx.z, h = blockIdx.y, q0 = blockIdx.x * 64;
    const int tid = threadIdx.x, lane = tid & 31, wid = tid >> 5;
    const uint32_t sQ = smem_u32(Qs), sK = smem_u32(Ks), sV = smem_u32(Vs);

#define ISSUE_KV(t, bufi) do {                                                    \
    const int kv0_ = (t) * 64;                                                    \
    _Pragma("unroll")                                                             \
    for (int i_ = tid; i_ < 512; i_ += 128) {                                     \
        int te_ = i_ >> 8, idx_ = i_ & 255, r_ = idx_ >> 2, cc_ = idx_ & 3;       \
        const __nv_bfloat16* src_ = qkv + (size_t)(b * Q_ + kv0_ + r_) * 768      \
                                    + 256 + te_ * 256 + h * HD + cc_ * 8;         \
        cpasync16((te_ ? sV : sK) + (bufi) * KVB + r_ * 80 + cc_ * 16, src_,      \
                  (kv0_ + r_) < Q_ ? 16 : 0);                                     \
    }                                                                             \
    asm volatile("cp.async.commit_group;" ::: "memory");                          \
} while (0)

    #pragma unroll
    for (int i = tid; i < 256; i += 128) {
        int r = i >> 2, cc = i & 3;
        const __nv_bfloat16* src = qkv + (size_t)(b * Q_ + q0 + r) * 768 + h * HD + cc * 8;
        cpasync16(sQ + r * 80 + cc * 16, src, (q0 + r) < Q_ ? 16 : 0);
    }
    asm volatile("cp.async.commit_group;" ::: "memory");
    ISSUE_KV(0, 0);
    asm volatile("cp.async.wait_group 1;" ::: "memory");
    __syncthreads();

    const int r8 = (lane & 7) + ((lane >> 3) & 1) * 8;
    const int c16 = (lane >> 4) * 16;

    uint32_t qf[2][4];
    {
        uint32_t qa = sQ + (wid * 16 + r8) * 80 + c16;
        ldsm4(qf[0], qa);
        ldsm4(qf[1], qa + 32);
    }

    float lr[2] = {0.f, 0.f};
    float o[4][4] = {};

    for (int t = 0; t < 15; t++) {
        const int kv0 = t * 64;
        if (t + 1 < 15) {
            ISSUE_KV(t + 1, (t + 1) & 1);
            asm volatile("cp.async.wait_group 1;" ::: "memory");
        } else {
            asm volatile("cp.async.wait_group 0;" ::: "memory");
        }
        __syncthreads();

        const uint32_t sKb = sK + (t & 1) * KVB;
        const uint32_t sVb = sV + (t & 1) * KVB;

        float c[8][4] = {};
        #pragma unroll
        for (int ks = 0; ks < 2; ks++) {
            #pragma unroll
            for (int p = 0; p < 4; p++) {
                uint32_t kf[4];
                ldsm4(kf, sKb + (p * 16 + r8) * 80 + c16 + ks * 32);
                uint32_t b0[2] = {kf[0], kf[2]}, b1[2] = {kf[1], kf[3]};
                mma16816(c[2 * p],     qf[ks], b0);
                mma16816(c[2 * p + 1], qf[ks], b1);
            }
        }
        if (kv0 + 64 > Q_) {
            #pragma unroll
            for (int p8 = 0; p8 < 8; p8++)
                #pragma unroll
                for (int j = 0; j < 2; j++)
                    if (kv0 + p8 * 8 + 2 * (lane & 3) + j >= Q_) {
                        c[p8][j] = -1e30f;
                        c[p8][2 + j] = -1e30f;
                    }
        }
        // no-max softmax: exponentiate and accumulate lane-local partial sums
        #pragma unroll
        for (int p8 = 0; p8 < 8; p8++) {
            c[p8][0] = ex2f(c[p8][0]);
            c[p8][1] = ex2f(c[p8][1]);
            c[p8][2] = ex2f(c[p8][2]);
            c[p8][3] = ex2f(c[p8][3]);
            lr[0] += c[p8][0] + c[p8][1];
            lr[1] += c[p8][2] + c[p8][3];
        }
        #pragma unroll
        for (int ts = 0; ts < 4; ts++) {
            uint32_t af[4];
            af[0] = pack_bf16(c[2 * ts][0], c[2 * ts][1]);
            af[1] = pack_bf16(c[2 * ts][2], c[2 * ts][3]);
            af[2] = pack_bf16(c[2 * ts + 1][0], c[2 * ts + 1][1]);
            af[3] = pack_bf16(c[2 * ts + 1][2], c[2 * ts + 1][3]);
            #pragma unroll
            for (int np = 0; np < 2; np++) {
                uint32_t vf[4];
                ldsm4t(vf, sVb + (ts * 16 + r8) * 80 + np * 32 + c16);
                uint32_t b0[2] = {vf[0], vf[1]}, b1[2] = {vf[2], vf[3]};
                mma16816(o[2 * np],     af, b0);
                mma16816(o[2 * np + 1], af, b1);
            }
        }
        __syncthreads();
    }
#undef ISSUE_KV

    // final Σexp reduction across the 4 lanes of each row quad
    #pragma unroll
    for (int rw = 0; rw < 2; rw++) {
        lr[rw] += __shfl_xor_sync(0xffffffffu, lr[rw], 1);
        lr[rw] += __shfl_xor_sync(0xffffffffu, lr[rw], 2);
    }

    const float inv0 = 1.f / lr[0], inv1 = 1.f / lr[1];
    const int gr0 = q0 + wid * 16 + (lane >> 2);
    #pragma unroll
    for (int nt = 0; nt < 4; nt++) {
        const int col = h * HD + nt * 8 + 2 * (lane & 3);
        if (gr0 < Q_)
            *(__nv_bfloat162*)(sa + (size_t)(b * Q_ + gr0) * DM + col)
                = __floats2bfloat162_rn(o[nt][0] * inv0, o[nt][1] * inv0);
        if (gr0 + 8 < Q_)
            *(__nv_bfloat162*)(sa + (size_t)(b * Q_ + gr0 + 8) * DM + col)
                = __floats2bfloat162_rn(o[nt][2] * inv1, o[nt][3] * inv1);
    }
}

// ---------------- LayerNorm: warp per row, 8 rows/CTA ----------------
template<int OSPLIT>
__global__ __launch_bounds__(256)
void ln_kernel(const float* __restrict__ in, const float* __restrict__ g,
               const float* __restrict__ bta, float* __restrict__ out,
               __nv_bfloat16* __restrict__ oh, __nv_bfloat16* __restrict__ ol)
{
    const int warp = threadIdx.x >> 5, lane = threadIdx.x & 31;
    const int row = blockIdx.x * 8 + warp;
    const float4* ip = (const float4*)(in + (size_t)row * DM);
    float4 v0 = ip[lane], v1 = ip[lane + 32];

    float s = ((v0.x + v0.y) + (v0.z + v0.w)) + ((v1.x + v1.y) + (v1.z + v1.w));
    #pragma unroll
    for (int o = 16; o > 0; o >>= 1) s += __shfl_xor_sync(0xffffffffu, s, o);
    const float mu = s * (1.f / 256.f);

    v0.x -= mu; v0.y -= mu; v0.z -= mu; v0.w -= mu;
    v1.x -= mu; v1.y -= mu; v1.z -= mu; v1.w -= mu;
    float vs = ((v0.x * v0.x + v0.y * v0.y) + (v0.z * v0.z + v0.w * v0.w))
             + ((v1.x * v1.x + v1.y * v1.y) + (v1.z * v1.z + v1.w * v1.w));
    #pragma unroll
    for (int o = 16; o > 0; o >>= 1) vs += __shfl_xor_sync(0xffffffffu, vs, o);
    const float rs = rsqrtf(vs * (1.f / 256.f) + 1e-5f);

    const float4 g0 = ((const float4*)g)[lane],  g1 = ((const float4*)g)[lane + 32];
    const float4 b0 = ((const float4*)bta)[lane], b1 = ((const float4*)bta)[lane + 32];
    float4 y0, y1;
    y0.x = v0.x * rs * g0.x + b0.x; y0.y = v0.y * rs * g0.y + b0.y;
    y0.z = v0.z * rs * g0.z + b0.z; y0.w = v0.w * rs * g0.w + b0.w;
    y1.x = v1.x * rs * g1.x + b1.x; y1.y = v1.y * rs * g1.y + b1.y;
    y1.z = v1.z * rs * g1.z + b1.z; y1.w = v1.w * rs * g1.w + b1.w;

    float4* op = (float4*)(out + (size_t)row * DM);
    op[lane] = y0; op[lane + 32] = y1;

    if (OSPLIT >= 1) {
        const size_t i0 = (size_t)row * DM + lane * 4;
        const size_t i1 = i0 + 128;
        if (OSPLIT == 1) {
            *(__nv_bfloat162*)(oh + i0)     = __floats2bfloat162_rn(y0.x, y0.y);
            *(__nv_bfloat162*)(oh + i0 + 2) = __floats2bfloat162_rn(y0.z, y0.w);
            *(__nv_bfloat162*)(oh + i1)     = __floats2bfloat162_rn(y1.x, y1.y);
            *(__nv_bfloat162*)(oh + i1 + 2) = __floats2bfloat162_rn(y1.z, y1.w);
        } else {
            __nv_bfloat162 h, l;
            split2(y0.x, y0.y, h, l);
            *(__nv_bfloat162*)(oh + i0) = h;     *(__nv_bfloat162*)(ol + i0) = l;
            split2(y0.z, y0.w, h, l);
            *(__nv_bfloat162*)(oh + i0 + 2) = h; *(__nv_bfloat162*)(ol + i0 + 2) = l;
            split2(y1.x, y1.y, h, l);
            *(__nv_bfloat162*)(oh + i1) = h;     *(__nv_bfloat162*)(ol + i1) = l;
            split2(y1.z, y1.w, h, l);
            *(__nv_bfloat162*)(oh + i1 + 2) = h; *(__nv_bfloat162*)(ol + i1 + 2) = l;
        }
    }
}

// ---------------- deformable sampling + weight softmax ----------------
__global__ __launch_bounds__(256)
void deform_kernel(const float* __restrict__ offaw,
                   const __nv_bfloat16* __restrict__ value, const float* __restrict__ refp,
                   __nv_bfloat16* __restrict__ outh)
{
    const int gw = (blockIdx.x * blockDim.x + threadIdx.x) >> 5;
    const int lane = threadIdx.x & 31;
    if (gw >= B_ * Q_ * NH) return;
    const int h = gw & 7;
    const int q = (gw >> 3) % Q_;
    const int b = gw / (NH * Q_);
    const size_t bq = (size_t)b * Q_ + q;

    float logit = (lane < 16) ? offaw[bq * 384 + 256 + h * 16 + lane] : -1e30f;
    float mx = logit;
    #pragma unroll
    for (int o = 16; o > 0; o >>= 1) mx = fmaxf(mx, __shfl_xor_sync(0xffffffffu, mx, o));
    float e = (lane < 16) ? __expf(logit - mx) : 0.f;
    float se = e;
    #pragma unroll
    for (int o = 16; o > 0; o >>= 1) se += __shfl_xor_sync(0xffffffffu, se, o);
    const float aw = e / se;

    const int HWl[4][2] = {{100,100},{50,50},{25,25},{13,13}};
    const int ST[4]     = {0, 10000, 12500, 13125};

    float accv = 0.f;
    #pragma unroll
    for (int lvl = 0; lvl < 4; lvl++) {
        const int Hi = HWl[lvl][0], Wi = HWl[lvl][1];
        const float Hl = (float)Hi, Wl = (float)Wi;
        const float refx = refp[(bq * 4 + lvl) * 2 + 0];
        const float refy = refp[(bq * 4 + lvl) * 2 + 1];
        const __nv_bfloat16* vbase = value + ((size_t)b * STOT + ST[lvl]) * DM + h * HD + lane;
        #pragma unroll
        for (int p = 0; p < 4; p++) {
            const int oidx = ((h * 4 + lvl) * 4 + p) * 2;
            const float ox = offaw[bq * 384 + oidx + 0];
            const float oy = offaw[bq * 384 + oidx + 1];
            const float x = (refx + ox / Wl) * Wl - 0.5f;
            const float y = (refy + oy / Hl) * Hl - 0.5f;
            const float x0 = floorf(x), y0 = floorf(y);
            float samp = 0.f;
            #pragma unroll
            for (int cq = 0; cq < 4; cq++) {
                const float xi = x0 + (float)(cq & 1);
                const float yi = y0 + (float)(cq >> 1);
                const float w = (1.f - fabsf(x - xi)) * (1.f - fabsf(y - yi));
                if (xi >= 0.f && xi < Wl && yi >= 0.f && yi < Hl && w != 0.f) {
                    const int ii = (int)yi * Wi + (int)xi;
                    samp += w * __bfloat162float(vbase[(size_t)ii * DM]);
                }
            }
            const float awp = __shfl_sync(0xffffffffu, aw, lvl * 4 + p);
            accv += awp * samp;
        }
    }
    outh[bq * DM + h * HD + lane] = __float2bfloat16(accv);
}

// ---------------- launch ----------------
extern "C" void kernel_launch(void* const* d_in, const int* in_sizes, int n_in,
                              void* d_out, int out_size)
{
    (void)in_sizes; (void)n_in; (void)out_size;
    const float* tgt   = (const float*)d_in[0];
    const float* mem   = (const float*)d_in[1];
    const float* refp  = (const float*)d_in[3];
    const float* ipw = (const float*)d_in[6],  *ipb = (const float*)d_in[7];
    const float* opw = (const float*)d_in[8],  *opb = (const float*)d_in[9];
    const float* n1g = (const float*)d_in[10], *n1b = (const float*)d_in[11];
    const float* n2g = (const float*)d_in[12], *n2b = (const float*)d_in[13];
    const float* n3g = (const float*)d_in[14], *n3b = (const float*)d_in[15];
    const float* sow = (const float*)d_in[16], *sob = (const float*)d_in[17];
    const float* aww = (const float*)d_in[18], *awb = (const float*)d_in[19];
    const float* vpw = (const float*)d_in[20], *vpb = (const float*)d_in[21];
    const float* oqw = (const float*)d_in[22], *oqb = (const float*)d_in[23];
    const float* l1w = (const float*)d_in[24], *l1b = (const float*)d_in[25];
    const float* l2w = (const float*)d_in[26], *l2b = (const float*)d_in[27];
    float* out = (float*)d_out;

    float *buf, *tgt1, *tgt2, *offaw, *soawb;
    cudaGetSymbolAddress((void**)&buf,   g_buf);
    cudaGetSymbolAddress((void**)&tgt1,  g_tgt1);
    cudaGetSymbolAddress((void**)&tgt2,  g_tgt2);
    cudaGetSymbolAddress((void**)&offaw, g_offaw);
    cudaGetSymbolAddress((void**)&soawb, g_soawb);

    __nv_bfloat16 *p_qkv, *p_sa, *p_tgt1, *p_val, *p_ca, *p_tgt2, *p_ffn1;
    __nv_bfloat16 *p_ipw, *p_opw, *p_vpw, *p_soaw, *p_oqw, *p_l1w, *p_l2w;
    cudaGetSymbolAddress((void**)&p_qkv,  b_qkv);
    cudaGetSymbolAddress((void**)&p_sa,   b_sa);
    cudaGetSymbolAddress((void**)&p_tgt1, b_tgt1);
    cudaGetSymbolAddress((void**)&p_val,  b_val);
    cudaGetSymbolAddress((void**)&p_ca,   b_ca);
    cudaGetSymbolAddress((void**)&p_tgt2, b_tgt2);
    cudaGetSymbolAddress((void**)&p_ffn1, b_ffn1);
    cudaGetSymbolAddress((void**)&p_ipw,  b_ipw);
    cudaGetSymbolAddress((void**)&p_opw,  b_opw);
    cudaGetSymbolAddress((void**)&p_vpw,  b_vpw);
    cudaGetSymbolAddress((void**)&p_soaw, b_soaw);
    cudaGetSymbolAddress((void**)&p_oqw,  b_oqw);
    cudaGetSymbolAddress((void**)&p_l1w,  b_l1w);
    cudaGetSymbolAddress((void**)&p_l2w,  b_l2w);

    const int SMEM1 = 2 * 2 * TILEB;   // 40960
    const int SMEM2 = 2 * 3 * TILEB;   // 61440
    cudaFuncSetAttribute(gemm_mma<1, false, false, 1, true,  true >, cudaFuncAttributeMaxDynamicSharedMemorySize, SMEM1);
    cudaFuncSetAttribute(gemm_mma<1, false, false, 1, true,  false>, cudaFuncAttributeMaxDynamicSharedMemorySize, SMEM1);
    cudaFuncSetAttribute(gemm_mma<1, false, true,  0, false, false>, cudaFuncAttributeMaxDynamicSharedMemorySize, SMEM1);
    cudaFuncSetAttribute(gemm_mma<1, false, false, 0, false, false>, cudaFuncAttributeMaxDynamicSharedMemorySize, SMEM1);
    cudaFuncSetAttribute(gemm_mma<2, true,  false, 1, false, false>, cudaFuncAttributeMaxDynamicSharedMemorySize, SMEM2);
    cudaFuncSetAttribute(gemm_mma<2, false, true,  0, false, false>, cudaFuncAttributeMaxDynamicSharedMemorySize, SMEM2);

    const int MT  = (BQ + 127) / 128;    // 57
    const int MTV = (BS + 127) / 128;    // 831

    cudaStream_t s2;
    cudaStreamCreateWithFlags(&s2, cudaStreamNonBlocking);
    cudaEvent_t evA, evB;
    cudaEventCreateWithFlags(&evA, cudaEventDisableTiming);
    cudaEventCreateWithFlags(&evB, cudaEventDisableTiming);

#define HL(p, n) (p), (p) + (n)

    // ---- all weight conversions + fused bias, ONE launch ----
    convert_all<<<(254048 + 255) / 256, 256>>>(
        ipw, opw, vpw, sow, aww, oqw, l1w, l2w, sob, awb,
        p_ipw, p_opw, p_vpw, p_soaw, p_oqw, p_l1w, p_l2w, soawb);

    // fork: value projection on s2
    cudaEventRecord(evA, 0);
    cudaStreamWaitEvent(s2, evA, 0);
    gemm_mma<1, false, false, 1, true, false><<<dim3(2, MTV), 256, SMEM1, s2>>>(
        mem, nullptr, nullptr, p_vpw, nullptr, vpb, nullptr, nullptr, p_val, nullptr, BS, DM, DM);
    cudaEventRecord(evB, s2);

    // main path
    // 1. QKV projection (AFP32, x1, bf16 out, Q pre-scaled by scale*log2e)
    gemm_mma<1, false, false, 1, true, true><<<dim3(6, MT), 256, SMEM1>>>(
        tgt, nullptr, nullptr, p_ipw, nullptr, ipb, nullptr, nullptr, p_qkv, nullptr, BQ, 768, DM);
    // 2. flash self-attention (no-max softmax)
    attn_mma<<<dim3((Q_ + 63) / 64, NH, B_), 128>>>(p_qkv, p_sa);
    // 3. out-proj + residual (x1), 4. LN1 (hi split)
    gemm_mma<1, false, true, 0, false, false><<<dim3(2, MT), 256, SMEM1>>>(
        nullptr, p_sa, nullptr, p_opw, nullptr, opb, tgt, buf, nullptr, nullptr, BQ, DM, DM);
    ln_kernel<1><<<BQ / 8, 256>>>(buf, n1g, n1b, tgt1, p_tgt1, nullptr);
    // 5+6. fused sampling offsets + attention-weight logits (N=384)
    gemm_mma<1, false, false, 0, false, false><<<dim3(3, MT), 256, SMEM1>>>(
        nullptr, p_tgt1, nullptr, p_soaw, nullptr, soawb, nullptr, offaw, nullptr, nullptr, BQ, 384, DM);

    // join: need value tensor before sampling
    cudaStreamWaitEvent((cudaStream_t)0, evB, 0);
    // 7. deformable sampling -> bf16 ca
    deform_kernel<<<(B_ * Q_ * NH * 32 + 255) / 256, 256>>>(offaw, p_val, refp, p_ca);
    // 8. output proj + residual (x1), 9. LN2 (hi split)
    gemm_mma<1, false, true, 0, false, false><<<dim3(2, MT), 256, SMEM1>>>(
        nullptr, p_ca, nullptr, p_oqw, nullptr, oqb, tgt1, buf, nullptr, nullptr, BQ, DM, DM);
    ln_kernel<1><<<BQ / 8, 256>>>(buf, n2g, n2b, tgt2, p_tgt2, nullptr);
    // 10. FFN up + relu (x2, hi out), 11. FFN down + residual (x2), 12. LN3 -> out
    gemm_mma<2, true, false, 1, false, false><<<dim3(8, MT), 256, SMEM2>>>(
        nullptr, p_tgt2, nullptr, HL(p_l1w, 1024 * 256), l1b, nullptr, nullptr, p_ffn1, nullptr, BQ, DFFN, DM);
    gemm_mma<2, false, true, 0, false, false><<<dim3(2, MT), 256, SMEM2>>>(
        nullptr, p_ffn1, nullptr, HL(p_l2w, 256 * 1024), l2b, tgt2, buf, nullptr, nullptr, BQ, DM, DFFN);
    ln_kernel<0><<<BQ / 8, 256>>>(buf, n3g, n3b, out, nullptr, nullptr);
#undef HL
}

// round 15
// speedup vs baseline: 3.7275x; 1.0074x over previous
#include <cuda_runtime.h>
#include <cuda_bf16.h>
#include <cuda_fp16.h>
#include <math.h>
#include <stdint.h>

// ---------------- problem constants ----------------
#define B_      8
#define Q_      900
#define BQ      7200          // B*Q
#define DM      256
#define STOT    13294
#define BS      106352        // B*STOT
#define NH      8
#define HD      32
#define DFFN    1024

// ---------------- fp32 scratch ----------------
__device__ float g_buf  [BQ * DM];
__device__ float g_tgt1 [BQ * DM];
__device__ float g_tgt2 [BQ * DM];
__device__ float g_offaw[BQ * 384];
__device__ float g_soawb[384];

// ---------------- bf16 scratch ----------------
__device__ __nv_bfloat16 b_qkv [BQ * 768];       // Q,K bf16; V stored as fp16 bits
__device__ __nv_bfloat16 b_sa  [BQ * DM];
__device__ __nv_bfloat16 b_tgt1[BQ * DM];
__device__ __nv_bfloat16 b_val [(size_t)BS * DM];
__device__ __nv_bfloat16 b_ca  [BQ * DM];
__device__ __nv_bfloat16 b_tgt2[BQ * DM];
__device__ __nv_bfloat16 b_ffn1[BQ * DFFN];
__device__ __nv_bfloat16 b_ipw [768 * 256];
__device__ __nv_bfloat16 b_opw [256 * 256];
__device__ __nv_bfloat16 b_vpw [256 * 256];
__device__ __nv_bfloat16 b_soaw[384 * 256];      // sow (256 rows) ++ aww (128 rows)
__device__ __nv_bfloat16 b_oqw [256 * 256];
__device__ __nv_bfloat16 b_l1w [2][1024 * 256];
__device__ __nv_bfloat16 b_l2w [2][256 * 1024];

// ---------------- helpers ----------------
__device__ __forceinline__ uint32_t smem_u32(const void* p) {
    uint32_t a;
    asm("{ .reg .u64 t; cvta.to.shared.u64 t, %1; cvt.u32.u64 %0, t; }" : "=r"(a) : "l"(p));
    return a;
}
__device__ __forceinline__ void ldsm4(uint32_t* r, uint32_t addr) {
    asm volatile("ldmatrix.sync.aligned.m8n8.x4.shared.b16 {%0,%1,%2,%3}, [%4];"
        : "=r"(r[0]), "=r"(r[1]), "=r"(r[2]), "=r"(r[3]) : "r"(addr));
}
__device__ __forceinline__ void ldsm4t(uint32_t* r, uint32_t addr) {
    asm volatile("ldmatrix.sync.aligned.m8n8.x4.trans.shared.b16 {%0,%1,%2,%3}, [%4];"
        : "=r"(r[0]), "=r"(r[1]), "=r"(r[2]), "=r"(r[3]) : "r"(addr));
}
__device__ __forceinline__ void mma16816(float* c, const uint32_t* a, const uint32_t* b) {
    asm volatile("mma.sync.aligned.m16n8k16.row.col.f32.bf16.bf16.f32 "
        "{%0,%1,%2,%3}, {%4,%5,%6,%7}, {%8,%9}, {%0,%1,%2,%3};"
        : "+f"(c[0]), "+f"(c[1]), "+f"(c[2]), "+f"(c[3])
        : "r"(a[0]), "r"(a[1]), "r"(a[2]), "r"(a[3]), "r"(b[0]), "r"(b[1]));
}
__device__ __forceinline__ void mma16816h(float* c, const uint32_t* a, const uint32_t* b) {
    asm volatile("mma.sync.aligned.m16n8k16.row.col.f32.f16.f16.f32 "
        "{%0,%1,%2,%3}, {%4,%5,%6,%7}, {%8,%9}, {%0,%1,%2,%3};"
        : "+f"(c[0]), "+f"(c[1]), "+f"(c[2]), "+f"(c[3])
        : "r"(a[0]), "r"(a[1]), "r"(a[2]), "r"(a[3]), "r"(b[0]), "r"(b[1]));
}
__device__ __forceinline__ void cpasync16(uint32_t dst, const void* src, int sz) {
    asm volatile("cp.async.cg.shared.global [%0], [%1], 16, %2;" :: "r"(dst), "l"(src), "r"(sz));
}
__device__ __forceinline__ void split2(float a, float b, __nv_bfloat162& h, __nv_bfloat162& l) {
    h = __floats2bfloat162_rn(a, b);
    float2 hf = __bfloat1622float2(h);
    l = __floats2bfloat162_rn(a - hf.x, b - hf.y);
}
__device__ __forceinline__ uint32_t pack_f16(float a, float b) {
    __half2 h = __floats2half2_rn(a, b);
    return *reinterpret_cast<uint32_t*>(&h);
}
__device__ __forceinline__ uint32_t ex2_h2(uint32_t x) {
    uint32_t y;
    asm("ex2.approx.f16x2 %0, %1;" : "=r"(y) : "r"(x));
    return y;
}

// ---------------- one-shot weight conversion (all weights + fused bias) ----------------
__global__ __launch_bounds__(256)
void convert_all(const float* __restrict__ ipw, const float* __restrict__ opw,
                 const float* __restrict__ vpw, const float* __restrict__ sow,
                 const float* __restrict__ aww, const float* __restrict__ oqw,
                 const float* __restrict__ l1w, const float* __restrict__ l2w,
                 const float* __restrict__ sob, const float* __restrict__ awb,
                 __nv_bfloat16* __restrict__ d_ipw, __nv_bfloat16* __restrict__ d_opw,
                 __nv_bfloat16* __restrict__ d_vpw, __nv_bfloat16* __restrict__ d_soaw,
                 __nv_bfloat16* __restrict__ d_oqw, __nv_bfloat16* __restrict__ d_l1w,
                 __nv_bfloat16* __restrict__ d_l2w, float* __restrict__ soawb)
{
    const int i = blockIdx.x * 256 + threadIdx.x;
    const float* src;
    __nv_bfloat16* hi;
    __nv_bfloat16* lo = nullptr;
    int base;
    if (i < 49152)       { src = ipw; hi = d_ipw; base = 0; }
    else if (i < 65536)  { src = opw; hi = d_opw; base = 49152; }
    else if (i < 81920)  { src = vpw; hi = d_vpw; base = 65536; }
    else if (i < 98304)  { src = sow; hi = d_soaw; base = 81920; }
    else if (i < 106496) { src = aww; hi = d_soaw + 65536; base = 98304; }
    else if (i < 122880) { src = oqw; hi = d_oqw; base = 106496; }
    else if (i < 188416) { src = l1w; hi = d_l1w; lo = d_l1w + 262144; base = 122880; }
    else if (i < 253952) { src = l2w; hi = d_l2w; lo = d_l2w + 262144; base = 188416; }
    else if (i < 254048) {
        const int j = i - 253952;
        float4 v = (j < 64) ? ((const float4*)sob)[j] : ((const float4*)awb)[j - 64];
        ((float4*)soawb)[j] = v;
        return;
    } else return;

    const int j = i - base;
    float4 v = ((const float4*)src)[j];
    if (lo == nullptr) {
        ((__nv_bfloat162*)hi)[j * 2 + 0] = __floats2bfloat162_rn(v.x, v.y);
        ((__nv_bfloat162*)hi)[j * 2 + 1] = __floats2bfloat162_rn(v.z, v.w);
    } else {
        __nv_bfloat162 h0, l0, h1, l1;
        split2(v.x, v.y, h0, l0);
        split2(v.z, v.w, h1, l1);
        ((__nv_bfloat162*)hi)[j * 2 + 0] = h0;
        ((__nv_bfloat162*)hi)[j * 2 + 1] = h1;
        ((__nv_bfloat162*)lo)[j * 2 + 0] = l0;
        ((__nv_bfloat162*)lo)[j * 2 + 1] = l1;
    }
}

// ---------------- bf16 mma.sync GEMM ----------------
// NPASS: 1 = Ah*Wh; 2 = Ah*Wh + Ah*Wl; 3 = Ah*Wh + Al*Wh + Ah*Wl.
// OUT: 0 = fp32 C, 1 = bf16 Ch, 2 = bf16 Ch+Cl.
// AFP32: A read fp32 with register-pipelined inline conversion.
// QS (QKV only): cols<256 scaled by scale*log2e (Q); cols>=512 stored f16 (V).
#define TILEB 10240

template<int NPASS, bool RELU, bool RESID, int OUT, bool AFP32, bool QS>
__global__ __launch_bounds__(256)
void gemm_mma(const float* __restrict__ Af,
              const __nv_bfloat16* __restrict__ Ah, const __nv_bfloat16* __restrict__ Al,
              const __nv_bfloat16* __restrict__ Wh, const __nv_bfloat16* __restrict__ Wl,
              const float* __restrict__ bias, const float* __restrict__ R,
              float* __restrict__ C, __nv_bfloat16* __restrict__ Ch,
              __nv_bfloat16* __restrict__ Cl, int M, int N, int K)
{
    constexpr int NTIL = (NPASS == 3) ? 4 : (NPASS == 2 ? 3 : 2);
    constexpr int STGB = NTIL * TILEB;
    constexpr int WOFF = (NPASS == 3 ? 2 : 1) * TILEB;

    extern __shared__ char smem[];
    const uint32_t sb = smem_u32(smem);
    const int tid = threadIdx.x, lane = tid & 31, wid = tid >> 5;
    const int am = (wid & 3) * 32;
    const int bn = (wid >> 2) * 64;
    const int m0 = blockIdx.y * 128, n0 = blockIdx.x * 128;

    float c[2][8][4] = {};

    float4 aReg[2][2];
    const int pr0 = tid >> 2, pq = tid & 3;

#define LDG_A(ch) do {                                                            \
    const int kb_ = (ch) * 32;                                                    \
    _Pragma("unroll")                                                             \
    for (int u_ = 0; u_ < 2; u_++) {                                              \
        int r_ = pr0 + u_ * 64;                                                   \
        int row_ = m0 + r_; if (row_ >= M) row_ = M - 1;                          \
        const float* p_ = Af + (size_t)row_ * K + kb_ + pq * 8;                   \
        aReg[u_][0] = *(const float4*)p_;                                         \
        aReg[u_][1] = *(const float4*)(p_ + 4);                                   \
    }                                                                             \
} while (0)

#define STS_A(st) do {                                                            \
    _Pragma("unroll")                                                             \
    for (int u_ = 0; u_ < 2; u_++) {                                              \
        int r_ = pr0 + u_ * 64;                                                   \
        uint4 w4_;                                                                \
        __nv_bfloat162 t0_ = __floats2bfloat162_rn(aReg[u_][0].x, aReg[u_][0].y); \
        __nv_bfloat162 t1_ = __floats2bfloat162_rn(aReg[u_][0].z, aReg[u_][0].w); \
        __nv_bfloat162 t2_ = __floats2bfloat162_rn(aReg[u_][1].x, aReg[u_][1].y); \
        __nv_bfloat162 t3_ = __floats2bfloat162_rn(aReg[u_][1].z, aReg[u_][1].w); \
        w4_.x = *reinterpret_cast<uint32_t*>(&t0_);                               \
        w4_.y = *reinterpret_cast<uint32_t*>(&t1_);                               \
        w4_.z = *reinterpret_cast<uint32_t*>(&t2_);                               \
        w4_.w = *reinterpret_cast<uint32_t*>(&t3_);                               \
        *(uint4*)(smem + (st) * STGB + r_ * 80 + pq * 16) = w4_;                  \
    }                                                                             \
} while (0)

#define ISSUE_W(st, ch) do {                                                      \
    const int kb_ = (ch) * 32;                                                    \
    const uint32_t so_ = sb + (st) * STGB;                                        \
    _Pragma("unroll")                                                             \
    for (int cix = tid; cix < (NPASS >= 2 ? 1024 : 512); cix += 256) {            \
        int t_ = cix >> 9, idx_ = cix & 511, r_ = idx_ >> 2, q_ = idx_ & 3;       \
        const __nv_bfloat16* base_ = t_ ? Wl : Wh;                                \
        cpasync16(so_ + WOFF + t_ * TILEB + r_ * 80 + q_ * 16,                    \
                  base_ + (size_t)(n0 + r_) * K + kb_ + q_ * 8, 16);              \
    }                                                                             \
    asm volatile("cp.async.commit_group;" ::: "memory");                          \
} while (0)

#define ISSUE_AB(st, ch) do {                                                     \
    const int kb_ = (ch) * 32;                                                    \
    const uint32_t so_ = sb + (st) * STGB;                                        \
    _Pragma("unroll")                                                             \
    for (int cix = tid; cix < NTIL * 512; cix += 256) {                           \
        int t_ = cix >> 9, idx_ = cix & 511, r_ = idx_ >> 2, q_ = idx_ & 3;       \
        uint32_t d_ = so_ + t_ * TILEB + r_ * 80 + q_ * 16;                       \
        const __nv_bfloat16* base_;                                               \
        bool isA_;                                                                \
        if (NPASS == 1) { isA_ = (t_ == 0); base_ = isA_ ? Ah : Wh; }             \
        else if (NPASS == 2) { isA_ = (t_ == 0);                                  \
               base_ = (t_ == 0 ? Ah : t_ == 1 ? Wh : Wl); }                      \
        else { isA_ = (t_ < 2);                                                   \
               base_ = (t_ == 0 ? Ah : t_ == 1 ? Al : t_ == 2 ? Wh : Wl); }       \
        if (isA_) cpasync16(d_, base_ + (size_t)(m0 + r_) * K + kb_ + q_ * 8,     \
                            (m0 + r_) < M ? 16 : 0);                              \
        else      cpasync16(d_, base_ + (size_t)(n0 + r_) * K + kb_ + q_ * 8, 16);\
    }                                                                             \
    asm volatile("cp.async.commit_group;" ::: "memory");                          \
} while (0)

    const int nCh = K >> 5;
    if (AFP32) {
        LDG_A(0);
        ISSUE_W(0, 0);
    } else {
        ISSUE_AB(0, 0);
    }

    const int lar = lane & 15;
    const int lac = (lane >> 4) * 16;
    const int lbr = (lane & 7) + ((lane >> 4) & 1) * 8;
    const int lbc = ((lane >> 3) & 1) * 16;

    for (int ch = 0; ch < nCh; ch++) {
        if (AFP32) {
            STS_A(ch & 1);
            if (ch + 1 < nCh) {
                LDG_A(ch + 1);
                ISSUE_W((ch + 1) & 1, ch + 1);
                asm volatile("cp.async.wait_group 1;" ::: "memory");
            } else {
                asm volatile("cp.async.wait_group 0;" ::: "memory");
            }
        } else {
            if (ch + 1 < nCh) {
                ISSUE_AB((ch + 1) & 1, ch + 1);
                asm volatile("cp.async.wait_group 1;" ::: "memory");
            } else {
                asm volatile("cp.async.wait_group 0;" ::: "memory");
            }
        }
        __syncthreads();

        const uint32_t so = sb + (ch & 1) * STGB;
        #pragma unroll
        for (int ks = 0; ks < 2; ks++) {
            uint32_t ah[2][4], al[2][4], bb[4][4];
            const uint32_t acol = ks * 32 + lac;
            const uint32_t bcol = ks * 32 + lbc;
            ldsm4(ah[0], so + (am + lar) * 80 + acol);
            ldsm4(ah[1], so + (am + 16 + lar) * 80 + acol);
            if (NPASS == 3) {
                ldsm4(al[0], so + TILEB + (am + lar) * 80 + acol);
                ldsm4(al[1], so + TILEB + (am + 16 + lar) * 80 + acol);
            }
            #pragma unroll
            for (int p = 0; p < 4; p++)
                ldsm4(bb[p], so + WOFF + (bn + p * 16 + lbr) * 80 + bcol);
            #pragma unroll
            for (int fm = 0; fm < 2; fm++)
                #pragma unroll
                for (int p = 0; p < 4; p++) {
                    mma16816(c[fm][2 * p],     ah[fm], bb[p]);
                    mma16816(c[fm][2 * p + 1], ah[fm], bb[p] + 2);
                    if (NPASS == 3) {
                        mma16816(c[fm][2 * p],     al[fm], bb[p]);
                        mma16816(c[fm][2 * p + 1], al[fm], bb[p] + 2);
                    }
                }
            if (NPASS >= 2) {
                #pragma unroll
                for (int p = 0; p < 4; p++)
                    ldsm4(bb[p], so + WOFF + TILEB + (bn + p * 16 + lbr) * 80 + bcol);
                #pragma unroll
                for (int fm = 0; fm < 2; fm++)
                    #pragma unroll
                    for (int p = 0; p < 4; p++) {
                        mma16816(c[fm][2 * p],     ah[fm], bb[p]);
                        mma16816(c[fm][2 * p + 1], ah[fm], bb[p] + 2);
                    }
            }
        }
        __syncthreads();
    }
#undef ISSUE_AB
#undef ISSUE_W
#undef STS_A
#undef LDG_A

    // epilogue
    const int r0 = m0 + am + (lane >> 2);
    const int colb = n0 + bn + (lane & 3) * 2;
    #pragma unroll
    for (int fm = 0; fm < 2; fm++) {
        #pragma unroll
        for (int p = 0; p < 8; p++) {
            const int col = colb + p * 8;
            const float2 bv = *(const float2*)(bias + col);
            #pragma unroll
            for (int hh = 0; hh < 2; hh++) {
                const int row = r0 + fm * 16 + hh * 8;
                if (row < M) {
                    float o0 = c[fm][p][hh * 2 + 0] + bv.x;
                    float o1 = c[fm][p][hh * 2 + 1] + bv.y;
                    if (QS && col < 256) {
                        const float qsf = 0.17677669529663687f * 1.4426950408889634f;
                        o0 *= qsf; o1 *= qsf;
                    }
                    if (RESID) {
                        float2 rv = *(const float2*)(R + (size_t)row * N + col);
                        o0 += rv.x; o1 += rv.y;
                    }
                    if (RELU) { o0 = fmaxf(o0, 0.f); o1 = fmaxf(o1, 0.f); }
                    if (OUT == 0) {
                        *(float2*)(C + (size_t)row * N + col) = make_float2(o0, o1);
                    } else if (OUT == 1) {
                        if (QS && col >= 512) {
                            // V stored as fp16 bits for f16 PV MMA in attention
                            *(uint32_t*)(Ch + (size_t)row * N + col) = pack_f16(o0, o1);
                        } else {
                            *(__nv_bfloat162*)(Ch + (size_t)row * N + col) = __floats2bfloat162_rn(o0, o1);
                        }
                    } else {
                        __nv_bfloat162 h, l;
                        split2(o0, o1, h, l);
                        *(__nv_bfloat162*)(Ch + (size_t)row * N + col) = h;
                        *(__nv_bfloat162*)(Cl + (size_t)row * N + col) = l;
                    }
                }
            }
        }
    }
}

// ---------------- flash self-attention ----------------
// QK in bf16 mma; P exponentiated in f16x2 (ex2.approx.f16x2) and used directly
// as f16 A-fragment; V stored f16; Sexp via ones-column f16 MMA (csum).
// No-max softmax (scores O(1), masked with -1e4 -> exp2 underflows to 0).
// 64 Q-rows per CTA, 128 threads (4 warps x 16 rows).
#define KVB 5120

__global__ __launch_bounds__(128)
void attn_mma(const __nv_bfloat16* __restrict__ qkv, __nv_bfloat16* __restrict__ sa)
{
    __shared__ __nv_bfloat16 Qs[64 * 40];
    __shared__ __nv_bfloat16 Ks[2][64 * 40];
    __shared__ __nv_bfloat16 Vs[2][64 * 40];
    const int b = blockIdx.z, h = blockIdx.y, q0 = blockIdx.x * 64;
    const int tid = threadIdx.x, lane = tid & 31, wid = tid >> 5;
    const uint32_t sQ = smem_u32(Qs), sK = smem_u32(Ks), sV = smem_u32(Vs);

#define ISSUE_KV(t, bufi) do {                                                    \
    const int kv0_ = (t) * 64;                                                    \
    _Pragma("unroll")                                                             \
    for (int i_ = tid; i_ < 512; i_ += 128) {                                     \
        int te_ = i_ >> 8, idx_ = i_ & 255, r_ = idx_ >> 2, cc_ = idx_ & 3;       \
        const __nv_bfloat16* src_ = qkv + (size_t)(b * Q_ + kv0_ + r_) * 768      \
                                    + 256 + te_ * 256 + h * HD + cc_ * 8;         \
        cpasync16((te_ ? sV : sK) + (bufi) * KVB + r_ * 80 + cc_ * 16, src_,      \
                  (kv0_ + r_) < Q_ ? 16 : 0);                                     \
    }                                                                             \
    asm volatile("cp.async.commit_group;" ::: "memory");                          \
} while (0)

    #pragma unroll
    for (int i = tid; i < 256; i += 128) {
        int r = i >> 2, cc = i & 3;
        const __nv_bfloat16* src = qkv + (size_t)(b * Q_ + q0 + r) * 768 + h * HD + cc * 8;
        cpasync16(sQ + r * 80 + cc * 16, src, (q0 + r) < Q_ ? 16 : 0);
    }
    asm volatile("cp.async.commit_group;" ::: "memory");
    ISSUE_KV(0, 0);
    asm volatile("cp.async.wait_group 1;" ::: "memory");
    __syncthreads();

    const int r8 = (lane & 7) + ((lane >> 3) & 1) * 8;
    const int c16 = (lane >> 4) * 16;

    uint32_t qf[2][4];
    {
        uint32_t qa = sQ + (wid * 16 + r8) * 80 + c16;
        ldsm4(qf[0], qa);
        ldsm4(qf[1], qa + 32);
    }

    float csum[4] = {};          // row-sum accumulator (ones-MMA)
    float o[4][4] = {};
    const uint32_t ones2[2] = {0x3C003C00u, 0x3C003C00u};   // f16 1.0 x4

    for (int t = 0; t < 15; t++) {
        const int kv0 = t * 64;
        if (t + 1 < 15) {
            ISSUE_KV(t + 1, (t + 1) & 1);
            asm volatile("cp.async.wait_group 1;" ::: "memory");
        } else {
            asm volatile("cp.async.wait_group 0;" ::: "memory");
        }
        __syncthreads();

        const uint32_t sKb = sK + (t & 1) * KVB;
        const uint32_t sVb = sV + (t & 1) * KVB;

        float c[8][4] = {};
        #pragma unroll
        for (int ks = 0; ks < 2; ks++) {
            #pragma unroll
            for (int p = 0; p < 4; p++) {
                uint32_t kf[4];
                ldsm4(kf, sKb + (p * 16 + r8) * 80 + c16 + ks * 32);
                uint32_t b0[2] = {kf[0], kf[2]}, b1[2] = {kf[1], kf[3]};
                mma16816(c[2 * p],     qf[ks], b0);
                mma16816(c[2 * p + 1], qf[ks], b1);
            }
        }
        if (kv0 + 64 > Q_) {
            #pragma unroll
            for (int p8 = 0; p8 < 8; p8++)
                #pragma unroll
                for (int j = 0; j < 2; j++)
                    if (kv0 + p8 * 8 + 2 * (lane & 3) + j >= Q_) {
                        c[p8][j] = -1e4f;     // finite in f16; exp2 underflows to 0
                        c[p8][2 + j] = -1e4f;
                    }
        }
        // P = exp2(scores) computed in f16x2, directly forming the A fragment
        #pragma unroll
        for (int ts = 0; ts < 4; ts++) {
            uint32_t af[4];
            af[0] = ex2_h2(pack_f16(c[2 * ts][0], c[2 * ts][1]));
            af[1] = ex2_h2(pack_f16(c[2 * ts][2], c[2 * ts][3]));
            af[2] = ex2_h2(pack_f16(c[2 * ts + 1][0], c[2 * ts + 1][1]));
            af[3] = ex2_h2(pack_f16(c[2 * ts + 1][2], c[2 * ts + 1][3]));
            mma16816h(csum, af, ones2);      // row sums of P
            #pragma unroll
            for (int np = 0; np < 2; np++) {
                uint32_t vf[4];
                ldsm4t(vf, sVb + (ts * 16 + r8) * 80 + np * 32 + c16);
                uint32_t b0[2] = {vf[0], vf[1]}, b1[2] = {vf[2], vf[3]};
                mma16816h(o[2 * np],     af, b0);
                mma16816h(o[2 * np + 1], af, b1);
            }
        }
        __syncthreads();
    }
#undef ISSUE_KV

    const float inv0 = 1.f / csum[0], inv1 = 1.f / csum[2];
    const int gr0 = q0 + wid * 16 + (lane >> 2);
    #pragma unroll
    for (int nt = 0; nt < 4; nt++) {
        const int col = h * HD + nt * 8 + 2 * (lane & 3);
        if (gr0 < Q_)
            *(__nv_bfloat162*)(sa + (size_t)(b * Q_ + gr0) * DM + col)
                = __floats2bfloat162_rn(o[nt][0] * inv0, o[nt][1] * inv0);
        if (gr0 + 8 < Q_)
            *(__nv_bfloat162*)(sa + (size_t)(b * Q_ + gr0 + 8) * DM + col)
                = __floats2bfloat162_rn(o[nt][2] * inv1, o[nt][3] * inv1);
    }
}

// ---------------- LayerNorm: warp per row, 8 rows/CTA ----------------
template<int OSPLIT>
__global__ __launch_bounds__(256)
void ln_kernel(const float* __restrict__ in, const float* __restrict__ g,
               const float* __restrict__ bta, float* __restrict__ out,
               __nv_bfloat16* __restrict__ oh, __nv_bfloat16* __restrict__ ol)
{
    const int warp = threadIdx.x >> 5, lane = threadIdx.x & 31;
    const int row = blockIdx.x * 8 + warp;
    const float4* ip = (const float4*)(in + (size_t)row * DM);
    float4 v0 = ip[lane], v1 = ip[lane + 32];

    float s = ((v0.x + v0.y) + (v0.z + v0.w)) + ((v1.x + v1.y) + (v1.z + v1.w));
    #pragma unroll
    for (int o = 16; o > 0; o >>= 1) s += __shfl_xor_sync(0xffffffffu, s, o);
    const float mu = s * (1.f / 256.f);

    v0.x -= mu; v0.y -= mu; v0.z -= mu; v0.w -= mu;
    v1.x -= mu; v1.y -= mu; v1.z -= mu; v1.w -= mu;
    float vs = ((v0.x * v0.x + v0.y * v0.y) + (v0.z * v0.z + v0.w * v0.w))
             + ((v1.x * v1.x + v1.y * v1.y) + (v1.z * v1.z + v1.w * v1.w));
    #pragma unroll
    for (int o = 16; o > 0; o >>= 1) vs += __shfl_xor_sync(0xffffffffu, vs, o);
    const float rs = rsqrtf(vs * (1.f / 256.f) + 1e-5f);

    const float4 g0 = ((const float4*)g)[lane],  g1 = ((const float4*)g)[lane + 32];
    const float4 b0 = ((const float4*)bta)[lane], b1 = ((const float4*)bta)[lane + 32];
    float4 y0, y1;
    y0.x = v0.x * rs * g0.x + b0.x; y0.y = v0.y * rs * g0.y + b0.y;
    y0.z = v0.z * rs * g0.z + b0.z; y0.w = v0.w * rs * g0.w + b0.w;
    y1.x = v1.x * rs * g1.x + b1.x; y1.y = v1.y * rs * g1.y + b1.y;
    y1.z = v1.z * rs * g1.z + b1.z; y1.w = v1.w * rs * g1.w + b1.w;

    float4* op = (float4*)(out + (size_t)row * DM);
    op[lane] = y0; op[lane + 32] = y1;

    if (OSPLIT >= 1) {
        const size_t i0 = (size_t)row * DM + lane * 4;
        const size_t i1 = i0 + 128;
        if (OSPLIT == 1) {
            *(__nv_bfloat162*)(oh + i0)     = __floats2bfloat162_rn(y0.x, y0.y);
            *(__nv_bfloat162*)(oh + i0 + 2) = __floats2bfloat162_rn(y0.z, y0.w);
            *(__nv_bfloat162*)(oh + i1)     = __floats2bfloat162_rn(y1.x, y1.y);
            *(__nv_bfloat162*)(oh + i1 + 2) = __floats2bfloat162_rn(y1.z, y1.w);
        } else {
            __nv_bfloat162 h, l;
            split2(y0.x, y0.y, h, l);
            *(__nv_bfloat162*)(oh + i0) = h;     *(__nv_bfloat162*)(ol + i0) = l;
            split2(y0.z, y0.w, h, l);
            *(__nv_bfloat162*)(oh + i0 + 2) = h; *(__nv_bfloat162*)(ol + i0 + 2) = l;
            split2(y1.x, y1.y, h, l);
            *(__nv_bfloat162*)(oh + i1) = h;     *(__nv_bfloat162*)(ol + i1) = l;
            split2(y1.z, y1.w, h, l);
            *(__nv_bfloat162*)(oh + i1 + 2) = h; *(__nv_bfloat162*)(ol + i1 + 2) = l;
        }
    }
}

// ---------------- deformable sampling + weight softmax ----------------
__global__ __launch_bounds__(256)
void deform_kernel(const float* __restrict__ offaw,
                   const __nv_bfloat16* __restrict__ value, const float* __restrict__ refp,
                   __nv_bfloat16* __restrict__ outh)
{
    const int gw = (blockIdx.x * blockDim.x + threadIdx.x) >> 5;
    const int lane = threadIdx.x & 31;
    if (gw >= B_ * Q_ * NH) return;
    const int h = gw & 7;
    const int q = (gw >> 3) % Q_;
    const int b = gw / (NH * Q_);
    const size_t bq = (size_t)b * Q_ + q;

    float logit = (lane < 16) ? offaw[bq * 384 + 256 + h * 16 + lane] : -1e30f;
    float mx = logit;
    #pragma unroll
    for (int o = 16; o > 0; o >>= 1) mx = fmaxf(mx, __shfl_xor_sync(0xffffffffu, mx, o));
    float e = (lane < 16) ? __expf(logit - mx) : 0.f;
    float se = e;
    #pragma unroll
    for (int o = 16; o > 0; o >>= 1) se += __shfl_xor_sync(0xffffffffu, se, o);
    const float aw = e / se;

    const int HWl[4][2] = {{100,100},{50,50},{25,25},{13,13}};
    const int ST[4]     = {0, 10000, 12500, 13125};

    float accv = 0.f;
    #pragma unroll
    for (int lvl = 0; lvl < 4; lvl++) {
        const int Hi = HWl[lvl][0], Wi = HWl[lvl][1];
        const float Hl = (float)Hi, Wl = (float)Wi;
        const float refx = refp[(bq * 4 + lvl) * 2 + 0];
        const float refy = refp[(bq * 4 + lvl) * 2 + 1];
        const __nv_bfloat16* vbase = value + ((size_t)b * STOT + ST[lvl]) * DM + h * HD + lane;
        #pragma unroll
        for (int p = 0; p < 4; p++) {
            const int oidx = ((h * 4 + lvl) * 4 + p) * 2;
            const float ox = offaw[bq * 384 + oidx + 0];
            const float oy = offaw[bq * 384 + oidx + 1];
            const float x = (refx + ox / Wl) * Wl - 0.5f;
            const float y = (refy + oy / Hl) * Hl - 0.5f;
            const float x0 = floorf(x), y0 = floorf(y);
            float samp = 0.f;
            #pragma unroll
            for (int cq = 0; cq < 4; cq++) {
                const float xi = x0 + (float)(cq & 1);
                const float yi = y0 + (float)(cq >> 1);
                const float w = (1.f - fabsf(x - xi)) * (1.f - fabsf(y - yi));
                if (xi >= 0.f && xi < Wl && yi >= 0.f && yi < Hl && w != 0.f) {
                    const int ii = (int)yi * Wi + (int)xi;
                    samp += w * __bfloat162float(vbase[(size_t)ii * DM]);
                }
            }
            const float awp = __shfl_sync(0xffffffffu, aw, lvl * 4 + p);
            accv += awp * samp;
        }
    }
    outh[bq * DM + h * HD + lane] = __float2bfloat16(accv);
}

// ---------------- launch ----------------
extern "C" void kernel_launch(void* const* d_in, const int* in_sizes, int n_in,
                              void* d_out, int out_size)
{
    (void)in_sizes; (void)n_in; (void)out_size;
    const float* tgt   = (const float*)d_in[0];
    const float* mem   = (const float*)d_in[1];
    const float* refp  = (const float*)d_in[3];
    const float* ipw = (const float*)d_in[6],  *ipb = (const float*)d_in[7];
    const float* opw = (const float*)d_in[8],  *opb = (const float*)d_in[9];
    const float* n1g = (const float*)d_in[10], *n1b = (const float*)d_in[11];
    const float* n2g = (const float*)d_in[12], *n2b = (const float*)d_in[13];
    const float* n3g = (const float*)d_in[14], *n3b = (const float*)d_in[15];
    const float* sow = (const float*)d_in[16], *sob = (const float*)d_in[17];
    const float* aww = (const float*)d_in[18], *awb = (const float*)d_in[19];
    const float* vpw = (const float*)d_in[20], *vpb = (const float*)d_in[21];
    const float* oqw = (const float*)d_in[22], *oqb = (const float*)d_in[23];
    const float* l1w = (const float*)d_in[24], *l1b = (const float*)d_in[25];
    const float* l2w = (const float*)d_in[26], *l2b = (const float*)d_in[27];
    float* out = (float*)d_out;

    float *buf, *tgt1, *tgt2, *offaw, *soawb;
    cudaGetSymbolAddress((void**)&buf,   g_buf);
    cudaGetSymbolAddress((void**)&tgt1,  g_tgt1);
    cudaGetSymbolAddress((void**)&tgt2,  g_tgt2);
    cudaGetSymbolAddress((void**)&offaw, g_offaw);
    cudaGetSymbolAddress((void**)&soawb, g_soawb);

    __nv_bfloat16 *p_qkv, *p_sa, *p_tgt1, *p_val, *p_ca, *p_tgt2, *p_ffn1;
    __nv_bfloat16 *p_ipw, *p_opw, *p_vpw, *p_soaw, *p_oqw, *p_l1w, *p_l2w;
    cudaGetSymbolAddress((void**)&p_qkv,  b_qkv);
    cudaGetSymbolAddress((void**)&p_sa,   b_sa);
    cudaGetSymbolAddress((void**)&p_tgt1, b_tgt1);
    cudaGetSymbolAddress((void**)&p_val,  b_val);
    cudaGetSymbolAddress((void**)&p_ca,   b_ca);
    cudaGetSymbolAddress((void**)&p_tgt2, b_tgt2);
    cudaGetSymbolAddress((void**)&p_ffn1, b_ffn1);
    cudaGetSymbolAddress((void**)&p_ipw,  b_ipw);
    cudaGetSymbolAddress((void**)&p_opw,  b_opw);
    cudaGetSymbolAddress((void**)&p_vpw,  b_vpw);
    cudaGetSymbolAddress((void**)&p_soaw, b_soaw);
    cudaGetSymbolAddress((void**)&p_oqw,  b_oqw);
    cudaGetSymbolAddress((void**)&p_l1w,  b_l1w);
    cudaGetSymbolAddress((void**)&p_l2w,  b_l2w);

    const int SMEM1 = 2 * 2 * TILEB;   // 40960
    const int SMEM2 = 2 * 3 * TILEB;   // 61440
    cudaFuncSetAttribute(gemm_mma<1, false, false, 1, true,  true >, cudaFuncAttributeMaxDynamicSharedMemorySize, SMEM1);
    cudaFuncSetAttribute(gemm_mma<1, false, false, 1, true,  false>, cudaFuncAttributeMaxDynamicSharedMemorySize, SMEM1);
    cudaFuncSetAttribute(gemm_mma<1, false, true,  0, false, false>, cudaFuncAttributeMaxDynamicSharedMemorySize, SMEM1);
    cudaFuncSetAttribute(gemm_mma<1, false, false, 0, false, false>, cudaFuncAttributeMaxDynamicSharedMemorySize, SMEM1);
    cudaFuncSetAttribute(gemm_mma<2, true,  false, 1, false, false>, cudaFuncAttributeMaxDynamicSharedMemorySize, SMEM2);
    cudaFuncSetAttribute(gemm_mma<2, false, true,  0, false, false>, cudaFuncAttributeMaxDynamicSharedMemorySize, SMEM2);

    const int MT  = (BQ + 127) / 128;    // 57
    const int MTV = (BS + 127) / 128;    // 831

    cudaStream_t s2;
    cudaStreamCreateWithFlags(&s2, cudaStreamNonBlocking);
    cudaEvent_t evA, evB;
    cudaEventCreateWithFlags(&evA, cudaEventDisableTiming);
    cudaEventCreateWithFlags(&evB, cudaEventDisableTiming);

#define HL(p, n) (p), (p) + (n)

    // ---- all weight conversions + fused bias, ONE launch ----
    convert_all<<<(254048 + 255) / 256, 256>>>(
        ipw, opw, vpw, sow, aww, oqw, l1w, l2w, sob, awb,
        p_ipw, p_opw, p_vpw, p_soaw, p_oqw, p_l1w, p_l2w, soawb);

    // fork: value projection on s2
    cudaEventRecord(evA, 0);
    cudaStreamWaitEvent(s2, evA, 0);
    gemm_mma<1, false, false, 1, true, false><<<dim3(2, MTV), 256, SMEM1, s2>>>(
        mem, nullptr, nullptr, p_vpw, nullptr, vpb, nullptr, nullptr, p_val, nullptr, BS, DM, DM);
    cudaEventRecord(evB, s2);

    // main path
    // 1. QKV projection (AFP32, x1; Q scaled, V emitted as f16)
    gemm_mma<1, false, false, 1, true, true><<<dim3(6, MT), 256, SMEM1>>>(
        tgt, nullptr, nullptr, p_ipw, nullptr, ipb, nullptr, nullptr, p_qkv, nullptr, BQ, 768, DM);
    // 2. flash self-attention (f16 P/V, ones-MMA row sums)
    attn_mma<<<dim3((Q_ + 63) / 64, NH, B_), 128>>>(p_qkv, p_sa);
    // 3. out-proj + residual (x1), 4. LN1 (hi split)
    gemm_mma<1, false, true, 0, false, false><<<dim3(2, MT), 256, SMEM1>>>(
        nullptr, p_sa, nullptr, p_opw, nullptr, opb, tgt, buf, nullptr, nullptr, BQ, DM, DM);
    ln_kernel<1><<<BQ / 8, 256>>>(buf, n1g, n1b, tgt1, p_tgt1, nullptr);
    // 5+6. fused sampling offsets + attention-weight logits (N=384)
    gemm_mma<1, false, false, 0, false, false><<<dim3(3, MT), 256, SMEM1>>>(
        nullptr, p_tgt1, nullptr, p_soaw, nullptr, soawb, nullptr, offaw, nullptr, nullptr, BQ, 384, DM);

    // join: need value tensor before sampling
    cudaStreamWaitEvent((cudaStream_t)0, evB, 0);
    // 7. deformable sampling -> bf16 ca
    deform_kernel<<<(B_ * Q_ * NH * 32 + 255) / 256, 256>>>(offaw, p_val, refp, p_ca);
    // 8. output proj + residual (x1), 9. LN2 (hi split)
    gemm_mma<1, false, true, 0, false, false><<<dim3(2, MT), 256, SMEM1>>>(
        nullptr, p_ca, nullptr, p_oqw, nullptr, oqb, tgt1, buf, nullptr, nullptr, BQ, DM, DM);
    ln_kernel<1><<<BQ / 8, 256>>>(buf, n2g, n2b, tgt2, p_tgt2, nullptr);
    // 10. FFN up + relu (x2, hi out), 11. FFN down + residual (x2), 12. LN3 -> out
    gemm_mma<2, true, false, 1, false, false><<<dim3(8, MT), 256, SMEM2>>>(
        nullptr, p_tgt2, nullptr, HL(p_l1w, 1024 * 256), l1b, nullptr, nullptr, p_ffn1, nullptr, BQ, DFFN, DM);
    gemm_mma<2, false, true, 0, false, false><<<dim3(2, MT), 256, SMEM2>>>(
        nullptr, p_ffn1, nullptr, HL(p_l2w, 256 * 1024), l2b, tgt2, buf, nullptr, nullptr, BQ, DM, DFFN);
    ln_kernel<0><<<BQ / 8, 256>>>(buf, n3g, n3b, out, nullptr, nullptr);
#undef HL
}

// round 16
// speedup vs baseline: 3.7941x; 1.0179x over previous
#include <cuda_runtime.h>
#include <cuda_bf16.h>
#include <cuda_fp16.h>
#include <math.h>
#include <stdint.h>

// ---------------- problem constants ----------------
#define B_      8
#define Q_      900
#define BQ      7200          // B*Q
#define DM      256
#define STOT    13294
#define BS      106352        // B*STOT
#define NH      8
#define HD      32
#define DFFN    1024

// ---------------- fp32 scratch ----------------
__device__ float g_buf  [BQ * DM];
__device__ float g_tgt1 [BQ * DM];
__device__ float g_tgt2 [BQ * DM];
__device__ float g_offaw[BQ * 384];
__device__ float g_soawb[384];

// ---------------- bf16 scratch ----------------
__device__ __nv_bfloat16 b_qkv [BQ * 768];       // Q,K bf16; V stored as fp16 bits
__device__ __nv_bfloat16 b_sa  [BQ * DM];
__device__ __nv_bfloat16 b_tgt1[BQ * DM];
__device__ __nv_bfloat16 b_val [(size_t)BS * DM];
__device__ __nv_bfloat16 b_ca  [BQ * DM];
__device__ __nv_bfloat16 b_tgt2[BQ * DM];
__device__ __nv_bfloat16 b_ffn1[BQ * DFFN];
__device__ __nv_bfloat16 b_ipw [768 * 256];
__device__ __nv_bfloat16 b_opw [256 * 256];
__device__ __nv_bfloat16 b_vpw [256 * 256];
__device__ __nv_bfloat16 b_soaw[384 * 256];      // sow (256 rows) ++ aww (128 rows)
__device__ __nv_bfloat16 b_oqw [256 * 256];
__device__ __nv_bfloat16 b_l1w [2][1024 * 256];
__device__ __nv_bfloat16 b_l2w [2][256 * 1024];

// ---------------- helpers ----------------
__device__ __forceinline__ uint32_t smem_u32(const void* p) {
    uint32_t a;
    asm("{ .reg .u64 t; cvta.to.shared.u64 t, %1; cvt.u32.u64 %0, t; }" : "=r"(a) : "l"(p));
    return a;
}
__device__ __forceinline__ void ldsm4(uint32_t* r, uint32_t addr) {
    asm volatile("ldmatrix.sync.aligned.m8n8.x4.shared.b16 {%0,%1,%2,%3}, [%4];"
        : "=r"(r[0]), "=r"(r[1]), "=r"(r[2]), "=r"(r[3]) : "r"(addr));
}
__device__ __forceinline__ void ldsm4t(uint32_t* r, uint32_t addr) {
    asm volatile("ldmatrix.sync.aligned.m8n8.x4.trans.shared.b16 {%0,%1,%2,%3}, [%4];"
        : "=r"(r[0]), "=r"(r[1]), "=r"(r[2]), "=r"(r[3]) : "r"(addr));
}
__device__ __forceinline__ void mma16816(float* c, const uint32_t* a, const uint32_t* b) {
    asm volatile("mma.sync.aligned.m16n8k16.row.col.f32.bf16.bf16.f32 "
        "{%0,%1,%2,%3}, {%4,%5,%6,%7}, {%8,%9}, {%0,%1,%2,%3};"
        : "+f"(c[0]), "+f"(c[1]), "+f"(c[2]), "+f"(c[3])
        : "r"(a[0]), "r"(a[1]), "r"(a[2]), "r"(a[3]), "r"(b[0]), "r"(b[1]));
}
__device__ __forceinline__ void mma16816h(float* c, const uint32_t* a, const uint32_t* b) {
    asm volatile("mma.sync.aligned.m16n8k16.row.col.f32.f16.f16.f32 "
        "{%0,%1,%2,%3}, {%4,%5,%6,%7}, {%8,%9}, {%0,%1,%2,%3};"
        : "+f"(c[0]), "+f"(c[1]), "+f"(c[2]), "+f"(c[3])
        : "r"(a[0]), "r"(a[1]), "r"(a[2]), "r"(a[3]), "r"(b[0]), "r"(b[1]));
}
__device__ __forceinline__ void cpasync16(uint32_t dst, const void* src, int sz) {
    asm volatile("cp.async.cg.shared.global [%0], [%1], 16, %2;" :: "r"(dst), "l"(src), "r"(sz));
}
__device__ __forceinline__ void split2(float a, float b, __nv_bfloat162& h, __nv_bfloat162& l) {
    h = __floats2bfloat162_rn(a, b);
    float2 hf = __bfloat1622float2(h);
    l = __floats2bfloat162_rn(a - hf.x, b - hf.y);
}
__device__ __forceinline__ uint32_t pack_f16(float a, float b) {
    __half2 h = __floats2half2_rn(a, b);
    return *reinterpret_cast<uint32_t*>(&h);
}
__device__ __forceinline__ uint32_t ex2_h2(uint32_t x) {
    uint32_t y;
    asm("ex2.approx.f16x2 %0, %1;" : "=r"(y) : "r"(x));
    return y;
}

// ---------------- one-shot weight conversion (all weights + fused bias) ----------------
__global__ __launch_bounds__(256)
void convert_all(const float* __restrict__ ipw, const float* __restrict__ opw,
                 const float* __restrict__ vpw, const float* __restrict__ sow,
                 const float* __restrict__ aww, const float* __restrict__ oqw,
                 const float* __restrict__ l1w, const float* __restrict__ l2w,
                 const float* __restrict__ sob, const float* __restrict__ awb,
                 __nv_bfloat16* __restrict__ d_ipw, __nv_bfloat16* __restrict__ d_opw,
                 __nv_bfloat16* __restrict__ d_vpw, __nv_bfloat16* __restrict__ d_soaw,
                 __nv_bfloat16* __restrict__ d_oqw, __nv_bfloat16* __restrict__ d_l1w,
                 __nv_bfloat16* __restrict__ d_l2w, float* __restrict__ soawb)
{
    const int i = blockIdx.x * 256 + threadIdx.x;
    const float* src;
    __nv_bfloat16* hi;
    __nv_bfloat16* lo = nullptr;
    int base;
    if (i < 49152)       { src = ipw; hi = d_ipw; base = 0; }
    else if (i < 65536)  { src = opw; hi = d_opw; base = 49152; }
    else if (i < 81920)  { src = vpw; hi = d_vpw; base = 65536; }
    else if (i < 98304)  { src = sow; hi = d_soaw; base = 81920; }
    else if (i < 106496) { src = aww; hi = d_soaw + 65536; base = 98304; }
    else if (i < 122880) { src = oqw; hi = d_oqw; base = 106496; }
    else if (i < 188416) { src = l1w; hi = d_l1w; lo = d_l1w + 262144; base = 122880; }
    else if (i < 253952) { src = l2w; hi = d_l2w; lo = d_l2w + 262144; base = 188416; }
    else if (i < 254048) {
        const int j = i - 253952;
        float4 v = (j < 64) ? ((const float4*)sob)[j] : ((const float4*)awb)[j - 64];
        ((float4*)soawb)[j] = v;
        return;
    } else return;

    const int j = i - base;
    float4 v = ((const float4*)src)[j];
    if (lo == nullptr) {
        ((__nv_bfloat162*)hi)[j * 2 + 0] = __floats2bfloat162_rn(v.x, v.y);
        ((__nv_bfloat162*)hi)[j * 2 + 1] = __floats2bfloat162_rn(v.z, v.w);
    } else {
        __nv_bfloat162 h0, l0, h1, l1;
        split2(v.x, v.y, h0, l0);
        split2(v.z, v.w, h1, l1);
        ((__nv_bfloat162*)hi)[j * 2 + 0] = h0;
        ((__nv_bfloat162*)hi)[j * 2 + 1] = h1;
        ((__nv_bfloat162*)lo)[j * 2 + 0] = l0;
        ((__nv_bfloat162*)lo)[j * 2 + 1] = l1;
    }
}

// ---------------- bf16 mma.sync GEMM ----------------
// NPASS: 1 = Ah*Wh; 2 = Ah*Wh + Ah*Wl; 3 = Ah*Wh + Al*Wh + Ah*Wl.
// OUT: 0 = fp32 C, 1 = bf16 Ch, 2 = bf16 Ch+Cl.
// AFP32: A read fp32 (2-stage pipeline, register A path).
// non-AFP32: 3-stage cp.async pipeline (hides full LDG latency at 1 CTA/SM).
// QS (QKV only): cols<256 scaled by scale*log2e (Q); cols>=512 stored f16 (V).
#define TILEB 10240

template<int NPASS, bool RELU, bool RESID, int OUT, bool AFP32, bool QS>
__global__ __launch_bounds__(256)
void gemm_mma(const float* __restrict__ Af,
              const __nv_bfloat16* __restrict__ Ah, const __nv_bfloat16* __restrict__ Al,
              const __nv_bfloat16* __restrict__ Wh, const __nv_bfloat16* __restrict__ Wl,
              const float* __restrict__ bias, const float* __restrict__ R,
              float* __restrict__ C, __nv_bfloat16* __restrict__ Ch,
              __nv_bfloat16* __restrict__ Cl, int M, int N, int K)
{
    constexpr int NTIL = (NPASS == 3) ? 4 : (NPASS == 2 ? 3 : 2);
    constexpr int STGB = NTIL * TILEB;
    constexpr int WOFF = (NPASS == 3 ? 2 : 1) * TILEB;
    constexpr int NST  = AFP32 ? 2 : 3;

    extern __shared__ char smem[];
    const uint32_t sb = smem_u32(smem);
    const int tid = threadIdx.x, lane = tid & 31, wid = tid >> 5;
    const int am = (wid & 3) * 32;
    const int bn = (wid >> 2) * 64;
    const int m0 = blockIdx.y * 128, n0 = blockIdx.x * 128;

    float c[2][8][4] = {};

    float4 aReg[2][2];
    const int pr0 = tid >> 2, pq = tid & 3;

#define LDG_A(ch) do {                                                            \
    const int kb_ = (ch) * 32;                                                    \
    _Pragma("unroll")                                                             \
    for (int u_ = 0; u_ < 2; u_++) {                                              \
        int r_ = pr0 + u_ * 64;                                                   \
        int row_ = m0 + r_; if (row_ >= M) row_ = M - 1;                          \
        const float* p_ = Af + (size_t)row_ * K + kb_ + pq * 8;                   \
        aReg[u_][0] = *(const float4*)p_;                                         \
        aReg[u_][1] = *(const float4*)(p_ + 4);                                   \
    }                                                                             \
} while (0)

#define STS_A(st) do {                                                            \
    _Pragma("unroll")                                                             \
    for (int u_ = 0; u_ < 2; u_++) {                                              \
        int r_ = pr0 + u_ * 64;                                                   \
        uint4 w4_;                                                                \
        __nv_bfloat162 t0_ = __floats2bfloat162_rn(aReg[u_][0].x, aReg[u_][0].y); \
        __nv_bfloat162 t1_ = __floats2bfloat162_rn(aReg[u_][0].z, aReg[u_][0].w); \
        __nv_bfloat162 t2_ = __floats2bfloat162_rn(aReg[u_][1].x, aReg[u_][1].y); \
        __nv_bfloat162 t3_ = __floats2bfloat162_rn(aReg[u_][1].z, aReg[u_][1].w); \
        w4_.x = *reinterpret_cast<uint32_t*>(&t0_);                               \
        w4_.y = *reinterpret_cast<uint32_t*>(&t1_);                               \
        w4_.z = *reinterpret_cast<uint32_t*>(&t2_);                               \
        w4_.w = *reinterpret_cast<uint32_t*>(&t3_);                               \
        *(uint4*)(smem + (st) * STGB + r_ * 80 + pq * 16) = w4_;                  \
    }                                                                             \
} while (0)

#define ISSUE_W(st, ch) do {                                                      \
    const int kb_ = (ch) * 32;                                                    \
    const uint32_t so_ = sb + (st) * STGB;                                        \
    _Pragma("unroll")                                                             \
    for (int cix = tid; cix < (NPASS >= 2 ? 1024 : 512); cix += 256) {            \
        int t_ = cix >> 9, idx_ = cix & 511, r_ = idx_ >> 2, q_ = idx_ & 3;       \
        const __nv_bfloat16* base_ = t_ ? Wl : Wh;                                \
        cpasync16(so_ + WOFF + t_ * TILEB + r_ * 80 + q_ * 16,                    \
                  base_ + (size_t)(n0 + r_) * K + kb_ + q_ * 8, 16);              \
    }                                                                             \
    asm volatile("cp.async.commit_group;" ::: "memory");                          \
} while (0)

#define ISSUE_AB(st, ch) do {                                                     \
    const int kb_ = (ch) * 32;                                                    \
    const uint32_t so_ = sb + (st) * STGB;                                        \
    _Pragma("unroll")                                                             \
    for (int cix = tid; cix < NTIL * 512; cix += 256) {                           \
        int t_ = cix >> 9, idx_ = cix & 511, r_ = idx_ >> 2, q_ = idx_ & 3;       \
        uint32_t d_ = so_ + t_ * TILEB + r_ * 80 + q_ * 16;                       \
        const __nv_bfloat16* base_;                                               \
        bool isA_;                                                                \
        if (NPASS == 1) { isA_ = (t_ == 0); base_ = isA_ ? Ah : Wh; }             \
        else if (NPASS == 2) { isA_ = (t_ == 0);                                  \
               base_ = (t_ == 0 ? Ah : t_ == 1 ? Wh : Wl); }                      \
        else { isA_ = (t_ < 2);                                                   \
               base_ = (t_ == 0 ? Ah : t_ == 1 ? Al : t_ == 2 ? Wh : Wl); }       \
        if (isA_) cpasync16(d_, base_ + (size_t)(m0 + r_) * K + kb_ + q_ * 8,     \
                            (m0 + r_) < M ? 16 : 0);                              \
        else      cpasync16(d_, base_ + (size_t)(n0 + r_) * K + kb_ + q_ * 8, 16);\
    }                                                                             \
    asm volatile("cp.async.commit_group;" ::: "memory");                          \
} while (0)

    const int nCh = K >> 5;
    if (AFP32) {
        LDG_A(0);
        ISSUE_W(0, 0);
    } else {
        ISSUE_AB(0, 0);
        if (nCh > 1) ISSUE_AB(1, 1);
    }

    const int lar = lane & 15;
    const int lac = (lane >> 4) * 16;
    const int lbr = (lane & 7) + ((lane >> 4) & 1) * 8;
    const int lbc = ((lane >> 3) & 1) * 16;

    for (int ch = 0; ch < nCh; ch++) {
        if (AFP32) {
            STS_A(ch & 1);
            if (ch + 1 < nCh) {
                LDG_A(ch + 1);
                ISSUE_W((ch + 1) & 1, ch + 1);
                asm volatile("cp.async.wait_group 1;" ::: "memory");
            } else {
                asm volatile("cp.async.wait_group 0;" ::: "memory");
            }
        } else {
            if (ch + 2 < nCh) {
                ISSUE_AB((ch + 2) % 3, ch + 2);
                asm volatile("cp.async.wait_group 2;" ::: "memory");
            } else if (ch + 1 < nCh) {
                asm volatile("cp.async.wait_group 1;" ::: "memory");
            } else {
                asm volatile("cp.async.wait_group 0;" ::: "memory");
            }
        }
        __syncthreads();

        const uint32_t so = sb + (ch % NST) * STGB;
        #pragma unroll
        for (int ks = 0; ks < 2; ks++) {
            uint32_t ah[2][4], al[2][4], bb[4][4];
            const uint32_t acol = ks * 32 + lac;
            const uint32_t bcol = ks * 32 + lbc;
            ldsm4(ah[0], so + (am + lar) * 80 + acol);
            ldsm4(ah[1], so + (am + 16 + lar) * 80 + acol);
            if (NPASS == 3) {
                ldsm4(al[0], so + TILEB + (am + lar) * 80 + acol);
                ldsm4(al[1], so + TILEB + (am + 16 + lar) * 80 + acol);
            }
            #pragma unroll
            for (int p = 0; p < 4; p++)
                ldsm4(bb[p], so + WOFF + (bn + p * 16 + lbr) * 80 + bcol);
            #pragma unroll
            for (int fm = 0; fm < 2; fm++)
                #pragma unroll
                for (int p = 0; p < 4; p++) {
                    mma16816(c[fm][2 * p],     ah[fm], bb[p]);
                    mma16816(c[fm][2 * p + 1], ah[fm], bb[p] + 2);
                    if (NPASS == 3) {
                        mma16816(c[fm][2 * p],     al[fm], bb[p]);
                        mma16816(c[fm][2 * p + 1], al[fm], bb[p] + 2);
                    }
                }
            if (NPASS >= 2) {
                #pragma unroll
                for (int p = 0; p < 4; p++)
                    ldsm4(bb[p], so + WOFF + TILEB + (bn + p * 16 + lbr) * 80 + bcol);
                #pragma unroll
                for (int fm = 0; fm < 2; fm++)
                    #pragma unroll
                    for (int p = 0; p < 4; p++) {
                        mma16816(c[fm][2 * p],     ah[fm], bb[p]);
                        mma16816(c[fm][2 * p + 1], ah[fm], bb[p] + 2);
                    }
            }
        }
        __syncthreads();
    }
#undef ISSUE_AB
#undef ISSUE_W
#undef STS_A
#undef LDG_A

    // epilogue
    const int r0 = m0 + am + (lane >> 2);
    const int colb = n0 + bn + (lane & 3) * 2;
    #pragma unroll
    for (int fm = 0; fm < 2; fm++) {
        #pragma unroll
        for (int p = 0; p < 8; p++) {
            const int col = colb + p * 8;
            const float2 bv = *(const float2*)(bias + col);
            #pragma unroll
            for (int hh = 0; hh < 2; hh++) {
                const int row = r0 + fm * 16 + hh * 8;
                if (row < M) {
                    float o0 = c[fm][p][hh * 2 + 0] + bv.x;
                    float o1 = c[fm][p][hh * 2 + 1] + bv.y;
                    if (QS && col < 256) {
                        const float qsf = 0.17677669529663687f * 1.4426950408889634f;
                        o0 *= qsf; o1 *= qsf;
                    }
                    if (RESID) {
                        float2 rv = *(const float2*)(R + (size_t)row * N + col);
                        o0 += rv.x; o1 += rv.y;
                    }
                    if (RELU) { o0 = fmaxf(o0, 0.f); o1 = fmaxf(o1, 0.f); }
                    if (OUT == 0) {
                        *(float2*)(C + (size_t)row * N + col) = make_float2(o0, o1);
                    } else if (OUT == 1) {
                        if (QS && col >= 512) {
                            *(uint32_t*)(Ch + (size_t)row * N + col) = pack_f16(o0, o1);
                        } else {
                            *(__nv_bfloat162*)(Ch + (size_t)row * N + col) = __floats2bfloat162_rn(o0, o1);
                        }
                    } else {
                        __nv_bfloat162 h, l;
                        split2(o0, o1, h, l);
                        *(__nv_bfloat162*)(Ch + (size_t)row * N + col) = h;
                        *(__nv_bfloat162*)(Cl + (size_t)row * N + col) = l;
                    }
                }
            }
        }
    }
}

// ---------------- flash self-attention ----------------
// QK bf16 mma; P exp2'd in f16x2, used directly as f16 A-fragment; V f16;
// Sexp via ones-column f16 MMA. Dual accumulators (even/odd ts) halve the
// dependent-HMMA chain depth. No-max softmax.
// 64 Q-rows per CTA, 128 threads (4 warps x 16 rows).
#define KVB 5120

__global__ __launch_bounds__(128)
void attn_mma(const __nv_bfloat16* __restrict__ qkv, __nv_bfloat16* __restrict__ sa)
{
    __shared__ __nv_bfloat16 Qs[64 * 40];
    __shared__ __nv_bfloat16 Ks[2][64 * 40];
    __shared__ __nv_bfloat16 Vs[2][64 * 40];
    const int b = blockIdx.z, h = blockIdx.y, q0 = blockIdx.x * 64;
    const int tid = threadIdx.x, lane = tid & 31, wid = tid >> 5;
    const uint32_t sQ = smem_u32(Qs), sK = smem_u32(Ks), sV = smem_u32(Vs);

#define ISSUE_KV(t, bufi) do {                                                    \
    const int kv0_ = (t) * 64;                                                    \
    _Pragma("unroll")                                                             \
    for (int i_ = tid; i_ < 512; i_ += 128) {                                     \
        int te_ = i_ >> 8, idx_ = i_ & 255, r_ = idx_ >> 2, cc_ = idx_ & 3;       \
        const __nv_bfloat16* src_ = qkv + (size_t)(b * Q_ + kv0_ + r_) * 768      \
                                    + 256 + te_ * 256 + h * HD + cc_ * 8;         \
        cpasync16((te_ ? sV : sK) + (bufi) * KVB + r_ * 80 + cc_ * 16, src_,      \
                  (kv0_ + r_) < Q_ ? 16 : 0);                                     \
    }                                                                             \
    asm volatile("cp.async.commit_group;" ::: "memory");                          \
} while (0)

    #pragma unroll
    for (int i = tid; i < 256; i += 128) {
        int r = i >> 2, cc = i & 3;
        const __nv_bfloat16* src = qkv + (size_t)(b * Q_ + q0 + r) * 768 + h * HD + cc * 8;
        cpasync16(sQ + r * 80 + cc * 16, src, (q0 + r) < Q_ ? 16 : 0);
    }
    asm volatile("cp.async.commit_group;" ::: "memory");
    ISSUE_KV(0, 0);
    asm volatile("cp.async.wait_group 1;" ::: "memory");
    __syncthreads();

    const int r8 = (lane & 7) + ((lane >> 3) & 1) * 8;
    const int c16 = (lane >> 4) * 16;

    uint32_t qf[2][4];
    {
        uint32_t qa = sQ + (wid * 16 + r8) * 80 + c16;
        ldsm4(qf[0], qa);
        ldsm4(qf[1], qa + 32);
    }

    float csum[4] = {}, csum2[4] = {};
    float o[4][4] = {}, o2[4][4] = {};
    const uint32_t ones2[2] = {0x3C003C00u, 0x3C003C00u};   // f16 1.0 x4

    for (int t = 0; t < 15; t++) {
        const int kv0 = t * 64;
        if (t + 1 < 15) {
            ISSUE_KV(t + 1, (t + 1) & 1);
            asm volatile("cp.async.wait_group 1;" ::: "memory");
        } else {
            asm volatile("cp.async.wait_group 0;" ::: "memory");
        }
        __syncthreads();

        const uint32_t sKb = sK + (t & 1) * KVB;
        const uint32_t sVb = sV + (t & 1) * KVB;

        float c[8][4] = {};
        #pragma unroll
        for (int ks = 0; ks < 2; ks++) {
            #pragma unroll
            for (int p = 0; p < 4; p++) {
                uint32_t kf[4];
                ldsm4(kf, sKb + (p * 16 + r8) * 80 + c16 + ks * 32);
                uint32_t b0[2] = {kf[0], kf[2]}, b1[2] = {kf[1], kf[3]};
                mma16816(c[2 * p],     qf[ks], b0);
                mma16816(c[2 * p + 1], qf[ks], b1);
            }
        }
        if (kv0 + 64 > Q_) {
            #pragma unroll
            for (int p8 = 0; p8 < 8; p8++)
                #pragma unroll
                for (int j = 0; j < 2; j++)
                    if (kv0 + p8 * 8 + 2 * (lane & 3) + j >= Q_) {
                        c[p8][j] = -1e4f;
                        c[p8][2 + j] = -1e4f;
                    }
        }
        // P = exp2(scores) in f16x2, directly forming the A fragment.
        // Even ts -> o/csum, odd ts -> o2/csum2 (halved dependency chains).
        #pragma unroll
        for (int ts = 0; ts < 4; ts++) {
            uint32_t af[4];
            af[0] = ex2_h2(pack_f16(c[2 * ts][0], c[2 * ts][1]));
            af[1] = ex2_h2(pack_f16(c[2 * ts][2], c[2 * ts][3]));
            af[2] = ex2_h2(pack_f16(c[2 * ts + 1][0], c[2 * ts + 1][1]));
            af[3] = ex2_h2(pack_f16(c[2 * ts + 1][2], c[2 * ts + 1][3]));
            float* cs = (ts & 1) ? csum2 : csum;
            float (*oo)[4] = (ts & 1) ? o2 : o;
            mma16816h(cs, af, ones2);
            #pragma unroll
            for (int np = 0; np < 2; np++) {
                uint32_t vf[4];
                ldsm4t(vf, sVb + (ts * 16 + r8) * 80 + np * 32 + c16);
                uint32_t b0[2] = {vf[0], vf[1]}, b1[2] = {vf[2], vf[3]};
                mma16816h(oo[2 * np],     af, b0);
                mma16816h(oo[2 * np + 1], af, b1);
            }
        }
        __syncthreads();
    }
#undef ISSUE_KV

    const float inv0 = 1.f / (csum[0] + csum2[0]);
    const float inv1 = 1.f / (csum[2] + csum2[2]);
    const int gr0 = q0 + wid * 16 + (lane >> 2);
    #pragma unroll
    for (int nt = 0; nt < 4; nt++) {
        const int col = h * HD + nt * 8 + 2 * (lane & 3);
        if (gr0 < Q_)
            *(__nv_bfloat162*)(sa + (size_t)(b * Q_ + gr0) * DM + col)
                = __floats2bfloat162_rn((o[nt][0] + o2[nt][0]) * inv0,
                                        (o[nt][1] + o2[nt][1]) * inv0);
        if (gr0 + 8 < Q_)
            *(__nv_bfloat162*)(sa + (size_t)(b * Q_ + gr0 + 8) * DM + col)
                = __floats2bfloat162_rn((o[nt][2] + o2[nt][2]) * inv1,
                                        (o[nt][3] + o2[nt][3]) * inv1);
    }
}

// ---------------- LayerNorm: warp per row, 8 rows/CTA ----------------
template<int OSPLIT>
__global__ __launch_bounds__(256)
void ln_kernel(const float* __restrict__ in, const float* __restrict__ g,
               const float* __restrict__ bta, float* __restrict__ out,
               __nv_bfloat16* __restrict__ oh, __nv_bfloat16* __restrict__ ol)
{
    const int warp = threadIdx.x >> 5, lane = threadIdx.x & 31;
    const int row = blockIdx.x * 8 + warp;
    const float4* ip = (const float4*)(in + (size_t)row * DM);
    float4 v0 = ip[lane], v1 = ip[lane + 32];

    float s = ((v0.x + v0.y) + (v0.z + v0.w)) + ((v1.x + v1.y) + (v1.z + v1.w));
    #pragma unroll
    for (int o = 16; o > 0; o >>= 1) s += __shfl_xor_sync(0xffffffffu, s, o);
    const float mu = s * (1.f / 256.f);

    v0.x -= mu; v0.y -= mu; v0.z -= mu; v0.w -= mu;
    v1.x -= mu; v1.y -= mu; v1.z -= mu; v1.w -= mu;
    float vs = ((v0.x * v0.x + v0.y * v0.y) + (v0.z * v0.z + v0.w * v0.w))
             + ((v1.x * v1.x + v1.y * v1.y) + (v1.z * v1.z + v1.w * v1.w));
    #pragma unroll
    for (int o = 16; o > 0; o >>= 1) vs += __shfl_xor_sync(0xffffffffu, vs, o);
    const float rs = rsqrtf(vs * (1.f / 256.f) + 1e-5f);

    const float4 g0 = ((const float4*)g)[lane],  g1 = ((const float4*)g)[lane + 32];
    const float4 b0 = ((const float4*)bta)[lane], b1 = ((const float4*)bta)[lane + 32];
    float4 y0, y1;
    y0.x = v0.x * rs * g0.x + b0.x; y0.y = v0.y * rs * g0.y + b0.y;
    y0.z = v0.z * rs * g0.z + b0.z; y0.w = v0.w * rs * g0.w + b0.w;
    y1.x = v1.x * rs * g1.x + b1.x; y1.y = v1.y * rs * g1.y + b1.y;
    y1.z = v1.z * rs * g1.z + b1.z; y1.w = v1.w * rs * g1.w + b1.w;

    float4* op = (float4*)(out + (size_t)row * DM);
    op[lane] = y0; op[lane + 32] = y1;

    if (OSPLIT >= 1) {
        const size_t i0 = (size_t)row * DM + lane * 4;
        const size_t i1 = i0 + 128;
        if (OSPLIT == 1) {
            *(__nv_bfloat162*)(oh + i0)     = __floats2bfloat162_rn(y0.x, y0.y);
            *(__nv_bfloat162*)(oh + i0 + 2) = __floats2bfloat162_rn(y0.z, y0.w);
            *(__nv_bfloat162*)(oh + i1)     = __floats2bfloat162_rn(y1.x, y1.y);
            *(__nv_bfloat162*)(oh + i1 + 2) = __floats2bfloat162_rn(y1.z, y1.w);
        } else {
            __nv_bfloat162 h, l;
            split2(y0.x, y0.y, h, l);
            *(__nv_bfloat162*)(oh + i0) = h;     *(__nv_bfloat162*)(ol + i0) = l;
            split2(y0.z, y0.w, h, l);
            *(__nv_bfloat162*)(oh + i0 + 2) = h; *(__nv_bfloat162*)(ol + i0 + 2) = l;
            split2(y1.x, y1.y, h, l);
            *(__nv_bfloat162*)(oh + i1) = h;     *(__nv_bfloat162*)(ol + i1) = l;
            split2(y1.z, y1.w, h, l);
            *(__nv_bfloat162*)(oh + i1 + 2) = h; *(__nv_bfloat162*)(ol + i1 + 2) = l;
        }
    }
}

// ---------------- deformable sampling + weight softmax ----------------
__global__ __launch_bounds__(256)
void deform_kernel(const float* __restrict__ offaw,
                   const __nv_bfloat16* __restrict__ value, const float* __restrict__ refp,
                   __nv_bfloat16* __restrict__ outh)
{
    const int gw = (blockIdx.x * blockDim.x + threadIdx.x) >> 5;
    const int lane = threadIdx.x & 31;
    if (gw >= B_ * Q_ * NH) return;
    const int h = gw & 7;
    const int q = (gw >> 3) % Q_;
    const int b = gw / (NH * Q_);
    const size_t bq = (size_t)b * Q_ + q;

    float logit = (lane < 16) ? offaw[bq * 384 + 256 + h * 16 + lane] : -1e30f;
    float mx = logit;
    #pragma unroll
    for (int o = 16; o > 0; o >>= 1) mx = fmaxf(mx, __shfl_xor_sync(0xffffffffu, mx, o));
    float e = (lane < 16) ? __expf(logit - mx) : 0.f;
    float se = e;
    #pragma unroll
    for (int o = 16; o > 0; o >>= 1) se += __shfl_xor_sync(0xffffffffu, se, o);
    const float aw = e / se;

    const int HWl[4][2] = {{100,100},{50,50},{25,25},{13,13}};
    const int ST[4]     = {0, 10000, 12500, 13125};

    float accv = 0.f;
    #pragma unroll
    for (int lvl = 0; lvl < 4; lvl++) {
        const int Hi = HWl[lvl][0], Wi = HWl[lvl][1];
        const float Hl = (float)Hi, Wl = (float)Wi;
        const float refx = refp[(bq * 4 + lvl) * 2 + 0];
        const float refy = refp[(bq * 4 + lvl) * 2 + 1];
        const __nv_bfloat16* vbase = value + ((size_t)b * STOT + ST[lvl]) * DM + h * HD + lane;
        #pragma unroll
        for (int p = 0; p < 4; p++) {
            const int oidx = ((h * 4 + lvl) * 4 + p) * 2;
            const float ox = offaw[bq * 384 + oidx + 0];
            const float oy = offaw[bq * 384 + oidx + 1];
            const float x = (refx + ox / Wl) * Wl - 0.5f;
            const float y = (refy + oy / Hl) * Hl - 0.5f;
            const float x0 = floorf(x), y0 = floorf(y);
            float samp = 0.f;
            #pragma unroll
            for (int cq = 0; cq < 4; cq++) {
                const float xi = x0 + (float)(cq & 1);
                const float yi = y0 + (float)(cq >> 1);
                const float w = (1.f - fabsf(x - xi)) * (1.f - fabsf(y - yi));
                if (xi >= 0.f && xi < Wl && yi >= 0.f && yi < Hl && w != 0.f) {
                    const int ii = (int)yi * Wi + (int)xi;
                    samp += w * __bfloat162float(vbase[(size_t)ii * DM]);
                }
            }
            const float awp = __shfl_sync(0xffffffffu, aw, lvl * 4 + p);
            accv += awp * samp;
        }
    }
    outh[bq * DM + h * HD + lane] = __float2bfloat16(accv);
}

// ---------------- launch ----------------
extern "C" void kernel_launch(void* const* d_in, const int* in_sizes, int n_in,
                              void* d_out, int out_size)
{
    (void)in_sizes; (void)n_in; (void)out_size;
    const float* tgt   = (const float*)d_in[0];
    const float* mem   = (const float*)d_in[1];
    const float* refp  = (const float*)d_in[3];
    const float* ipw = (const float*)d_in[6],  *ipb = (const float*)d_in[7];
    const float* opw = (const float*)d_in[8],  *opb = (const float*)d_in[9];
    const float* n1g = (const float*)d_in[10], *n1b = (const float*)d_in[11];
    const float* n2g = (const float*)d_in[12], *n2b = (const float*)d_in[13];
    const float* n3g = (const float*)d_in[14], *n3b = (const float*)d_in[15];
    const float* sow = (const float*)d_in[16], *sob = (const float*)d_in[17];
    const float* aww = (const float*)d_in[18], *awb = (const float*)d_in[19];
    const float* vpw = (const float*)d_in[20], *vpb = (const float*)d_in[21];
    const float* oqw = (const float*)d_in[22], *oqb = (const float*)d_in[23];
    const float* l1w = (const float*)d_in[24], *l1b = (const float*)d_in[25];
    const float* l2w = (const float*)d_in[26], *l2b = (const float*)d_in[27];
    float* out = (float*)d_out;

    float *buf, *tgt1, *tgt2, *offaw, *soawb;
    cudaGetSymbolAddress((void**)&buf,   g_buf);
    cudaGetSymbolAddress((void**)&tgt1,  g_tgt1);
    cudaGetSymbolAddress((void**)&tgt2,  g_tgt2);
    cudaGetSymbolAddress((void**)&offaw, g_offaw);
    cudaGetSymbolAddress((void**)&soawb, g_soawb);

    __nv_bfloat16 *p_qkv, *p_sa, *p_tgt1, *p_val, *p_ca, *p_tgt2, *p_ffn1;
    __nv_bfloat16 *p_ipw, *p_opw, *p_vpw, *p_soaw, *p_oqw, *p_l1w, *p_l2w;
    cudaGetSymbolAddress((void**)&p_qkv,  b_qkv);
    cudaGetSymbolAddress((void**)&p_sa,   b_sa);
    cudaGetSymbolAddress((void**)&p_tgt1, b_tgt1);
    cudaGetSymbolAddress((void**)&p_val,  b_val);
    cudaGetSymbolAddress((void**)&p_ca,   b_ca);
    cudaGetSymbolAddress((void**)&p_tgt2, b_tgt2);
    cudaGetSymbolAddress((void**)&p_ffn1, b_ffn1);
    cudaGetSymbolAddress((void**)&p_ipw,  b_ipw);
    cudaGetSymbolAddress((void**)&p_opw,  b_opw);
    cudaGetSymbolAddress((void**)&p_vpw,  b_vpw);
    cudaGetSymbolAddress((void**)&p_soaw, b_soaw);
    cudaGetSymbolAddress((void**)&p_oqw,  b_oqw);
    cudaGetSymbolAddress((void**)&p_l1w,  b_l1w);
    cudaGetSymbolAddress((void**)&p_l2w,  b_l2w);

    const int SMEM_A2 = 2 * 2 * TILEB;   // 40960 (AFP32, 2-stage)
    const int SMEM_13 = 3 * 2 * TILEB;   // 61440 (NPASS=1, 3-stage)
    const int SMEM_23 = 3 * 3 * TILEB;   // 92160 (NPASS=2, 3-stage)
    cudaFuncSetAttribute(gemm_mma<1, false, false, 1, true,  true >, cudaFuncAttributeMaxDynamicSharedMemorySize, SMEM_A2);
    cudaFuncSetAttribute(gemm_mma<1, false, false, 1, true,  false>, cudaFuncAttributeMaxDynamicSharedMemorySize, SMEM_A2);
    cudaFuncSetAttribute(gemm_mma<1, false, true,  0, false, false>, cudaFuncAttributeMaxDynamicSharedMemorySize, SMEM_13);
    cudaFuncSetAttribute(gemm_mma<1, false, false, 0, false, false>, cudaFuncAttributeMaxDynamicSharedMemorySize, SMEM_13);
    cudaFuncSetAttribute(gemm_mma<2, true,  false, 1, false, false>, cudaFuncAttributeMaxDynamicSharedMemorySize, SMEM_23);
    cudaFuncSetAttribute(gemm_mma<2, false, true,  0, false, false>, cudaFuncAttributeMaxDynamicSharedMemorySize, SMEM_23);

    const int MT  = (BQ + 127) / 128;    // 57
    const int MTV = (BS + 127) / 128;    // 831

    cudaStream_t s2;
    cudaStreamCreateWithFlags(&s2, cudaStreamNonBlocking);
    cudaEvent_t evA, evB;
    cudaEventCreateWithFlags(&evA, cudaEventDisableTiming);
    cudaEventCreateWithFlags(&evB, cudaEventDisableTiming);

#define HL(p, n) (p), (p) + (n)

    // ---- all weight conversions + fused bias, ONE launch ----
    convert_all<<<(254048 + 255) / 256, 256>>>(
        ipw, opw, vpw, sow, aww, oqw, l1w, l2w, sob, awb,
        p_ipw, p_opw, p_vpw, p_soaw, p_oqw, p_l1w, p_l2w, soawb);

    // fork: value projection on s2
    cudaEventRecord(evA, 0);
    cudaStreamWaitEvent(s2, evA, 0);
    gemm_mma<1, false, false, 1, true, false><<<dim3(2, MTV), 256, SMEM_A2, s2>>>(
        mem, nullptr, nullptr, p_vpw, nullptr, vpb, nullptr, nullptr, p_val, nullptr, BS, DM, DM);
    cudaEventRecord(evB, s2);

    // main path
    // 1. QKV projection (AFP32, x1; Q scaled, V emitted as f16)
    gemm_mma<1, false, false, 1, true, true><<<dim3(6, MT), 256, SMEM_A2>>>(
        tgt, nullptr, nullptr, p_ipw, nullptr, ipb, nullptr, nullptr, p_qkv, nullptr, BQ, 768, DM);
    // 2. flash self-attention (dual accumulators)
    attn_mma<<<dim3((Q_ + 63) / 64, NH, B_), 128>>>(p_qkv, p_sa);
    // 3. out-proj + residual (x1), 4. LN1 (hi split)
    gemm_mma<1, false, true, 0, false, false><<<dim3(2, MT), 256, SMEM_13>>>(
        nullptr, p_sa, nullptr, p_opw, nullptr, opb, tgt, buf, nullptr, nullptr, BQ, DM, DM);
    ln_kernel<1><<<BQ / 8, 256>>>(buf, n1g, n1b, tgt1, p_tgt1, nullptr);
    // 5+6. fused sampling offsets + attention-weight logits (N=384)
    gemm_mma<1, false, false, 0, false, false><<<dim3(3, MT), 256, SMEM_13>>>(
        nullptr, p_tgt1, nullptr, p_soaw, nullptr, soawb, nullptr, offaw, nullptr, nullptr, BQ, 384, DM);

    // join: need value tensor before sampling
    cudaStreamWaitEvent((cudaStream_t)0, evB, 0);
    // 7. deformable sampling -> bf16 ca
    deform_kernel<<<(B_ * Q_ * NH * 32 + 255) / 256, 256>>>(offaw, p_val, refp, p_ca);
    // 8. output proj + residual (x1), 9. LN2 (hi split)
    gemm_mma<1, false, true, 0, false, false><<<dim3(2, MT), 256, SMEM_13>>>(
        nullptr, p_ca, nullptr, p_oqw, nullptr, oqb, tgt1, buf, nullptr, nullptr, BQ, DM, DM);
    ln_kernel<1><<<BQ / 8, 256>>>(buf, n2g, n2b, tgt2, p_tgt2, nullptr);
    // 10. FFN up + relu (x2, hi out), 11. FFN down + residual (x2), 12. LN3 -> out
    gemm_mma<2, true, false, 1, false, false><<<dim3(8, MT), 256, SMEM_23>>>(
        nullptr, p_tgt2, nullptr, HL(p_l1w, 1024 * 256), l1b, nullptr, nullptr, p_ffn1, nullptr, BQ, DFFN, DM);
    gemm_mma<2, false, true, 0, false, false><<<dim3(2, MT), 256, SMEM_23>>>(
        nullptr, p_ffn1, nullptr, HL(p_l2w, 256 * 1024), l2b, tgt2, buf, nullptr, nullptr, BQ, DM, DFFN);
    ln_kernel<0><<<BQ / 8, 256>>>(buf, n3g, n3b, out, nullptr, nullptr);
#undef HL
}